// round 1
// baseline (speedup 1.0000x reference)
#include <cuda_runtime.h>
#include <cuda_bf16.h>
#include <math.h>

// Problem dims (fixed by the dataset)
#define BATCH 8
#define SEQ   2048
#define DMODEL 1024
#define DK    128
#define DFF   4096
#define MS    (BATCH*SEQ)        // 16384 rows

// ---------------- scratch (static device globals; no allocation) -------------
__device__ float g_xn [(size_t)MS*DMODEL];   // ln1(x)
__device__ float g_q  [(size_t)MS*DK];
__device__ float g_k  [(size_t)MS*DK];
__device__ float g_v  [(size_t)MS*DK];
__device__ float g_sc [(size_t)BATCH*SEQ*SEQ]; // attention scores/probs
__device__ float g_att[(size_t)MS*DK];       // A@V
__device__ float g_y  [(size_t)MS*DMODEL];   // residual 1 output
__device__ float g_h  [(size_t)MS*DMODEL];   // ln2(y)
__device__ float g_act[(size_t)MS*DFF];      // gelu(h@W1+b1)

// ---------------- LayerNorm: one block per row of 1024 -----------------------
__global__ __launch_bounds__(256) void ln_k(const float* __restrict__ x,
                                            const float* __restrict__ g,
                                            const float* __restrict__ b,
                                            float* __restrict__ o)
{
    const int row = blockIdx.x;
    const int tid = threadIdx.x;
    const float* xr = x + (size_t)row * DMODEL;
    float4 v = *(const float4*)(xr + tid * 4);

    float s  = v.x + v.y + v.z + v.w;
    float s2 = v.x*v.x + v.y*v.y + v.z*v.z + v.w*v.w;
    #pragma unroll
    for (int off = 16; off; off >>= 1) {
        s  += __shfl_xor_sync(0xffffffffu, s,  off);
        s2 += __shfl_xor_sync(0xffffffffu, s2, off);
    }
    __shared__ float ss[8], ss2[8], stats[2];
    const int wid = tid >> 5, lane = tid & 31;
    if (lane == 0) { ss[wid] = s; ss2[wid] = s2; }
    __syncthreads();
    if (wid == 0) {
        s  = (lane < 8) ? ss[lane]  : 0.f;
        s2 = (lane < 8) ? ss2[lane] : 0.f;
        #pragma unroll
        for (int off = 4; off; off >>= 1) {
            s  += __shfl_xor_sync(0xffffffffu, s,  off);
            s2 += __shfl_xor_sync(0xffffffffu, s2, off);
        }
        if (lane == 0) {
            float mean = s * (1.0f / DMODEL);
            float var  = s2 * (1.0f / DMODEL) - mean * mean;
            stats[0] = mean;
            stats[1] = rsqrtf(var + 1e-5f);
        }
    }
    __syncthreads();
    const float mean = stats[0], rstd = stats[1];
    float4 gg = *(const float4*)(g + tid * 4);
    float4 bb = *(const float4*)(b + tid * 4);
    float4 out;
    out.x = (v.x - mean) * rstd * gg.x + bb.x;
    out.y = (v.y - mean) * rstd * gg.y + bb.y;
    out.z = (v.z - mean) * rstd * gg.z + bb.z;
    out.w = (v.w - mean) * rstd * gg.w + bb.w;
    *(float4*)(o + (size_t)row * DMODEL + tid * 4) = out;
}

// ---------------- row softmax over N=2048 (in place) --------------------------
__global__ __launch_bounds__(256) void softmax_k(float* __restrict__ S)
{
    const size_t row = blockIdx.x;
    float* p = S + row * (size_t)SEQ;
    const int tid = threadIdx.x;
    float4 a = *(const float4*)(p + tid * 4);
    float4 c = *(const float4*)(p + 1024 + tid * 4);

    float m = fmaxf(fmaxf(fmaxf(a.x, a.y), fmaxf(a.z, a.w)),
                    fmaxf(fmaxf(c.x, c.y), fmaxf(c.z, c.w)));
    #pragma unroll
    for (int off = 16; off; off >>= 1)
        m = fmaxf(m, __shfl_xor_sync(0xffffffffu, m, off));
    __shared__ float sm[8], sred[2];
    const int wid = tid >> 5, lane = tid & 31;
    if (lane == 0) sm[wid] = m;
    __syncthreads();
    if (wid == 0) {
        m = (lane < 8) ? sm[lane] : -1e30f;
        #pragma unroll
        for (int off = 4; off; off >>= 1)
            m = fmaxf(m, __shfl_xor_sync(0xffffffffu, m, off));
        if (lane == 0) sred[0] = m;
    }
    __syncthreads();
    m = sred[0];

    a.x = expf(a.x - m); a.y = expf(a.y - m); a.z = expf(a.z - m); a.w = expf(a.w - m);
    c.x = expf(c.x - m); c.y = expf(c.y - m); c.z = expf(c.z - m); c.w = expf(c.w - m);
    float s = a.x + a.y + a.z + a.w + c.x + c.y + c.z + c.w;
    #pragma unroll
    for (int off = 16; off; off >>= 1)
        s += __shfl_xor_sync(0xffffffffu, s, off);
    if (lane == 0) sm[wid] = s;
    __syncthreads();
    if (wid == 0) {
        s = (lane < 8) ? sm[lane] : 0.f;
        #pragma unroll
        for (int off = 4; off; off >>= 1)
            s += __shfl_xor_sync(0xffffffffu, s, off);
        if (lane == 0) sred[1] = 1.0f / s;
    }
    __syncthreads();
    const float r = sred[1];
    a.x *= r; a.y *= r; a.z *= r; a.w *= r;
    c.x *= r; c.y *= r; c.z *= r; c.w *= r;
    *(float4*)(p + tid * 4) = a;
    *(float4*)(p + 1024 + tid * 4) = c;
}

// ---------------- generic fp32 GEMM, 128x128x16, 256 thr, 8x8 microtile ------
// A: [M,K] row-major (lda=K). B: TB? [N,K] (ldb=K) : [K,N] (ldb=N).
// C: [M,N]. Batched via blockIdx.z with element strides sA/sB/sC.
// EPI bits: 1=+bias[col], 2=exact gelu, 4=+res (same layout as C).
#define BM 128
#define BN 128
#define BKK 16

template<bool TB, int EPI>
__global__ __launch_bounds__(256) void gemm_k(
    const float* __restrict__ A, const float* __restrict__ B,
    const float* __restrict__ bias, const float* __restrict__ res,
    float* __restrict__ C, int M, int N, int K,
    long long sA, long long sB, long long sC, float alpha)
{
    __shared__ float As[BKK][BM];
    __shared__ float Bs[BKK][BN];

    const int tid = threadIdx.x;
    const int tx = tid & 15, ty = tid >> 4;
    const int bx = blockIdx.x, by = blockIdx.y, bz = blockIdx.z;

    A += (long long)bz * sA;
    B += (long long)bz * sB;
    C += (long long)bz * sC;
    const float* R = ((EPI & 4) ? res + (long long)bz * sC : nullptr);

    const float* Ab = A + (size_t)(by * BM) * K;

    float acc[8][8];
    #pragma unroll
    for (int i = 0; i < 8; i++)
        #pragma unroll
        for (int j = 0; j < 8; j++) acc[i][j] = 0.f;

    const int a_m = tid >> 2;          // 0..63 (+64 on 2nd pass)
    const int a_k = (tid & 3) * 4;     // 0,4,8,12
    const int b_kk = tid >> 5;         // 0..7 (+8)       (NN path)
    const int b_n4 = (tid & 31) * 4;   // 0..124          (NN path)

    for (int k0 = 0; k0 < K; k0 += BKK) {
        #pragma unroll
        for (int r = 0; r < 2; r++) {
            int m = a_m + r * 64;
            float4 v = *(const float4*)(Ab + (size_t)m * K + k0 + a_k);
            As[a_k + 0][m] = v.x; As[a_k + 1][m] = v.y;
            As[a_k + 2][m] = v.z; As[a_k + 3][m] = v.w;
        }
        if (!TB) {
            #pragma unroll
            for (int r = 0; r < 2; r++) {
                int kk = b_kk + r * 8;
                float4 v = *(const float4*)(B + (size_t)(k0 + kk) * N + bx * BN + b_n4);
                *(float4*)&Bs[kk][b_n4] = v;
            }
        } else {
            #pragma unroll
            for (int r = 0; r < 2; r++) {
                int n = a_m + r * 64;
                float4 v = *(const float4*)(B + (size_t)(bx * BN + n) * K + k0 + a_k);
                Bs[a_k + 0][n] = v.x; Bs[a_k + 1][n] = v.y;
                Bs[a_k + 2][n] = v.z; Bs[a_k + 3][n] = v.w;
            }
        }
        __syncthreads();

        #pragma unroll
        for (int kk = 0; kk < BKK; kk++) {
            float a[8], b[8];
            *(float4*)&a[0] = *(const float4*)&As[kk][ty * 4];
            *(float4*)&a[4] = *(const float4*)&As[kk][64 + ty * 4];
            *(float4*)&b[0] = *(const float4*)&Bs[kk][tx * 4];
            *(float4*)&b[4] = *(const float4*)&Bs[kk][64 + tx * 4];
            #pragma unroll
            for (int i = 0; i < 8; i++)
                #pragma unroll
                for (int j = 0; j < 8; j++)
                    acc[i][j] += a[i] * b[j];
        }
        __syncthreads();
    }

    // epilogue
    #pragma unroll
    for (int i = 0; i < 8; i++) {
        int ri = (i < 4) ? (ty * 4 + i) : (64 + ty * 4 + i - 4);
        size_t r = (size_t)(by * BM + ri);
        #pragma unroll
        for (int j = 0; j < 8; j++) {
            int cj = (j < 4) ? (tx * 4 + j) : (64 + tx * 4 + j - 4);
            size_t c = (size_t)(bx * BN + cj);
            float v = acc[i][j] * alpha;
            if (EPI & 1) v += bias[c];
            if (EPI & 2) v = 0.5f * v * (1.0f + erff(v * 0.70710678118654752f));
            if (EPI & 4) v += R[r * N + c];
            C[r * N + c] = v;
        }
    }
}

// ---------------- launch sequence -------------------------------------------
extern "C" void kernel_launch(void* const* d_in, const int* in_sizes, int n_in,
                              void* d_out, int out_size)
{
    const float* x     = (const float*)d_in[0];
    const float* ln1_g = (const float*)d_in[1];
    const float* ln1_b = (const float*)d_in[2];
    const float* Wq    = (const float*)d_in[3];
    const float* bq    = (const float*)d_in[4];
    const float* Wk    = (const float*)d_in[5];
    const float* bk    = (const float*)d_in[6];
    const float* Wv    = (const float*)d_in[7];
    const float* bv    = (const float*)d_in[8];
    const float* Wo    = (const float*)d_in[9];
    const float* bo    = (const float*)d_in[10];
    const float* ln2_g = (const float*)d_in[11];
    const float* ln2_b = (const float*)d_in[12];
    const float* W1    = (const float*)d_in[13];
    const float* b1    = (const float*)d_in[14];
    const float* W2    = (const float*)d_in[15];
    const float* b2    = (const float*)d_in[16];
    float* out = (float*)d_out;

    float *xn, *q, *k, *v, *sc, *att, *y, *h, *act;
    cudaGetSymbolAddress((void**)&xn,  g_xn);
    cudaGetSymbolAddress((void**)&q,   g_q);
    cudaGetSymbolAddress((void**)&k,   g_k);
    cudaGetSymbolAddress((void**)&v,   g_v);
    cudaGetSymbolAddress((void**)&sc,  g_sc);
    cudaGetSymbolAddress((void**)&att, g_att);
    cudaGetSymbolAddress((void**)&y,   g_y);
    cudaGetSymbolAddress((void**)&h,   g_h);
    cudaGetSymbolAddress((void**)&act, g_act);

    const float scale = 0.08838834764831845f; // 1/sqrt(128)

    // 1) xn = ln1(x)
    ln_k<<<MS, 256>>>(x, ln1_g, ln1_b, xn);

    // 2) q/k/v = xn@W + b          (M=16384, N=128, K=1024)
    gemm_k<false, 1><<<dim3(1, MS / BM, 1), 256>>>(xn, Wq, bq, nullptr, q,
                                                   MS, DK, DMODEL, 0, 0, 0, 1.f);
    gemm_k<false, 1><<<dim3(1, MS / BM, 1), 256>>>(xn, Wk, bk, nullptr, k,
                                                   MS, DK, DMODEL, 0, 0, 0, 1.f);
    gemm_k<false, 1><<<dim3(1, MS / BM, 1), 256>>>(xn, Wv, bv, nullptr, v,
                                                   MS, DK, DMODEL, 0, 0, 0, 1.f);

    // 3) scores = q @ k^T * scale  (per batch: 2048x2048x128)
    gemm_k<true, 0><<<dim3(SEQ / BN, SEQ / BM, BATCH), 256>>>(
        q, k, nullptr, nullptr, sc, SEQ, SEQ, DK,
        (long long)SEQ * DK, (long long)SEQ * DK, (long long)SEQ * SEQ, scale);

    // 4) softmax rows (in place)
    softmax_k<<<BATCH * SEQ, 256>>>(sc);

    // 5) att = probs @ v           (per batch: 2048x128x2048)
    gemm_k<false, 0><<<dim3(1, SEQ / BM, BATCH), 256>>>(
        sc, v, nullptr, nullptr, att, SEQ, DK, SEQ,
        (long long)SEQ * SEQ, (long long)SEQ * DK, (long long)SEQ * DK, 1.f);

    // 6) y = xn + att@Wo + bo      (16384x1024x128)
    gemm_k<false, 1 | 4><<<dim3(DMODEL / BN, MS / BM, 1), 256>>>(
        att, Wo, bo, xn, y, MS, DMODEL, DK, 0, 0, 0, 1.f);

    // 7) h = ln2(y)
    ln_k<<<MS, 256>>>(y, ln2_g, ln2_b, h);

    // 8) act = gelu(h@W1 + b1)     (16384x4096x1024)
    gemm_k<false, 1 | 2><<<dim3(DFF / BN, MS / BM, 1), 256>>>(
        h, W1, b1, nullptr, act, MS, DFF, DMODEL, 0, 0, 0, 1.f);

    // 9) out = y + act@W2 + b2     (16384x1024x4096)
    gemm_k<false, 1 | 4><<<dim3(DMODEL / BN, MS / BM, 1), 256>>>(
        act, W2, b2, y, out, MS, DMODEL, DFF, 0, 0, 0, 1.f);
}

// round 4
// speedup vs baseline: 1.8492x; 1.8492x over previous
#include <cuda_runtime.h>
#include <cuda_bf16.h>
#include <math.h>
#include <stdint.h>

#define BATCH 8
#define SEQ   2048
#define DMODEL 1024
#define DKV   128
#define DFF   4096
#define MS    (BATCH*SEQ)

// ---------------- scratch (static device globals) ----------------------------
__device__ float    g_xnF[(size_t)MS*DMODEL];
__device__ float    g_scF[(size_t)BATCH*SEQ*SEQ];
__device__ float    g_yF [(size_t)MS*DMODEL];

// bf16 hi/lo pairs stored as u32 (2 bf16 along the row / K dimension)
__device__ uint32_t g_xnH[(size_t)MS*DMODEL/2],  g_xnL[(size_t)MS*DMODEL/2];
__device__ uint32_t g_hH [(size_t)MS*DMODEL/2],  g_hL [(size_t)MS*DMODEL/2];
__device__ uint32_t g_qH [(size_t)MS*DKV/2],     g_qL [(size_t)MS*DKV/2];
__device__ uint32_t g_ktH[(size_t)BATCH*DKV*SEQ/2], g_ktL[(size_t)BATCH*DKV*SEQ/2];
__device__ uint32_t g_vH [(size_t)MS*DKV/2],     g_vL [(size_t)MS*DKV/2];
__device__ uint32_t g_pH [(size_t)BATCH*SEQ*SEQ/2], g_pL[(size_t)BATCH*SEQ*SEQ/2];
__device__ uint32_t g_atH[(size_t)MS*DKV/2],     g_atL[(size_t)MS*DKV/2];
__device__ uint32_t g_acH[(size_t)MS*DFF/2],     g_acL[(size_t)MS*DFF/2];

__device__ uint32_t g_wqH[(size_t)DMODEL*DKV/2], g_wqL[(size_t)DMODEL*DKV/2];
__device__ uint32_t g_wkH[(size_t)DMODEL*DKV/2], g_wkL[(size_t)DMODEL*DKV/2];
__device__ uint32_t g_wvH[(size_t)DMODEL*DKV/2], g_wvL[(size_t)DMODEL*DKV/2];
__device__ uint32_t g_woH[(size_t)DKV*DMODEL/2], g_woL[(size_t)DKV*DMODEL/2];
__device__ uint32_t g_w1H[(size_t)DMODEL*DFF/2], g_w1L[(size_t)DMODEL*DFF/2];
__device__ uint32_t g_w2H[(size_t)DFF*DMODEL/2], g_w2L[(size_t)DFF*DMODEL/2];

// ---------------- helpers ----------------------------------------------------
__device__ __forceinline__ uint32_t smem_u32(const void* p) {
    uint32_t a;
    asm("{ .reg .u64 t; cvta.to.shared.u64 t, %1; cvt.u32.u64 %0, t; }" : "=r"(a) : "l"(p));
    return a;
}
__device__ __forceinline__ void cpasync16(uint32_t dst, const void* src) {
    asm volatile("cp.async.cg.shared.global [%0], [%1], 16;" :: "r"(dst), "l"(src));
}
#define CP_COMMIT() asm volatile("cp.async.commit_group;" ::: "memory")
#define CP_WAIT1()  asm volatile("cp.async.wait_group 1;" ::: "memory")

__device__ __forceinline__ void ldm_x4(uint32_t r[4], uint32_t addr) {
    asm volatile("ldmatrix.sync.aligned.m8n8.x4.shared.b16 {%0,%1,%2,%3}, [%4];"
                 : "=r"(r[0]), "=r"(r[1]), "=r"(r[2]), "=r"(r[3]) : "r"(addr));
}
__device__ __forceinline__ void ldm_x4_t(uint32_t r[4], uint32_t addr) {
    asm volatile("ldmatrix.sync.aligned.m8n8.x4.trans.shared.b16 {%0,%1,%2,%3}, [%4];"
                 : "=r"(r[0]), "=r"(r[1]), "=r"(r[2]), "=r"(r[3]) : "r"(addr));
}
__device__ __forceinline__ void mma16816(float c[4], const uint32_t a[4], const uint32_t b[2]) {
    asm volatile("mma.sync.aligned.m16n8k16.row.col.f32.bf16.bf16.f32 "
                 "{%0,%1,%2,%3},{%4,%5,%6,%7},{%8,%9},{%0,%1,%2,%3};"
                 : "+f"(c[0]), "+f"(c[1]), "+f"(c[2]), "+f"(c[3])
                 : "r"(a[0]), "r"(a[1]), "r"(a[2]), "r"(a[3]), "r"(b[0]), "r"(b[1]));
}
__device__ __forceinline__ void split2(float a, float b, uint32_t& hi, uint32_t& lo) {
    __nv_bfloat16 ha = __float2bfloat16_rn(a);
    __nv_bfloat16 hb = __float2bfloat16_rn(b);
    __nv_bfloat16 la = __float2bfloat16_rn(a - __bfloat162float(ha));
    __nv_bfloat16 lb = __float2bfloat16_rn(b - __bfloat162float(hb));
    hi = (uint32_t)__bfloat16_as_ushort(ha) | ((uint32_t)__bfloat16_as_ushort(hb) << 16);
    lo = (uint32_t)__bfloat16_as_ushort(la) | ((uint32_t)__bfloat16_as_ushort(lb) << 16);
}
__device__ __forceinline__ float gelu1(float v) {
    return 0.5f * v * (1.0f + erff(v * 0.70710678118654752f));
}

// ---------------- weight splitter: W [K,N] f32 -> hi/lo bf16 (same layout) ----
__global__ __launch_bounds__(256) void wconv(const float* __restrict__ W,
                                             uint32_t* __restrict__ H,
                                             uint32_t* __restrict__ L,
                                             int npairs)
{
    int u = blockIdx.x * 256 + threadIdx.x;
    if (u >= npairs) return;
    float2 v = *(const float2*)(W + (size_t)u * 2);
    uint32_t h, l;
    split2(v.x, v.y, h, l);
    H[u] = h; L[u] = l;
}

// ---------------- LayerNorm: one row/block, f32(optional) + bf16 pair emit ----
template<bool WF32>
__global__ __launch_bounds__(256) void ln_frag(const float* __restrict__ x,
                                               const float* __restrict__ g,
                                               const float* __restrict__ b,
                                               float* __restrict__ oF,
                                               uint32_t* __restrict__ H,
                                               uint32_t* __restrict__ L)
{
    const int row = blockIdx.x;
    const int tid = threadIdx.x;
    const float* xr = x + (size_t)row * DMODEL;
    float4 v = *(const float4*)(xr + tid * 4);

    float s  = v.x + v.y + v.z + v.w;
    float s2 = v.x*v.x + v.y*v.y + v.z*v.z + v.w*v.w;
    #pragma unroll
    for (int off = 16; off; off >>= 1) {
        s  += __shfl_xor_sync(0xffffffffu, s,  off);
        s2 += __shfl_xor_sync(0xffffffffu, s2, off);
    }
    __shared__ float ss[8], ss2[8], stats[2];
    const int wid = tid >> 5, lane = tid & 31;
    if (lane == 0) { ss[wid] = s; ss2[wid] = s2; }
    __syncthreads();
    if (wid == 0) {
        s  = (lane < 8) ? ss[lane]  : 0.f;
        s2 = (lane < 8) ? ss2[lane] : 0.f;
        #pragma unroll
        for (int off = 4; off; off >>= 1) {
            s  += __shfl_xor_sync(0xffffffffu, s,  off);
            s2 += __shfl_xor_sync(0xffffffffu, s2, off);
        }
        if (lane == 0) {
            float mean = s * (1.0f / DMODEL);
            float var  = s2 * (1.0f / DMODEL) - mean * mean;
            stats[0] = mean;
            stats[1] = rsqrtf(var + 1e-5f);
        }
    }
    __syncthreads();
    const float mean = stats[0], rstd = stats[1];
    float4 gg = *(const float4*)(g + tid * 4);
    float4 bb = *(const float4*)(b + tid * 4);
    float4 o;
    o.x = (v.x - mean) * rstd * gg.x + bb.x;
    o.y = (v.y - mean) * rstd * gg.y + bb.y;
    o.z = (v.z - mean) * rstd * gg.z + bb.z;
    o.w = (v.w - mean) * rstd * gg.w + bb.w;
    if (WF32) *(float4*)(oF + (size_t)row * DMODEL + tid * 4) = o;
    uint32_t h0, l0, h1, l1;
    split2(o.x, o.y, h0, l0);
    split2(o.z, o.w, h1, l1);
    size_t base = (size_t)row * (DMODEL / 2) + tid * 2;
    H[base] = h0; H[base + 1] = h1;
    L[base] = l0; L[base + 1] = l1;
}

// ---------------- softmax: one row/block, emits probs bf16 pairs --------------
__global__ __launch_bounds__(256) void softmax_frag(const float* __restrict__ S,
                                                    uint32_t* __restrict__ H,
                                                    uint32_t* __restrict__ L)
{
    const size_t row = blockIdx.x;
    const float* p = S + row * (size_t)SEQ;
    const int tid = threadIdx.x;
    float4 a = *(const float4*)(p + tid * 4);
    float4 c = *(const float4*)(p + 1024 + tid * 4);

    float m = fmaxf(fmaxf(fmaxf(a.x, a.y), fmaxf(a.z, a.w)),
                    fmaxf(fmaxf(c.x, c.y), fmaxf(c.z, c.w)));
    #pragma unroll
    for (int off = 16; off; off >>= 1)
        m = fmaxf(m, __shfl_xor_sync(0xffffffffu, m, off));
    __shared__ float sm[8], sred[2];
    const int wid = tid >> 5, lane = tid & 31;
    if (lane == 0) sm[wid] = m;
    __syncthreads();
    if (wid == 0) {
        m = (lane < 8) ? sm[lane] : -1e30f;
        #pragma unroll
        for (int off = 4; off; off >>= 1)
            m = fmaxf(m, __shfl_xor_sync(0xffffffffu, m, off));
        if (lane == 0) sred[0] = m;
    }
    __syncthreads();
    m = sred[0];

    a.x = expf(a.x - m); a.y = expf(a.y - m); a.z = expf(a.z - m); a.w = expf(a.w - m);
    c.x = expf(c.x - m); c.y = expf(c.y - m); c.z = expf(c.z - m); c.w = expf(c.w - m);
    float s = a.x + a.y + a.z + a.w + c.x + c.y + c.z + c.w;
    #pragma unroll
    for (int off = 16; off; off >>= 1)
        s += __shfl_xor_sync(0xffffffffu, s, off);
    if (lane == 0) sm[wid] = s;
    __syncthreads();
    if (wid == 0) {
        s = (lane < 8) ? sm[lane] : 0.f;
        #pragma unroll
        for (int off = 4; off; off >>= 1)
            s += __shfl_xor_sync(0xffffffffu, s, off);
        if (lane == 0) sred[1] = 1.0f / s;
    }
    __syncthreads();
    const float r = sred[1];
    a.x *= r; a.y *= r; a.z *= r; a.w *= r;
    c.x *= r; c.y *= r; c.z *= r; c.w *= r;

    uint32_t h, l;
    size_t base = row * (SEQ / 2) + tid * 2;
    split2(a.x, a.y, h, l); H[base] = h;       L[base] = l;
    split2(a.z, a.w, h, l); H[base + 1] = h;   L[base + 1] = l;
    base += 512;
    split2(c.x, c.y, h, l); H[base] = h;       L[base] = l;
    split2(c.z, c.w, h, l); H[base + 1] = h;   L[base + 1] = l;
}

// ---------------- HMMA GEMM 128x128, BK=64, 3-pass bf16 split -----------------
// A: [M,Ka] bf16 pairs (hi/lo). B: [K,Nb] bf16 pairs. C: [M,Nb].
// EMIT: 0 = f32 out; 1 = bf16 hi/lo pairs (A-layout for next GEMM);
//       2 = transposed bf16 emit for k -> kT[b][d][s].
// EPI bits: 1=+bias[col], 2=gelu, 4=+res (f32, same shape as C).
#define EM_F32 0
#define EM_BF  1
#define EM_BFT 2

template<int EMIT, int EPI>
__global__ __launch_bounds__(256, 1)
void hgemm(const uint32_t* __restrict__ Ah, const uint32_t* __restrict__ Al,
           const uint32_t* __restrict__ Bh, const uint32_t* __restrict__ Bl,
           const float* __restrict__ bias, const float* __restrict__ res,
           float* __restrict__ outF, uint32_t* __restrict__ outH, uint32_t* __restrict__ outL,
           int Ka, int Nb, int nc,
           long long sAu, long long sBu, long long sCf, long long sOu,
           float alpha)
{
    extern __shared__ char smc[];
    const uint32_t sb = smem_u32(smc);
    const int tid = threadIdx.x, wid = tid >> 5, lane = tid & 31;
    const int wm = wid >> 2, wn = wid & 3;              // 2 x 4 warp grid
    const int bx = blockIdx.x, by = blockIdx.y, bz = blockIdx.z;

    const uint32_t Ka2 = (uint32_t)Ka >> 1, Nb2 = (uint32_t)Nb >> 1;
    const uint32_t* Ahb = Ah + (size_t)bz * sAu;
    const uint32_t* Alb = Al + (size_t)bz * sAu;
    const uint32_t* Bhb = Bh + (size_t)bz * sBu;
    const uint32_t* Blb = Bl + (size_t)bz * sBu;

    // stage layout: Ahi 0 | Alo 16K | Bhi 32K | Blo 48K  (64KB/stage, 3 stages)
    auto load_stage = [&](int st, int c) {
        const uint32_t stb = sb + st * 65536;
        #pragma unroll
        for (int t = 0; t < 4; t++) {       // A: 1024 chunks of 16B per buffer
            int id = tid + t * 256;
            int m = id >> 3, ch = id & 7;
            size_t go = (size_t)(by * 128 + m) * Ka2 + (size_t)c * 32 + ch * 4;
            uint32_t sa = stb + m * 128 + ((ch ^ (m & 7)) << 4);
            cpasync16(sa, Ahb + go);
            cpasync16(sa + 16384, Alb + go);
        }
        #pragma unroll
        for (int t = 0; t < 4; t++) {       // B: 64 k-rows x 256B
            int id = tid + t * 256;
            int k = id >> 4, ch = id & 15;
            size_t go = (size_t)(c * 64 + k) * Nb2 + (size_t)bx * 64 + ch * 4;
            uint32_t sa = stb + 32768 + k * 256 + ((ch ^ (k & 15)) << 4);
            cpasync16(sa, Bhb + go);
            cpasync16(sa + 16384, Blb + go);
        }
    };

    float acc[4][4][4];
    #pragma unroll
    for (int i = 0; i < 4; i++)
        #pragma unroll
        for (int j = 0; j < 4; j++)
            #pragma unroll
            for (int r = 0; r < 4; r++) acc[i][j][r] = 0.f;

    load_stage(0, 0); CP_COMMIT();
    load_stage(1, 1); CP_COMMIT();

    const int q = lane >> 3, l7 = lane & 7;

    for (int c = 0; c < nc; ++c) {
        CP_WAIT1();
        __syncthreads();
        if (c + 2 < nc) load_stage((c + 2) % 3, c + 2);
        CP_COMMIT();

        const uint32_t stb = sb + (c % 3) * 65536;
        #pragma unroll
        for (int ks = 0; ks < 4; ks++) {
            uint32_t aH[4][4], aL[4][4], bH4[2][4], bL4[2][4];
            #pragma unroll
            for (int i = 0; i < 4; i++) {
                int m = wm * 64 + i * 16 + ((q & 1) << 3) + l7;
                int ch = 2 * ks + (q >> 1);
                uint32_t ad = stb + m * 128 + ((ch ^ (m & 7)) << 4);
                ldm_x4(aH[i], ad);
                ldm_x4(aL[i], ad + 16384);
            }
            #pragma unroll
            for (int g = 0; g < 2; g++) {
                int k = ks * 16 + ((q & 1) << 3) + l7;
                int ch = wn * 4 + g * 2 + (q >> 1);
                uint32_t bd = stb + 32768 + k * 256 + ((ch ^ (k & 15)) << 4);
                ldm_x4_t(bH4[g], bd);
                ldm_x4_t(bL4[g], bd + 16384);
            }
            #pragma unroll
            for (int i = 0; i < 4; i++)
                #pragma unroll
                for (int j = 0; j < 4; j++) {
                    const uint32_t* bh = &bH4[j >> 1][(j & 1) * 2];
                    const uint32_t* bl = &bL4[j >> 1][(j & 1) * 2];
                    mma16816(acc[i][j], aH[i], bh);
                    mma16816(acc[i][j], aH[i], bl);
                    mma16816(acc[i][j], aL[i], bh);
                }
        }
    }

    // ---- epilogue: stage C tile in smem [128][132] ----
    __syncthreads();
    float* Cs = (float*)smc;
    #pragma unroll
    for (int i = 0; i < 4; i++)
        #pragma unroll
        for (int j = 0; j < 4; j++) {
            int r0 = wm * 64 + i * 16 + (lane >> 2);
            int c0 = wn * 32 + j * 8 + 2 * (lane & 3);
            *(float2*)(Cs + r0 * 132 + c0)       = make_float2(acc[i][j][0], acc[i][j][1]);
            *(float2*)(Cs + (r0 + 8) * 132 + c0) = make_float2(acc[i][j][2], acc[i][j][3]);
        }
    __syncthreads();

    if (EMIT == EM_F32) {
        #pragma unroll
        for (int i = 0; i < 16; i++) {
            int u = tid + 256 * i;
            int row = u >> 5, c4 = (u & 31) * 4;
            float4 v = *(float4*)(Cs + row * 132 + c4);
            v.x *= alpha; v.y *= alpha; v.z *= alpha; v.w *= alpha;
            int gc = bx * 128 + c4;
            size_t gm = (size_t)by * 128 + row;
            if (EPI & 1) {
                float4 bb = *(const float4*)(bias + gc);
                v.x += bb.x; v.y += bb.y; v.z += bb.z; v.w += bb.w;
            }
            if (EPI & 2) { v.x = gelu1(v.x); v.y = gelu1(v.y); v.z = gelu1(v.z); v.w = gelu1(v.w); }
            if (EPI & 4) {
                float4 rr = *(const float4*)(res + gm * Nb + gc);
                v.x += rr.x; v.y += rr.y; v.z += rr.z; v.w += rr.w;
            }
            *(float4*)(outF + (size_t)bz * sCf + gm * Nb + gc) = v;
        }
    } else if (EMIT == EM_BF) {
        #pragma unroll
        for (int i = 0; i < 32; i++) {
            int u = tid + 256 * i;
            int row = u >> 6, np = u & 63;
            float v0 = Cs[row * 132 + 2 * np]     * alpha;
            float v1 = Cs[row * 132 + 2 * np + 1] * alpha;
            int gc = bx * 128 + 2 * np;
            if (EPI & 1) { v0 += __ldg(bias + gc); v1 += __ldg(bias + gc + 1); }
            if (EPI & 2) { v0 = gelu1(v0); v1 = gelu1(v1); }
            uint32_t h, l;
            split2(v0, v1, h, l);
            size_t gm = (size_t)by * 128 + row;
            size_t idx = (size_t)bz * sOu + gm * (Nb >> 1) + (size_t)bx * 64 + np;
            outH[idx] = h; outL[idx] = l;
        }
    } else { // EM_BFT: k -> kT[b][d][s] bf16 pairs along s  (QKV launch: bz=0, Nb=128)
        const int b = by >> 4;                 // 2048/128 = 16 M-tiles per batch
        const int s0p = (by & 15) * 64;        // s-pair offset within batch
        #pragma unroll
        for (int i = 0; i < 32; i++) {
            int u = tid + 256 * i;
            int d = u >> 6, sp = u & 63;
            float v0 = Cs[(2 * sp) * 132 + d]     * alpha;
            float v1 = Cs[(2 * sp + 1) * 132 + d] * alpha;
            if (EPI & 1) { float bb = __ldg(bias + bx * 128 + d); v0 += bb; v1 += bb; }
            uint32_t h, l;
            split2(v0, v1, h, l);
            size_t idx = (size_t)b * (DKV * SEQ / 2) + (size_t)d * (SEQ / 2) + s0p + sp;
            outH[idx] = h; outL[idx] = l;
        }
    }
}

// ---------------- launch sequence -------------------------------------------
extern "C" void kernel_launch(void* const* d_in, const int* in_sizes, int n_in,
                              void* d_out, int out_size)
{
    const float* x     = (const float*)d_in[0];
    const float* ln1_g = (const float*)d_in[1];
    const float* ln1_b = (const float*)d_in[2];
    const float* Wq    = (const float*)d_in[3];
    const float* bq    = (const float*)d_in[4];
    const float* Wk    = (const float*)d_in[5];
    const float* bk    = (const float*)d_in[6];
    const float* Wv    = (const float*)d_in[7];
    const float* bv    = (const float*)d_in[8];
    const float* Wo    = (const float*)d_in[9];
    const float* bo    = (const float*)d_in[10];
    const float* ln2_g = (const float*)d_in[11];
    const float* ln2_b = (const float*)d_in[12];
    const float* W1    = (const float*)d_in[13];
    const float* b1    = (const float*)d_in[14];
    const float* W2    = (const float*)d_in[15];
    const float* b2    = (const float*)d_in[16];
    float* out = (float*)d_out;

    float *xnF, *scF, *yF;
    uint32_t *xnH,*xnL,*hH,*hL,*qH,*qL,*ktH,*ktL,*vH,*vL,*pH,*pL,*atH,*atL,*acH,*acL;
    uint32_t *wqH,*wqL,*wkH,*wkL,*wvH,*wvL,*woH,*woL,*w1H,*w1L,*w2H,*w2L;
    cudaGetSymbolAddress((void**)&xnF, g_xnF); cudaGetSymbolAddress((void**)&scF, g_scF);
    cudaGetSymbolAddress((void**)&yF,  g_yF);
    cudaGetSymbolAddress((void**)&xnH, g_xnH); cudaGetSymbolAddress((void**)&xnL, g_xnL);
    cudaGetSymbolAddress((void**)&hH,  g_hH);  cudaGetSymbolAddress((void**)&hL,  g_hL);
    cudaGetSymbolAddress((void**)&qH,  g_qH);  cudaGetSymbolAddress((void**)&qL,  g_qL);
    cudaGetSymbolAddress((void**)&ktH, g_ktH); cudaGetSymbolAddress((void**)&ktL, g_ktL);
    cudaGetSymbolAddress((void**)&vH,  g_vH);  cudaGetSymbolAddress((void**)&vL,  g_vL);
    cudaGetSymbolAddress((void**)&pH,  g_pH);  cudaGetSymbolAddress((void**)&pL,  g_pL);
    cudaGetSymbolAddress((void**)&atH, g_atH); cudaGetSymbolAddress((void**)&atL, g_atL);
    cudaGetSymbolAddress((void**)&acH, g_acH); cudaGetSymbolAddress((void**)&acL, g_acL);
    cudaGetSymbolAddress((void**)&wqH, g_wqH); cudaGetSymbolAddress((void**)&wqL, g_wqL);
    cudaGetSymbolAddress((void**)&wkH, g_wkH); cudaGetSymbolAddress((void**)&wkL, g_wkL);
    cudaGetSymbolAddress((void**)&wvH, g_wvH); cudaGetSymbolAddress((void**)&wvL, g_wvL);
    cudaGetSymbolAddress((void**)&woH, g_woH); cudaGetSymbolAddress((void**)&woL, g_woL);
    cudaGetSymbolAddress((void**)&w1H, g_w1H); cudaGetSymbolAddress((void**)&w1L, g_w1L);
    cudaGetSymbolAddress((void**)&w2H, g_w2H); cudaGetSymbolAddress((void**)&w2L, g_w2L);

    const int SM_GE = 3 * 65536;   // 192 KB
    cudaFuncSetAttribute(hgemm<EM_BF, 1>, cudaFuncAttributeMaxDynamicSharedMemorySize, SM_GE);
    cudaFuncSetAttribute(hgemm<EM_BFT,1>, cudaFuncAttributeMaxDynamicSharedMemorySize, SM_GE);
    cudaFuncSetAttribute(hgemm<EM_F32,0>, cudaFuncAttributeMaxDynamicSharedMemorySize, SM_GE);
    cudaFuncSetAttribute(hgemm<EM_BF, 0>, cudaFuncAttributeMaxDynamicSharedMemorySize, SM_GE);
    cudaFuncSetAttribute(hgemm<EM_F32,5>, cudaFuncAttributeMaxDynamicSharedMemorySize, SM_GE);
    cudaFuncSetAttribute(hgemm<EM_BF, 3>, cudaFuncAttributeMaxDynamicSharedMemorySize, SM_GE);

    const float scale = 0.08838834764831845f; // 1/sqrt(128)

    // weights -> bf16 hi/lo (elementwise, same [K,N] layout)
    wconv<<<(DMODEL*DKV/2)/256, 256>>>(Wq, wqH, wqL, DMODEL*DKV/2);
    wconv<<<(DMODEL*DKV/2)/256, 256>>>(Wk, wkH, wkL, DMODEL*DKV/2);
    wconv<<<(DMODEL*DKV/2)/256, 256>>>(Wv, wvH, wvL, DMODEL*DKV/2);
    wconv<<<(DKV*DMODEL/2)/256, 256>>>(Wo, woH, woL, DKV*DMODEL/2);
    wconv<<<(DMODEL*DFF/2)/256, 256>>>(W1, w1H, w1L, DMODEL*DFF/2);
    wconv<<<(DFF*DMODEL/2)/256, 256>>>(W2, w2H, w2L, DFF*DMODEL/2);

    // 1) ln1 -> xn (f32 + bf16 pairs)
    ln_frag<true><<<MS, 256>>>(x, ln1_g, ln1_b, xnF, xnH, xnL);

    // 2) q/k/v projections (16384 x 128 x 1024)
    hgemm<EM_BF, 1><<<dim3(1,128,1), 256, SM_GE>>>(xnH, xnL, wqH, wqL, bq, nullptr,
        nullptr, qH, qL, DMODEL, DKV, 16, 0, 0, 0, 0, 1.f);
    hgemm<EM_BFT, 1><<<dim3(1,128,1), 256, SM_GE>>>(xnH, xnL, wkH, wkL, bk, nullptr,
        nullptr, ktH, ktL, DMODEL, DKV, 16, 0, 0, 0, 0, 1.f);
    hgemm<EM_BF, 1><<<dim3(1,128,1), 256, SM_GE>>>(xnH, xnL, wvH, wvL, bv, nullptr,
        nullptr, vH, vL, DMODEL, DKV, 16, 0, 0, 0, 0, 1.f);

    // 3) scores = q @ kT * scale   (per batch 2048 x 2048 x 128)
    hgemm<EM_F32, 0><<<dim3(16,16,8), 256, SM_GE>>>(qH, qL, ktH, ktL, nullptr, nullptr,
        scF, nullptr, nullptr, DKV, SEQ, 2,
        (long long)SEQ*DKV/2, (long long)DKV*SEQ/2, (long long)SEQ*SEQ, 0, scale);

    // 4) softmax -> probs bf16 pairs
    softmax_frag<<<BATCH*SEQ, 256>>>(scF, pH, pL);

    // 5) att = probs @ v           (per batch 2048 x 128 x 2048)
    hgemm<EM_BF, 0><<<dim3(1,16,8), 256, SM_GE>>>(pH, pL, vH, vL, nullptr, nullptr,
        nullptr, atH, atL, SEQ, DKV, 32,
        (long long)SEQ*SEQ/2, (long long)SEQ*DKV/2, 0, (long long)SEQ*DKV/2, 1.f);

    // 6) y = xn + att@Wo + bo      (16384 x 1024 x 128)
    hgemm<EM_F32, 5><<<dim3(8,128,1), 256, SM_GE>>>(atH, atL, woH, woL, bo, xnF,
        yF, nullptr, nullptr, DKV, DMODEL, 2, 0, 0, 0, 0, 1.f);

    // 7) ln2 -> h bf16 pairs
    ln_frag<false><<<MS, 256>>>(yF, ln2_g, ln2_b, nullptr, hH, hL);

    // 8) act = gelu(h@W1 + b1)     (16384 x 4096 x 1024)
    hgemm<EM_BF, 3><<<dim3(32,128,1), 256, SM_GE>>>(hH, hL, w1H, w1L, b1, nullptr,
        nullptr, acH, acL, DMODEL, DFF, 16, 0, 0, 0, 0, 1.f);

    // 9) out = y + act@W2 + b2     (16384 x 1024 x 4096)
    hgemm<EM_F32, 5><<<dim3(8,128,1), 256, SM_GE>>>(acH, acL, w2H, w2L, b2, yF,
        out, nullptr, nullptr, DFF, DMODEL, 64, 0, 0, 0, 0, 1.f);
}

// round 5
// speedup vs baseline: 2.7687x; 1.4972x over previous
#include <cuda_runtime.h>
#include <cuda_bf16.h>
#include <math.h>
#include <stdint.h>

#define BATCH 8
#define SEQ   2048
#define DMODEL 1024
#define DKV   128
#define DFF   4096
#define MS    (BATCH*SEQ)

// ---------------- scratch (static device globals) ----------------------------
__device__ float    g_xnF[(size_t)MS*DMODEL];
__device__ float    g_scF[(size_t)BATCH*SEQ*SEQ];
__device__ float    g_yF [(size_t)MS*DMODEL];

__device__ uint32_t g_xnH[(size_t)MS*DMODEL/2],  g_xnL[(size_t)MS*DMODEL/2];
__device__ uint32_t g_hH [(size_t)MS*DMODEL/2],  g_hL [(size_t)MS*DMODEL/2];
__device__ uint32_t g_qH [(size_t)MS*DKV/2],     g_qL [(size_t)MS*DKV/2];
__device__ uint32_t g_ktH[(size_t)BATCH*DKV*SEQ/2], g_ktL[(size_t)BATCH*DKV*SEQ/2];
__device__ uint32_t g_vH [(size_t)MS*DKV/2],     g_vL [(size_t)MS*DKV/2];
__device__ uint32_t g_pH [(size_t)BATCH*SEQ*SEQ/2], g_pL[(size_t)BATCH*SEQ*SEQ/2];
__device__ uint32_t g_atH[(size_t)MS*DKV/2],     g_atL[(size_t)MS*DKV/2];
__device__ uint32_t g_acH[(size_t)MS*DFF/2],     g_acL[(size_t)MS*DFF/2];

__device__ uint32_t g_wqkvH[(size_t)DMODEL*384/2], g_wqkvL[(size_t)DMODEL*384/2];
__device__ float    g_bqkv[384];
__device__ uint32_t g_woH[(size_t)DKV*DMODEL/2], g_woL[(size_t)DKV*DMODEL/2];
__device__ uint32_t g_w1H[(size_t)DMODEL*DFF/2], g_w1L[(size_t)DMODEL*DFF/2];
__device__ uint32_t g_w2H[(size_t)DFF*DMODEL/2], g_w2L[(size_t)DFF*DMODEL/2];

// ---------------- helpers ----------------------------------------------------
__device__ __forceinline__ uint32_t smem_u32(const void* p) {
    uint32_t a;
    asm("{ .reg .u64 t; cvta.to.shared.u64 t, %1; cvt.u32.u64 %0, t; }" : "=r"(a) : "l"(p));
    return a;
}
__device__ __forceinline__ void cpasync16(uint32_t dst, const void* src) {
    asm volatile("cp.async.cg.shared.global [%0], [%1], 16;" :: "r"(dst), "l"(src));
}
#define CP_COMMIT() asm volatile("cp.async.commit_group;" ::: "memory")
#define CP_WAIT1()  asm volatile("cp.async.wait_group 1;" ::: "memory")

__device__ __forceinline__ void ldm_x4(uint32_t r[4], uint32_t addr) {
    asm volatile("ldmatrix.sync.aligned.m8n8.x4.shared.b16 {%0,%1,%2,%3}, [%4];"
                 : "=r"(r[0]), "=r"(r[1]), "=r"(r[2]), "=r"(r[3]) : "r"(addr));
}
__device__ __forceinline__ void ldm_x4_t(uint32_t r[4], uint32_t addr) {
    asm volatile("ldmatrix.sync.aligned.m8n8.x4.trans.shared.b16 {%0,%1,%2,%3}, [%4];"
                 : "=r"(r[0]), "=r"(r[1]), "=r"(r[2]), "=r"(r[3]) : "r"(addr));
}
__device__ __forceinline__ void mma16816(float c[4], const uint32_t a[4], const uint32_t b[2]) {
    asm volatile("mma.sync.aligned.m16n8k16.row.col.f32.bf16.bf16.f32 "
                 "{%0,%1,%2,%3},{%4,%5,%6,%7},{%8,%9},{%0,%1,%2,%3};"
                 : "+f"(c[0]), "+f"(c[1]), "+f"(c[2]), "+f"(c[3])
                 : "r"(a[0]), "r"(a[1]), "r"(a[2]), "r"(a[3]), "r"(b[0]), "r"(b[1]));
}
__device__ __forceinline__ void split2(float a, float b, uint32_t& hi, uint32_t& lo) {
    __nv_bfloat16 ha = __float2bfloat16_rn(a);
    __nv_bfloat16 hb = __float2bfloat16_rn(b);
    __nv_bfloat16 la = __float2bfloat16_rn(a - __bfloat162float(ha));
    __nv_bfloat16 lb = __float2bfloat16_rn(b - __bfloat162float(hb));
    hi = (uint32_t)__bfloat16_as_ushort(ha) | ((uint32_t)__bfloat16_as_ushort(hb) << 16);
    lo = (uint32_t)__bfloat16_as_ushort(la) | ((uint32_t)__bfloat16_as_ushort(lb) << 16);
}
__device__ __forceinline__ float gelu1(float v) {
    return 0.5f * v * (1.0f + erff(v * 0.70710678118654752f));
}

// ---------------- one-shot weight conversion (all weights, one launch) -------
struct WJobs {
    const float* src[6];
    uint32_t* H[6];
    uint32_t* L[6];
    int np[6];      // pairs
    int srcP[6];    // pairs per src row
    int dstP[6];    // pairs per dst row
    int coff[6];    // dst col offset in pairs
    int blkStart[7];
    const float* bq; const float* bk; const float* bv;
    float* bqkv;
};

__global__ __launch_bounds__(256) void wconv_all(WJobs jb)
{
    const int blk = blockIdx.x, tid = threadIdx.x;
    if (blk >= jb.blkStart[6]) {       // bias packing block
        if (tid < 128) {
            jb.bqkv[tid]       = jb.bq[tid];
            jb.bqkv[128 + tid] = jb.bk[tid];
            jb.bqkv[256 + tid] = jb.bv[tid];
        }
        return;
    }
    int seg = 0;
    #pragma unroll
    for (int s = 1; s < 6; s++) if (blk >= jb.blkStart[s]) seg = s;
    int u = (blk - jb.blkStart[seg]) * 256 + tid;
    if (u >= jb.np[seg]) return;
    int k = u / jb.srcP[seg], p = u - k * jb.srcP[seg];
    float2 v = *(const float2*)(jb.src[seg] + ((size_t)u) * 2);
    uint32_t h, l;
    split2(v.x, v.y, h, l);
    size_t di = (size_t)k * jb.dstP[seg] + jb.coff[seg] + p;
    jb.H[seg][di] = h; jb.L[seg][di] = l;
}

// ---------------- LayerNorm: one row/block, f32(optional) + bf16 pair emit ----
template<bool WF32>
__global__ __launch_bounds__(256) void ln_frag(const float* __restrict__ x,
                                               const float* __restrict__ g,
                                               const float* __restrict__ b,
                                               float* __restrict__ oF,
                                               uint32_t* __restrict__ H,
                                               uint32_t* __restrict__ L)
{
    const int row = blockIdx.x;
    const int tid = threadIdx.x;
    const float* xr = x + (size_t)row * DMODEL;
    float4 v = *(const float4*)(xr + tid * 4);

    float s  = v.x + v.y + v.z + v.w;
    float s2 = v.x*v.x + v.y*v.y + v.z*v.z + v.w*v.w;
    #pragma unroll
    for (int off = 16; off; off >>= 1) {
        s  += __shfl_xor_sync(0xffffffffu, s,  off);
        s2 += __shfl_xor_sync(0xffffffffu, s2, off);
    }
    __shared__ float ss[8], ss2[8], stats[2];
    const int wid = tid >> 5, lane = tid & 31;
    if (lane == 0) { ss[wid] = s; ss2[wid] = s2; }
    __syncthreads();
    if (wid == 0) {
        s  = (lane < 8) ? ss[lane]  : 0.f;
        s2 = (lane < 8) ? ss2[lane] : 0.f;
        #pragma unroll
        for (int off = 4; off; off >>= 1) {
            s  += __shfl_xor_sync(0xffffffffu, s,  off);
            s2 += __shfl_xor_sync(0xffffffffu, s2, off);
        }
        if (lane == 0) {
            float mean = s * (1.0f / DMODEL);
            float var  = s2 * (1.0f / DMODEL) - mean * mean;
            stats[0] = mean;
            stats[1] = rsqrtf(var + 1e-5f);
        }
    }
    __syncthreads();
    const float mean = stats[0], rstd = stats[1];
    float4 gg = *(const float4*)(g + tid * 4);
    float4 bb = *(const float4*)(b + tid * 4);
    float4 o;
    o.x = (v.x - mean) * rstd * gg.x + bb.x;
    o.y = (v.y - mean) * rstd * gg.y + bb.y;
    o.z = (v.z - mean) * rstd * gg.z + bb.z;
    o.w = (v.w - mean) * rstd * gg.w + bb.w;
    if (WF32) *(float4*)(oF + (size_t)row * DMODEL + tid * 4) = o;
    uint32_t h0, l0, h1, l1;
    split2(o.x, o.y, h0, l0);
    split2(o.z, o.w, h1, l1);
    size_t base = (size_t)row * (DMODEL / 2) + tid * 2;
    H[base] = h0; H[base + 1] = h1;
    L[base] = l0; L[base + 1] = l1;
}

// ---------------- softmax: one row/block, emits probs bf16 pairs --------------
__global__ __launch_bounds__(256) void softmax_frag(const float* __restrict__ S,
                                                    uint32_t* __restrict__ H,
                                                    uint32_t* __restrict__ L)
{
    const size_t row = blockIdx.x;
    const float* p = S + row * (size_t)SEQ;
    const int tid = threadIdx.x;
    float4 a = *(const float4*)(p + tid * 4);
    float4 c = *(const float4*)(p + 1024 + tid * 4);

    float m = fmaxf(fmaxf(fmaxf(a.x, a.y), fmaxf(a.z, a.w)),
                    fmaxf(fmaxf(c.x, c.y), fmaxf(c.z, c.w)));
    #pragma unroll
    for (int off = 16; off; off >>= 1)
        m = fmaxf(m, __shfl_xor_sync(0xffffffffu, m, off));
    __shared__ float sm[8], sred[2];
    const int wid = tid >> 5, lane = tid & 31;
    if (lane == 0) sm[wid] = m;
    __syncthreads();
    if (wid == 0) {
        m = (lane < 8) ? sm[lane] : -1e30f;
        #pragma unroll
        for (int off = 4; off; off >>= 1)
            m = fmaxf(m, __shfl_xor_sync(0xffffffffu, m, off));
        if (lane == 0) sred[0] = m;
    }
    __syncthreads();
    m = sred[0];

    a.x = expf(a.x - m); a.y = expf(a.y - m); a.z = expf(a.z - m); a.w = expf(a.w - m);
    c.x = expf(c.x - m); c.y = expf(c.y - m); c.z = expf(c.z - m); c.w = expf(c.w - m);
    float s = a.x + a.y + a.z + a.w + c.x + c.y + c.z + c.w;
    #pragma unroll
    for (int off = 16; off; off >>= 1)
        s += __shfl_xor_sync(0xffffffffu, s, off);
    if (lane == 0) sm[wid] = s;
    __syncthreads();
    if (wid == 0) {
        s = (lane < 8) ? sm[lane] : 0.f;
        #pragma unroll
        for (int off = 4; off; off >>= 1)
            s += __shfl_xor_sync(0xffffffffu, s, off);
        if (lane == 0) sred[1] = 1.0f / s;
    }
    __syncthreads();
    const float r = sred[1];
    a.x *= r; a.y *= r; a.z *= r; a.w *= r;
    c.x *= r; c.y *= r; c.z *= r; c.w *= r;

    uint32_t h, l;
    size_t base = row * (SEQ / 2) + tid * 2;
    split2(a.x, a.y, h, l); H[base] = h;       L[base] = l;
    split2(a.z, a.w, h, l); H[base + 1] = h;   L[base + 1] = l;
    base += 512;
    split2(c.x, c.y, h, l); H[base] = h;       L[base] = l;
    split2(c.z, c.w, h, l); H[base + 1] = h;   L[base + 1] = l;
}

// ================= HMMA GEMM, BN=128 (3-stage), BK=64, 3-pass bf16 ===========
// EMIT: 0=f32, 1=bf16 pairs (A-layout), 3=fused QKV emit.
// EPI bits: 1=+bias[col], 2=gelu, 4=+res.
#define EM_F32 0
#define EM_BF  1
#define EM_QKV 3

template<int EMIT, int EPI>
__global__ __launch_bounds__(256, 1)
void hgemm(const uint32_t* __restrict__ Ah, const uint32_t* __restrict__ Al,
           const uint32_t* __restrict__ Bh, const uint32_t* __restrict__ Bl,
           const float* __restrict__ bias, const float* __restrict__ res,
           float* __restrict__ outF, uint32_t* __restrict__ outH, uint32_t* __restrict__ outL,
           uint32_t* __restrict__ outH2, uint32_t* __restrict__ outL2,
           uint32_t* __restrict__ outH3, uint32_t* __restrict__ outL3,
           int Ka, int Nb, int nc,
           long long sAu, long long sBu, long long sCf, long long sOu,
           float alpha)
{
    extern __shared__ char smc[];
    const uint32_t sb = smem_u32(smc);
    const int tid = threadIdx.x, wid = tid >> 5, lane = tid & 31;
    const int wm = wid >> 2, wn = wid & 3;
    const int bx = blockIdx.x, by = blockIdx.y, bz = blockIdx.z;

    const uint32_t Ka2 = (uint32_t)Ka >> 1, Nb2 = (uint32_t)Nb >> 1;
    const uint32_t* Ahb = Ah + (size_t)bz * sAu;
    const uint32_t* Alb = Al + (size_t)bz * sAu;
    const uint32_t* Bhb = Bh + (size_t)bz * sBu;
    const uint32_t* Blb = Bl + (size_t)bz * sBu;

    auto load_stage = [&](int st, int c) {
        const uint32_t stb = sb + st * 65536;
        #pragma unroll
        for (int t = 0; t < 4; t++) {
            int id = tid + t * 256;
            int m = id >> 3, ch = id & 7;
            size_t go = (size_t)(by * 128 + m) * Ka2 + (size_t)c * 32 + ch * 4;
            uint32_t sa = stb + m * 128 + ((ch ^ (m & 7)) << 4);
            cpasync16(sa, Ahb + go);
            cpasync16(sa + 16384, Alb + go);
        }
        #pragma unroll
        for (int t = 0; t < 4; t++) {
            int id = tid + t * 256;
            int k = id >> 4, ch = id & 15;
            size_t go = (size_t)(c * 64 + k) * Nb2 + (size_t)bx * 64 + ch * 4;
            uint32_t sa = stb + 32768 + k * 256 + ((ch ^ (k & 15)) << 4);
            cpasync16(sa, Bhb + go);
            cpasync16(sa + 16384, Blb + go);
        }
    };

    float acc[4][4][4];
    #pragma unroll
    for (int i = 0; i < 4; i++)
        #pragma unroll
        for (int j = 0; j < 4; j++)
            #pragma unroll
            for (int r = 0; r < 4; r++) acc[i][j][r] = 0.f;

    load_stage(0, 0); CP_COMMIT();
    load_stage(1, 1); CP_COMMIT();

    const int q = lane >> 3, l7 = lane & 7;

    for (int c = 0; c < nc; ++c) {
        CP_WAIT1();
        __syncthreads();
        if (c + 2 < nc) load_stage((c + 2) % 3, c + 2);
        CP_COMMIT();

        const uint32_t stb = sb + (c % 3) * 65536;
        #pragma unroll
        for (int ks = 0; ks < 4; ks++) {
            uint32_t aH[4][4], aL[4][4], bH4[2][4], bL4[2][4];
            #pragma unroll
            for (int i = 0; i < 4; i++) {
                int m = wm * 64 + i * 16 + ((q & 1) << 3) + l7;
                int ch = 2 * ks + (q >> 1);
                uint32_t ad = stb + m * 128 + ((ch ^ (m & 7)) << 4);
                ldm_x4(aH[i], ad);
                ldm_x4(aL[i], ad + 16384);
            }
            #pragma unroll
            for (int g = 0; g < 2; g++) {
                int k = ks * 16 + ((q & 1) << 3) + l7;
                int ch = wn * 4 + g * 2 + (q >> 1);
                uint32_t bd = stb + 32768 + k * 256 + ((ch ^ (k & 15)) << 4);
                ldm_x4_t(bH4[g], bd);
                ldm_x4_t(bL4[g], bd + 16384);
            }
            #pragma unroll
            for (int i = 0; i < 4; i++)
                #pragma unroll
                for (int j = 0; j < 4; j++) {
                    const uint32_t* bh = &bH4[j >> 1][(j & 1) * 2];
                    const uint32_t* bl = &bL4[j >> 1][(j & 1) * 2];
                    mma16816(acc[i][j], aH[i], bh);
                    mma16816(acc[i][j], aH[i], bl);
                    mma16816(acc[i][j], aL[i], bh);
                }
        }
    }

    // ---- epilogue: stage C tile in smem [128][132] ----
    __syncthreads();
    float* Cs = (float*)smc;
    #pragma unroll
    for (int i = 0; i < 4; i++)
        #pragma unroll
        for (int j = 0; j < 4; j++) {
            int r0 = wm * 64 + i * 16 + (lane >> 2);
            int c0 = wn * 32 + j * 8 + 2 * (lane & 3);
            *(float2*)(Cs + r0 * 132 + c0)       = make_float2(acc[i][j][0], acc[i][j][1]);
            *(float2*)(Cs + (r0 + 8) * 132 + c0) = make_float2(acc[i][j][2], acc[i][j][3]);
        }
    __syncthreads();

    if (EMIT == EM_F32) {
        #pragma unroll
        for (int i = 0; i < 16; i++) {
            int u = tid + 256 * i;
            int row = u >> 5, c4 = (u & 31) * 4;
            float4 v = *(float4*)(Cs + row * 132 + c4);
            v.x *= alpha; v.y *= alpha; v.z *= alpha; v.w *= alpha;
            int gc = bx * 128 + c4;
            size_t gm = (size_t)by * 128 + row;
            if (EPI & 1) {
                float4 bb = *(const float4*)(bias + gc);
                v.x += bb.x; v.y += bb.y; v.z += bb.z; v.w += bb.w;
            }
            if (EPI & 2) { v.x = gelu1(v.x); v.y = gelu1(v.y); v.z = gelu1(v.z); v.w = gelu1(v.w); }
            if (EPI & 4) {
                float4 rr = *(const float4*)(res + gm * Nb + gc);
                v.x += rr.x; v.y += rr.y; v.z += rr.z; v.w += rr.w;
            }
            *(float4*)(outF + (size_t)bz * sCf + gm * Nb + gc) = v;
        }
    } else if (EMIT == EM_BF) {
        #pragma unroll
        for (int i = 0; i < 32; i++) {
            int u = tid + 256 * i;
            int row = u >> 6, np = u & 63;
            float v0 = Cs[row * 132 + 2 * np]     * alpha;
            float v1 = Cs[row * 132 + 2 * np + 1] * alpha;
            int gc = bx * 128 + 2 * np;
            if (EPI & 1) { v0 += __ldg(bias + gc); v1 += __ldg(bias + gc + 1); }
            if (EPI & 2) { v0 = gelu1(v0); v1 = gelu1(v1); }
            uint32_t h, l;
            split2(v0, v1, h, l);
            size_t gm = (size_t)by * 128 + row;
            size_t idx = (size_t)bz * sOu + gm * (Nb >> 1) + (size_t)bx * 64 + np;
            outH[idx] = h; outL[idx] = l;
        }
    } else { // EM_QKV: bx=0 -> q pairs, bx=1 -> kT transposed, bx=2 -> v pairs
        if (bx == 1) {
            const int b = by >> 4;
            const int s0p = (by & 15) * 64;
            #pragma unroll
            for (int i = 0; i < 32; i++) {
                int u = tid + 256 * i;
                int d = u >> 6, sp = u & 63;
                float bb = __ldg(bias + 128 + d);
                float v0 = Cs[(2 * sp) * 132 + d]     + bb;
                float v1 = Cs[(2 * sp + 1) * 132 + d] + bb;
                uint32_t h, l;
                split2(v0, v1, h, l);
                size_t idx = (size_t)b * (DKV * SEQ / 2) + (size_t)d * (SEQ / 2) + s0p + sp;
                outH2[idx] = h; outL2[idx] = l;
            }
        } else {
            uint32_t* oh = (bx == 0) ? outH : outH3;
            uint32_t* ol = (bx == 0) ? outL : outL3;
            #pragma unroll
            for (int i = 0; i < 32; i++) {
                int u = tid + 256 * i;
                int row = u >> 6, np = u & 63;
                float v0 = Cs[row * 132 + 2 * np]     + __ldg(bias + bx * 128 + 2 * np);
                float v1 = Cs[row * 132 + 2 * np + 1] + __ldg(bias + bx * 128 + 2 * np + 1);
                uint32_t h, l;
                split2(v0, v1, h, l);
                size_t idx = ((size_t)by * 128 + row) * 64 + np;
                oh[idx] = h; ol[idx] = l;
            }
        }
    }
}

// ================= HMMA GEMM, BN=256 (2-stage), BK=64, 3-pass bf16 ===========
template<int EMIT, int EPI>
__global__ __launch_bounds__(256, 1)
void hgemm256(const uint32_t* __restrict__ Ah, const uint32_t* __restrict__ Al,
              const uint32_t* __restrict__ Bh, const uint32_t* __restrict__ Bl,
              const float* __restrict__ bias, const float* __restrict__ res,
              float* __restrict__ outF, uint32_t* __restrict__ outH, uint32_t* __restrict__ outL,
              int Ka, int Nb, int nc,
              long long sAu, long long sBu, long long sCf,
              float alpha)
{
    extern __shared__ char smc[];
    const uint32_t sb = smem_u32(smc);
    const int tid = threadIdx.x, wid = tid >> 5, lane = tid & 31;
    const int wm = wid >> 2, wn = wid & 3;            // 2 x 4, warp tile 64x64
    const int bx = blockIdx.x, by = blockIdx.y, bz = blockIdx.z;

    const uint32_t Ka2 = (uint32_t)Ka >> 1, Nb2 = (uint32_t)Nb >> 1;
    const uint32_t* Ahb = Ah + (size_t)bz * sAu;
    const uint32_t* Alb = Al + (size_t)bz * sAu;
    const uint32_t* Bhb = Bh + (size_t)bz * sBu;
    const uint32_t* Blb = Bl + (size_t)bz * sBu;

    // stage: Ahi 0 | Alo 16K | Bhi 32K | Blo 64K   (96KB per stage, 2 stages)
    auto load_stage = [&](int st, int c) {
        const uint32_t stb = sb + st * 98304;
        #pragma unroll
        for (int t = 0; t < 4; t++) {     // A: 1024 16B chunks per buffer
            int id = tid + t * 256;
            int m = id >> 3, ch = id & 7;
            size_t go = (size_t)(by * 128 + m) * Ka2 + (size_t)c * 32 + ch * 4;
            uint32_t sa = stb + m * 128 + ((ch ^ (m & 7)) << 4);
            cpasync16(sa, Ahb + go);
            cpasync16(sa + 16384, Alb + go);
        }
        #pragma unroll
        for (int t = 0; t < 8; t++) {     // B: 2048 16B chunks per buffer
            int id = tid + t * 256;
            int k = id >> 5, ch = id & 31;
            size_t go = (size_t)(c * 64 + k) * Nb2 + (size_t)bx * 128 + ch * 4;
            uint32_t sa = stb + 32768 + k * 512 + ((ch ^ (k & 15)) << 4);
            cpasync16(sa, Bhb + go);
            cpasync16(sa + 32768, Blb + go);
        }
    };

    float acc[4][8][4];
    #pragma unroll
    for (int i = 0; i < 4; i++)
        #pragma unroll
        for (int j = 0; j < 8; j++)
            #pragma unroll
            for (int r = 0; r < 4; r++) acc[i][j][r] = 0.f;

    load_stage(0, 0); CP_COMMIT();
    load_stage(1, 1); CP_COMMIT();

    const int q = lane >> 3, l7 = lane & 7;

    for (int c = 0; c < nc; ++c) {
        CP_WAIT1();
        __syncthreads();

        const uint32_t stb = sb + (c & 1) * 98304;
        #pragma unroll
        for (int ks = 0; ks < 4; ks++) {
            uint32_t aH[4][4], aL[4][4];
            #pragma unroll
            for (int i = 0; i < 4; i++) {
                int m = wm * 64 + i * 16 + ((q & 1) << 3) + l7;
                int ch = 2 * ks + (q >> 1);
                uint32_t ad = stb + m * 128 + ((ch ^ (m & 7)) << 4);
                ldm_x4(aH[i], ad);
                ldm_x4(aL[i], ad + 16384);
            }
            #pragma unroll
            for (int g = 0; g < 4; g++) {     // each g: 2 n8-tiles
                uint32_t bH4[4], bL4[4];
                int k = ks * 16 + ((q & 1) << 3) + l7;
                int ch = wn * 8 + g * 2 + (q >> 1);
                uint32_t bd = stb + 32768 + k * 512 + ((ch ^ (k & 15)) << 4);
                ldm_x4_t(bH4, bd);
                ldm_x4_t(bL4, bd + 32768);
                #pragma unroll
                for (int i = 0; i < 4; i++) {
                    #pragma unroll
                    for (int jj = 0; jj < 2; jj++) {
                        const uint32_t* bh = &bH4[jj * 2];
                        const uint32_t* bl = &bL4[jj * 2];
                        float* a4 = acc[i][g * 2 + jj];
                        mma16816(a4, aH[i], bh);
                        mma16816(a4, aH[i], bl);
                        mma16816(a4, aL[i], bh);
                    }
                }
            }
        }
        __syncthreads();
        if (c + 2 < nc) load_stage(c & 1, c + 2);
        CP_COMMIT();
    }

    // ---- epilogue: stage C tile [128][260] f32 ----
    __syncthreads();
    float* Cs = (float*)smc;
    #pragma unroll
    for (int i = 0; i < 4; i++)
        #pragma unroll
        for (int j = 0; j < 8; j++) {
            int r0 = wm * 64 + i * 16 + (lane >> 2);
            int c0 = wn * 64 + j * 8 + 2 * (lane & 3);
            *(float2*)(Cs + r0 * 260 + c0)       = make_float2(acc[i][j][0], acc[i][j][1]);
            *(float2*)(Cs + (r0 + 8) * 260 + c0) = make_float2(acc[i][j][2], acc[i][j][3]);
        }
    __syncthreads();

    if (EMIT == EM_F32) {
        #pragma unroll
        for (int i = 0; i < 32; i++) {
            int u = tid + 256 * i;
            int row = u >> 6, c4 = (u & 63) * 4;
            float4 v = *(float4*)(Cs + row * 260 + c4);
            v.x *= alpha; v.y *= alpha; v.z *= alpha; v.w *= alpha;
            int gc = bx * 256 + c4;
            size_t gm = (size_t)by * 128 + row;
            if (EPI & 1) {
                float4 bb = *(const float4*)(bias + gc);
                v.x += bb.x; v.y += bb.y; v.z += bb.z; v.w += bb.w;
            }
            if (EPI & 2) { v.x = gelu1(v.x); v.y = gelu1(v.y); v.z = gelu1(v.z); v.w = gelu1(v.w); }
            if (EPI & 4) {
                float4 rr = *(const float4*)(res + gm * Nb + gc);
                v.x += rr.x; v.y += rr.y; v.z += rr.z; v.w += rr.w;
            }
            *(float4*)(outF + (size_t)bz * sCf + gm * Nb + gc) = v;
        }
    } else { // EM_BF
        #pragma unroll
        for (int i = 0; i < 64; i++) {
            int u = tid + 256 * i;
            int row = u >> 7, np = u & 127;
            float v0 = Cs[row * 260 + 2 * np]     * alpha;
            float v1 = Cs[row * 260 + 2 * np + 1] * alpha;
            int gc = bx * 256 + 2 * np;
            if (EPI & 1) { v0 += __ldg(bias + gc); v1 += __ldg(bias + gc + 1); }
            if (EPI & 2) { v0 = gelu1(v0); v1 = gelu1(v1); }
            uint32_t h, l;
            split2(v0, v1, h, l);
            size_t gm = (size_t)by * 128 + row;
            size_t idx = gm * (Nb >> 1) + (size_t)bx * 128 + np;
            outH[idx] = h; outL[idx] = l;
        }
    }
}

// ---------------- launch sequence -------------------------------------------
extern "C" void kernel_launch(void* const* d_in, const int* in_sizes, int n_in,
                              void* d_out, int out_size)
{
    const float* x     = (const float*)d_in[0];
    const float* ln1_g = (const float*)d_in[1];
    const float* ln1_b = (const float*)d_in[2];
    const float* Wq    = (const float*)d_in[3];
    const float* bq    = (const float*)d_in[4];
    const float* Wk    = (const float*)d_in[5];
    const float* bk    = (const float*)d_in[6];
    const float* Wv    = (const float*)d_in[7];
    const float* bv    = (const float*)d_in[8];
    const float* Wo    = (const float*)d_in[9];
    const float* bo    = (const float*)d_in[10];
    const float* ln2_g = (const float*)d_in[11];
    const float* ln2_b = (const float*)d_in[12];
    const float* W1    = (const float*)d_in[13];
    const float* b1    = (const float*)d_in[14];
    const float* W2    = (const float*)d_in[15];
    const float* b2    = (const float*)d_in[16];
    float* out = (float*)d_out;

    float *xnF, *scF, *yF, *bqkv;
    uint32_t *xnH,*xnL,*hH,*hL,*qH,*qL,*ktH,*ktL,*vH,*vL,*pH,*pL,*atH,*atL,*acH,*acL;
    uint32_t *wqkvH,*wqkvL,*woH,*woL,*w1H,*w1L,*w2H,*w2L;
    cudaGetSymbolAddress((void**)&xnF, g_xnF); cudaGetSymbolAddress((void**)&scF, g_scF);
    cudaGetSymbolAddress((void**)&yF,  g_yF);  cudaGetSymbolAddress((void**)&bqkv, g_bqkv);
    cudaGetSymbolAddress((void**)&xnH, g_xnH); cudaGetSymbolAddress((void**)&xnL, g_xnL);
    cudaGetSymbolAddress((void**)&hH,  g_hH);  cudaGetSymbolAddress((void**)&hL,  g_hL);
    cudaGetSymbolAddress((void**)&qH,  g_qH);  cudaGetSymbolAddress((void**)&qL,  g_qL);
    cudaGetSymbolAddress((void**)&ktH, g_ktH); cudaGetSymbolAddress((void**)&ktL, g_ktL);
    cudaGetSymbolAddress((void**)&vH,  g_vH);  cudaGetSymbolAddress((void**)&vL,  g_vL);
    cudaGetSymbolAddress((void**)&pH,  g_pH);  cudaGetSymbolAddress((void**)&pL,  g_pL);
    cudaGetSymbolAddress((void**)&atH, g_atH); cudaGetSymbolAddress((void**)&atL, g_atL);
    cudaGetSymbolAddress((void**)&acH, g_acH); cudaGetSymbolAddress((void**)&acL, g_acL);
    cudaGetSymbolAddress((void**)&wqkvH, g_wqkvH); cudaGetSymbolAddress((void**)&wqkvL, g_wqkvL);
    cudaGetSymbolAddress((void**)&woH, g_woH); cudaGetSymbolAddress((void**)&woL, g_woL);
    cudaGetSymbolAddress((void**)&w1H, g_w1H); cudaGetSymbolAddress((void**)&w1L, g_w1L);
    cudaGetSymbolAddress((void**)&w2H, g_w2H); cudaGetSymbolAddress((void**)&w2L, g_w2L);

    const int SM_128 = 3 * 65536;   // 192 KB
    const int SM_256 = 2 * 98304;   // 192 KB (epilogue 128*260*4 = 133 KB fits)
    cudaFuncSetAttribute(hgemm<EM_QKV,1>,   cudaFuncAttributeMaxDynamicSharedMemorySize, SM_128);
    cudaFuncSetAttribute(hgemm<EM_BF, 0>,   cudaFuncAttributeMaxDynamicSharedMemorySize, SM_128);
    cudaFuncSetAttribute(hgemm256<EM_F32,0>, cudaFuncAttributeMaxDynamicSharedMemorySize, SM_256);
    cudaFuncSetAttribute(hgemm256<EM_F32,5>, cudaFuncAttributeMaxDynamicSharedMemorySize, SM_256);
    cudaFuncSetAttribute(hgemm256<EM_BF, 3>, cudaFuncAttributeMaxDynamicSharedMemorySize, SM_256);

    const float scale = 0.08838834764831845f; // 1/sqrt(128)

    // ---- 1 launch: all weight conversions + qkv bias pack ----
    {
        WJobs jb;
        jb.src[0] = Wq; jb.H[0] = wqkvH; jb.L[0] = wqkvL; jb.np[0] = DMODEL*DKV/2; jb.srcP[0] = 64;  jb.dstP[0] = 192; jb.coff[0] = 0;
        jb.src[1] = Wk; jb.H[1] = wqkvH; jb.L[1] = wqkvL; jb.np[1] = DMODEL*DKV/2; jb.srcP[1] = 64;  jb.dstP[1] = 192; jb.coff[1] = 64;
        jb.src[2] = Wv; jb.H[2] = wqkvH; jb.L[2] = wqkvL; jb.np[2] = DMODEL*DKV/2; jb.srcP[2] = 64;  jb.dstP[2] = 192; jb.coff[2] = 128;
        jb.src[3] = Wo; jb.H[3] = woH;   jb.L[3] = woL;   jb.np[3] = DKV*DMODEL/2; jb.srcP[3] = 512; jb.dstP[3] = 512; jb.coff[3] = 0;
        jb.src[4] = W1; jb.H[4] = w1H;   jb.L[4] = w1L;   jb.np[4] = DMODEL*DFF/2; jb.srcP[4] = 2048;jb.dstP[4] = 2048;jb.coff[4] = 0;
        jb.src[5] = W2; jb.H[5] = w2H;   jb.L[5] = w2L;   jb.np[5] = DFF*DMODEL/2; jb.srcP[5] = 512; jb.dstP[5] = 512; jb.coff[5] = 0;
        int acc_ = 0;
        for (int s = 0; s < 6; s++) { jb.blkStart[s] = acc_; acc_ += (jb.np[s] + 255) / 256; }
        jb.blkStart[6] = acc_;
        jb.bq = bq; jb.bk = bk; jb.bv = bv; jb.bqkv = bqkv;
        wconv_all<<<acc_ + 1, 256>>>(jb);
    }

    // 2) ln1 -> xn (f32 + bf16 pairs)
    ln_frag<true><<<MS, 256>>>(x, ln1_g, ln1_b, xnF, xnH, xnL);

    // 3) fused QKV (16384 x 384 x 1024): bx=0 q, bx=1 kT, bx=2 v
    hgemm<EM_QKV, 1><<<dim3(3,128,1), 256, SM_128>>>(xnH, xnL, wqkvH, wqkvL, bqkv, nullptr,
        nullptr, qH, qL, ktH, ktL, vH, vL, DMODEL, 384, 16, 0, 0, 0, 0, 1.f);

    // 4) scores = q @ kT * scale (per batch 2048 x 2048 x 128)
    hgemm256<EM_F32, 0><<<dim3(8,16,8), 256, SM_256>>>(qH, qL, ktH, ktL, nullptr, nullptr,
        scF, nullptr, nullptr, DKV, SEQ, 2,
        (long long)SEQ*DKV/2, (long long)DKV*SEQ/2, (long long)SEQ*SEQ, scale);

    // 5) softmax -> probs bf16 pairs
    softmax_frag<<<BATCH*SEQ, 256>>>(scF, pH, pL);

    // 6) att = probs @ v (per batch 2048 x 128 x 2048)   [ncu -s 5 lands here]
    hgemm<EM_BF, 0><<<dim3(1,16,8), 256, SM_128>>>(pH, pL, vH, vL, nullptr, nullptr,
        nullptr, atH, atL, nullptr, nullptr, nullptr, nullptr, SEQ, DKV, 32,
        (long long)SEQ*SEQ/2, (long long)SEQ*DKV/2, 0, (long long)SEQ*DKV/2, 1.f);

    // 7) y = xn + att@Wo + bo (16384 x 1024 x 128)
    hgemm256<EM_F32, 5><<<dim3(4,128,1), 256, SM_256>>>(atH, atL, woH, woL, bo, xnF,
        yF, nullptr, nullptr, DKV, DMODEL, 2, 0, 0, 0, 1.f);

    // 8) ln2 -> h bf16 pairs
    ln_frag<false><<<MS, 256>>>(yF, ln2_g, ln2_b, nullptr, hH, hL);

    // 9) act = gelu(h@W1 + b1) (16384 x 4096 x 1024)
    hgemm256<EM_BF, 3><<<dim3(16,128,1), 256, SM_256>>>(hH, hL, w1H, w1L, b1, nullptr,
        nullptr, acH, acL, DMODEL, DFF, 16, 0, 0, 0, 1.f);

    // 10) out = y + act@W2 + b2 (16384 x 1024 x 4096)
    hgemm256<EM_F32, 5><<<dim3(4,128,1), 256, SM_256>>>(acH, acL, w2H, w2L, b2, yF,
        out, nullptr, nullptr, DFF, DMODEL, 64, 0, 0, 0, 1.f);
}

// round 6
// speedup vs baseline: 3.7098x; 1.3399x over previous
#include <cuda_runtime.h>
#include <cuda_fp16.h>
#include <math.h>
#include <stdint.h>

#define BATCH 8
#define SEQ   2048
#define DMODEL 1024
#define DKV   128
#define DFF   4096
#define MS    (BATCH*SEQ)

// ---------------- scratch (static device globals) ----------------------------
__device__ float    g_xnF[(size_t)MS*DMODEL];
__device__ float    g_scF[(size_t)BATCH*SEQ*SEQ];
__device__ float    g_yF [(size_t)MS*DMODEL];

__device__ uint32_t g_xnH[(size_t)MS*DMODEL/2],  g_xnL[(size_t)MS*DMODEL/2];
__device__ uint32_t g_hH [(size_t)MS*DMODEL/2],  g_hL [(size_t)MS*DMODEL/2];
__device__ uint32_t g_qH [(size_t)MS*DKV/2],     g_qL [(size_t)MS*DKV/2];
__device__ uint32_t g_ktH[(size_t)BATCH*DKV*SEQ/2], g_ktL[(size_t)BATCH*DKV*SEQ/2];
__device__ uint32_t g_vH [(size_t)MS*DKV/2],     g_vL [(size_t)MS*DKV/2];
__device__ uint32_t g_pH [(size_t)BATCH*SEQ*SEQ/2], g_pL[(size_t)BATCH*SEQ*SEQ/2];
__device__ uint32_t g_atH[(size_t)MS*DKV/2],     g_atL[(size_t)MS*DKV/2];
__device__ uint32_t g_acH[(size_t)MS*DFF/2],     g_acL[(size_t)MS*DFF/2];

__device__ uint32_t g_wqkvH[(size_t)DMODEL*384/2], g_wqkvL[(size_t)DMODEL*384/2];
__device__ float    g_bqkv[384];
__device__ uint32_t g_woH[(size_t)DKV*DMODEL/2], g_woL[(size_t)DKV*DMODEL/2];
__device__ uint32_t g_w1H[(size_t)DMODEL*DFF/2];   // single fp16 (2-pass)
__device__ uint32_t g_w2H[(size_t)DFF*DMODEL/2];   // single fp16 (2-pass)

// ---------------- helpers ----------------------------------------------------
__device__ __forceinline__ uint32_t smem_u32(const void* p) {
    uint32_t a;
    asm("{ .reg .u64 t; cvta.to.shared.u64 t, %1; cvt.u32.u64 %0, t; }" : "=r"(a) : "l"(p));
    return a;
}
__device__ __forceinline__ void cpasync16(uint32_t dst, const void* src) {
    asm volatile("cp.async.cg.shared.global [%0], [%1], 16;" :: "r"(dst), "l"(src));
}
#define CP_COMMIT() asm volatile("cp.async.commit_group;" ::: "memory")
#define CP_WAIT1()  asm volatile("cp.async.wait_group 1;" ::: "memory")

__device__ __forceinline__ void ldm_x4(uint32_t r[4], uint32_t addr) {
    asm volatile("ldmatrix.sync.aligned.m8n8.x4.shared.b16 {%0,%1,%2,%3}, [%4];"
                 : "=r"(r[0]), "=r"(r[1]), "=r"(r[2]), "=r"(r[3]) : "r"(addr));
}
__device__ __forceinline__ void ldm_x4_t(uint32_t r[4], uint32_t addr) {
    asm volatile("ldmatrix.sync.aligned.m8n8.x4.trans.shared.b16 {%0,%1,%2,%3}, [%4];"
                 : "=r"(r[0]), "=r"(r[1]), "=r"(r[2]), "=r"(r[3]) : "r"(addr));
}
__device__ __forceinline__ void mma16816(float c[4], const uint32_t a[4], const uint32_t b[2]) {
    asm volatile("mma.sync.aligned.m16n8k16.row.col.f32.f16.f16.f32 "
                 "{%0,%1,%2,%3},{%4,%5,%6,%7},{%8,%9},{%0,%1,%2,%3};"
                 : "+f"(c[0]), "+f"(c[1]), "+f"(c[2]), "+f"(c[3])
                 : "r"(a[0]), "r"(a[1]), "r"(a[2]), "r"(a[3]), "r"(b[0]), "r"(b[1]));
}
__device__ __forceinline__ uint32_t packh(__half a, __half b) {
    return (uint32_t)__half_as_ushort(a) | ((uint32_t)__half_as_ushort(b) << 16);
}
__device__ __forceinline__ void split2(float a, float b, uint32_t& hi, uint32_t& lo) {
    __half ha = __float2half_rn(a);
    __half hb = __float2half_rn(b);
    __half la = __float2half_rn(a - __half2float(ha));
    __half lb = __float2half_rn(b - __half2float(hb));
    hi = packh(ha, hb);
    lo = packh(la, lb);
}
__device__ __forceinline__ uint32_t pack2(float a, float b) {
    return packh(__float2half_rn(a), __float2half_rn(b));
}
__device__ __forceinline__ float gelu1(float v) {
    return 0.5f * v * (1.0f + erff(v * 0.70710678118654752f));
}

// ---------------- one-shot weight conversion (all weights, one launch) -------
struct WJobs {
    const float* src[6];
    uint32_t* H[6];
    uint32_t* L[6];      // null -> single fp16 (2-pass weight)
    int np[6];
    int srcP[6];
    int dstP[6];
    int coff[6];
    int blkStart[7];
    const float* bq; const float* bk; const float* bv;
    float* bqkv;
};

__global__ __launch_bounds__(256) void wconv_all(WJobs jb)
{
    const int blk = blockIdx.x, tid = threadIdx.x;
    if (blk >= jb.blkStart[6]) {
        if (tid < 128) {
            jb.bqkv[tid]       = jb.bq[tid];
            jb.bqkv[128 + tid] = jb.bk[tid];
            jb.bqkv[256 + tid] = jb.bv[tid];
        }
        return;
    }
    int seg = 0;
    #pragma unroll
    for (int s = 1; s < 6; s++) if (blk >= jb.blkStart[s]) seg = s;
    int u = (blk - jb.blkStart[seg]) * 256 + tid;
    if (u >= jb.np[seg]) return;
    int k = u / jb.srcP[seg], p = u - k * jb.srcP[seg];
    float2 v = *(const float2*)(jb.src[seg] + ((size_t)u) * 2);
    size_t di = (size_t)k * jb.dstP[seg] + jb.coff[seg] + p;
    if (jb.L[seg]) {
        uint32_t h, l;
        split2(v.x, v.y, h, l);
        jb.H[seg][di] = h; jb.L[seg][di] = l;
    } else {
        jb.H[seg][di] = pack2(v.x, v.y);
    }
}

// ---------------- LayerNorm: one row/block, f32(optional) + fp16 pair emit ----
template<bool WF32>
__global__ __launch_bounds__(256) void ln_frag(const float* __restrict__ x,
                                               const float* __restrict__ g,
                                               const float* __restrict__ b,
                                               float* __restrict__ oF,
                                               uint32_t* __restrict__ H,
                                               uint32_t* __restrict__ L)
{
    const int row = blockIdx.x;
    const int tid = threadIdx.x;
    const float* xr = x + (size_t)row * DMODEL;
    float4 v = *(const float4*)(xr + tid * 4);

    float s  = v.x + v.y + v.z + v.w;
    float s2 = v.x*v.x + v.y*v.y + v.z*v.z + v.w*v.w;
    #pragma unroll
    for (int off = 16; off; off >>= 1) {
        s  += __shfl_xor_sync(0xffffffffu, s,  off);
        s2 += __shfl_xor_sync(0xffffffffu, s2, off);
    }
    __shared__ float ss[8], ss2[8], stats[2];
    const int wid = tid >> 5, lane = tid & 31;
    if (lane == 0) { ss[wid] = s; ss2[wid] = s2; }
    __syncthreads();
    if (wid == 0) {
        s  = (lane < 8) ? ss[lane]  : 0.f;
        s2 = (lane < 8) ? ss2[lane] : 0.f;
        #pragma unroll
        for (int off = 4; off; off >>= 1) {
            s  += __shfl_xor_sync(0xffffffffu, s,  off);
            s2 += __shfl_xor_sync(0xffffffffu, s2, off);
        }
        if (lane == 0) {
            float mean = s * (1.0f / DMODEL);
            float var  = s2 * (1.0f / DMODEL) - mean * mean;
            stats[0] = mean;
            stats[1] = rsqrtf(var + 1e-5f);
        }
    }
    __syncthreads();
    const float mean = stats[0], rstd = stats[1];
    float4 gg = *(const float4*)(g + tid * 4);
    float4 bb = *(const float4*)(b + tid * 4);
    float4 o;
    o.x = (v.x - mean) * rstd * gg.x + bb.x;
    o.y = (v.y - mean) * rstd * gg.y + bb.y;
    o.z = (v.z - mean) * rstd * gg.z + bb.z;
    o.w = (v.w - mean) * rstd * gg.w + bb.w;
    if (WF32) *(float4*)(oF + (size_t)row * DMODEL + tid * 4) = o;
    uint32_t h0, l0, h1, l1;
    split2(o.x, o.y, h0, l0);
    split2(o.z, o.w, h1, l1);
    size_t base = (size_t)row * (DMODEL / 2) + tid * 2;
    H[base] = h0; H[base + 1] = h1;
    L[base] = l0; L[base + 1] = l1;
}

// ---------------- softmax: one row/block, emits probs fp16 pairs --------------
__global__ __launch_bounds__(256) void softmax_frag(const float* __restrict__ S,
                                                    uint32_t* __restrict__ H,
                                                    uint32_t* __restrict__ L)
{
    const size_t row = blockIdx.x;
    const float* p = S + row * (size_t)SEQ;
    const int tid = threadIdx.x;
    float4 a = *(const float4*)(p + tid * 4);
    float4 c = *(const float4*)(p + 1024 + tid * 4);

    float m = fmaxf(fmaxf(fmaxf(a.x, a.y), fmaxf(a.z, a.w)),
                    fmaxf(fmaxf(c.x, c.y), fmaxf(c.z, c.w)));
    #pragma unroll
    for (int off = 16; off; off >>= 1)
        m = fmaxf(m, __shfl_xor_sync(0xffffffffu, m, off));
    __shared__ float sm[8], sred[2];
    const int wid = tid >> 5, lane = tid & 31;
    if (lane == 0) sm[wid] = m;
    __syncthreads();
    if (wid == 0) {
        m = (lane < 8) ? sm[lane] : -1e30f;
        #pragma unroll
        for (int off = 4; off; off >>= 1)
            m = fmaxf(m, __shfl_xor_sync(0xffffffffu, m, off));
        if (lane == 0) sred[0] = m;
    }
    __syncthreads();
    m = sred[0];

    a.x = expf(a.x - m); a.y = expf(a.y - m); a.z = expf(a.z - m); a.w = expf(a.w - m);
    c.x = expf(c.x - m); c.y = expf(c.y - m); c.z = expf(c.z - m); c.w = expf(c.w - m);
    float s = a.x + a.y + a.z + a.w + c.x + c.y + c.z + c.w;
    #pragma unroll
    for (int off = 16; off; off >>= 1)
        s += __shfl_xor_sync(0xffffffffu, s, off);
    if (lane == 0) sm[wid] = s;
    __syncthreads();
    if (wid == 0) {
        s = (lane < 8) ? sm[lane] : 0.f;
        #pragma unroll
        for (int off = 4; off; off >>= 1)
            s += __shfl_xor_sync(0xffffffffu, s, off);
        if (lane == 0) sred[1] = 1.0f / s;
    }
    __syncthreads();
    const float r = sred[1];
    a.x *= r; a.y *= r; a.z *= r; a.w *= r;
    c.x *= r; c.y *= r; c.z *= r; c.w *= r;

    uint32_t h, l;
    size_t base = row * (SEQ / 2) + tid * 2;
    split2(a.x, a.y, h, l); H[base] = h;       L[base] = l;
    split2(a.z, a.w, h, l); H[base + 1] = h;   L[base + 1] = l;
    base += 512;
    split2(c.x, c.y, h, l); H[base] = h;       L[base] = l;
    split2(c.z, c.w, h, l); H[base + 1] = h;   L[base + 1] = l;
}

// ================= HMMA GEMM, BN=128 (3-stage), BK=64, 3-pass fp16 ===========
#define EM_F32 0
#define EM_BF  1
#define EM_QKV 3

template<int EMIT, int EPI>
__global__ __launch_bounds__(256, 1)
void hgemm(const uint32_t* __restrict__ Ah, const uint32_t* __restrict__ Al,
           const uint32_t* __restrict__ Bh, const uint32_t* __restrict__ Bl,
           const float* __restrict__ bias, const float* __restrict__ res,
           float* __restrict__ outF, uint32_t* __restrict__ outH, uint32_t* __restrict__ outL,
           uint32_t* __restrict__ outH2, uint32_t* __restrict__ outL2,
           uint32_t* __restrict__ outH3, uint32_t* __restrict__ outL3,
           int Ka, int Nb, int nc,
           long long sAu, long long sBu, long long sCf, long long sOu,
           float alpha)
{
    extern __shared__ char smc[];
    const uint32_t sb = smem_u32(smc);
    const int tid = threadIdx.x, wid = tid >> 5, lane = tid & 31;
    const int wm = wid >> 2, wn = wid & 3;
    const int bx = blockIdx.x, by = blockIdx.y, bz = blockIdx.z;

    const uint32_t Ka2 = (uint32_t)Ka >> 1, Nb2 = (uint32_t)Nb >> 1;
    const uint32_t* Ahb = Ah + (size_t)bz * sAu;
    const uint32_t* Alb = Al + (size_t)bz * sAu;
    const uint32_t* Bhb = Bh + (size_t)bz * sBu;
    const uint32_t* Blb = Bl + (size_t)bz * sBu;

    auto load_stage = [&](int st, int c) {
        const uint32_t stb = sb + st * 65536;
        #pragma unroll
        for (int t = 0; t < 4; t++) {
            int id = tid + t * 256;
            int m = id >> 3, ch = id & 7;
            size_t go = (size_t)(by * 128 + m) * Ka2 + (size_t)c * 32 + ch * 4;
            uint32_t sa = stb + m * 128 + ((ch ^ (m & 7)) << 4);
            cpasync16(sa, Ahb + go);
            cpasync16(sa + 16384, Alb + go);
        }
        #pragma unroll
        for (int t = 0; t < 4; t++) {
            int id = tid + t * 256;
            int k = id >> 4, ch = id & 15;
            size_t go = (size_t)(c * 64 + k) * Nb2 + (size_t)bx * 64 + ch * 4;
            uint32_t sa = stb + 32768 + k * 256 + ((ch ^ (k & 15)) << 4);
            cpasync16(sa, Bhb + go);
            cpasync16(sa + 16384, Blb + go);
        }
    };

    float acc[4][4][4];
    #pragma unroll
    for (int i = 0; i < 4; i++)
        #pragma unroll
        for (int j = 0; j < 4; j++)
            #pragma unroll
            for (int r = 0; r < 4; r++) acc[i][j][r] = 0.f;

    load_stage(0, 0); CP_COMMIT();
    load_stage(1, 1); CP_COMMIT();

    const int q = lane >> 3, l7 = lane & 7;

    for (int c = 0; c < nc; ++c) {
        CP_WAIT1();
        __syncthreads();
        if (c + 2 < nc) load_stage((c + 2) % 3, c + 2);
        CP_COMMIT();

        const uint32_t stb = sb + (c % 3) * 65536;
        #pragma unroll
        for (int ks = 0; ks < 4; ks++) {
            uint32_t aH[4][4], aL[4][4], bH4[2][4], bL4[2][4];
            #pragma unroll
            for (int i = 0; i < 4; i++) {
                int m = wm * 64 + i * 16 + ((q & 1) << 3) + l7;
                int ch = 2 * ks + (q >> 1);
                uint32_t ad = stb + m * 128 + ((ch ^ (m & 7)) << 4);
                ldm_x4(aH[i], ad);
                ldm_x4(aL[i], ad + 16384);
            }
            #pragma unroll
            for (int g = 0; g < 2; g++) {
                int k = ks * 16 + ((q & 1) << 3) + l7;
                int ch = wn * 4 + g * 2 + (q >> 1);
                uint32_t bd = stb + 32768 + k * 256 + ((ch ^ (k & 15)) << 4);
                ldm_x4_t(bH4[g], bd);
                ldm_x4_t(bL4[g], bd + 16384);
            }
            #pragma unroll
            for (int i = 0; i < 4; i++)
                #pragma unroll
                for (int j = 0; j < 4; j++) {
                    const uint32_t* bh = &bH4[j >> 1][(j & 1) * 2];
                    const uint32_t* bl = &bL4[j >> 1][(j & 1) * 2];
                    mma16816(acc[i][j], aH[i], bh);
                    mma16816(acc[i][j], aH[i], bl);
                    mma16816(acc[i][j], aL[i], bh);
                }
        }
    }

    __syncthreads();
    float* Cs = (float*)smc;
    #pragma unroll
    for (int i = 0; i < 4; i++)
        #pragma unroll
        for (int j = 0; j < 4; j++) {
            int r0 = wm * 64 + i * 16 + (lane >> 2);
            int c0 = wn * 32 + j * 8 + 2 * (lane & 3);
            *(float2*)(Cs + r0 * 132 + c0)       = make_float2(acc[i][j][0], acc[i][j][1]);
            *(float2*)(Cs + (r0 + 8) * 132 + c0) = make_float2(acc[i][j][2], acc[i][j][3]);
        }
    __syncthreads();

    if (EMIT == EM_F32) {
        #pragma unroll
        for (int i = 0; i < 16; i++) {
            int u = tid + 256 * i;
            int row = u >> 5, c4 = (u & 31) * 4;
            float4 v = *(float4*)(Cs + row * 132 + c4);
            v.x *= alpha; v.y *= alpha; v.z *= alpha; v.w *= alpha;
            int gc = bx * 128 + c4;
            size_t gm = (size_t)by * 128 + row;
            if (EPI & 1) {
                float4 bb = *(const float4*)(bias + gc);
                v.x += bb.x; v.y += bb.y; v.z += bb.z; v.w += bb.w;
            }
            if (EPI & 2) { v.x = gelu1(v.x); v.y = gelu1(v.y); v.z = gelu1(v.z); v.w = gelu1(v.w); }
            if (EPI & 4) {
                float4 rr = *(const float4*)(res + gm * Nb + gc);
                v.x += rr.x; v.y += rr.y; v.z += rr.z; v.w += rr.w;
            }
            *(float4*)(outF + (size_t)bz * sCf + gm * Nb + gc) = v;
        }
    } else if (EMIT == EM_BF) {
        #pragma unroll
        for (int i = 0; i < 32; i++) {
            int u = tid + 256 * i;
            int row = u >> 6, np = u & 63;
            float v0 = Cs[row * 132 + 2 * np]     * alpha;
            float v1 = Cs[row * 132 + 2 * np + 1] * alpha;
            int gc = bx * 128 + 2 * np;
            if (EPI & 1) { v0 += __ldg(bias + gc); v1 += __ldg(bias + gc + 1); }
            if (EPI & 2) { v0 = gelu1(v0); v1 = gelu1(v1); }
            uint32_t h, l;
            split2(v0, v1, h, l);
            size_t gm = (size_t)by * 128 + row;
            size_t idx = (size_t)bz * sOu + gm * (Nb >> 1) + (size_t)bx * 64 + np;
            outH[idx] = h; outL[idx] = l;
        }
    } else { // EM_QKV
        if (bx == 1) {
            const int b = by >> 4;
            const int s0p = (by & 15) * 64;
            #pragma unroll
            for (int i = 0; i < 32; i++) {
                int u = tid + 256 * i;
                int d = u >> 6, sp = u & 63;
                float bb = __ldg(bias + 128 + d);
                float v0 = Cs[(2 * sp) * 132 + d]     + bb;
                float v1 = Cs[(2 * sp + 1) * 132 + d] + bb;
                uint32_t h, l;
                split2(v0, v1, h, l);
                size_t idx = (size_t)b * (DKV * SEQ / 2) + (size_t)d * (SEQ / 2) + s0p + sp;
                outH2[idx] = h; outL2[idx] = l;
            }
        } else {
            uint32_t* oh = (bx == 0) ? outH : outH3;
            uint32_t* ol = (bx == 0) ? outL : outL3;
            #pragma unroll
            for (int i = 0; i < 32; i++) {
                int u = tid + 256 * i;
                int row = u >> 6, np = u & 63;
                float v0 = Cs[row * 132 + 2 * np]     + __ldg(bias + bx * 128 + 2 * np);
                float v1 = Cs[row * 132 + 2 * np + 1] + __ldg(bias + bx * 128 + 2 * np + 1);
                uint32_t h, l;
                split2(v0, v1, h, l);
                size_t idx = ((size_t)by * 128 + row) * 64 + np;
                oh[idx] = h; ol[idx] = l;
            }
        }
    }
}

// ================= HMMA GEMM, BN=256, BK=64 =================================
// B2=false: 3-pass (B hi/lo), 2-stage (96KB/stage).
// B2=true : 2-pass (B single fp16), 3-stage (64KB/stage).
template<int EMIT, int EPI, bool B2>
__global__ __launch_bounds__(256, 1)
void hgemm256(const uint32_t* __restrict__ Ah, const uint32_t* __restrict__ Al,
              const uint32_t* __restrict__ Bh, const uint32_t* __restrict__ Bl,
              const float* __restrict__ bias, const float* __restrict__ res,
              float* __restrict__ outF, uint32_t* __restrict__ outH, uint32_t* __restrict__ outL,
              int Ka, int Nb, int nc,
              long long sAu, long long sBu, long long sCf,
              float alpha)
{
    extern __shared__ char smc[];
    const uint32_t sb = smem_u32(smc);
    const int tid = threadIdx.x, wid = tid >> 5, lane = tid & 31;
    const int wm = wid >> 2, wn = wid & 3;
    const int bx = blockIdx.x, by = blockIdx.y, bz = blockIdx.z;

    constexpr uint32_t STG = B2 ? 65536 : 98304;

    const uint32_t Ka2 = (uint32_t)Ka >> 1, Nb2 = (uint32_t)Nb >> 1;
    const uint32_t* Ahb = Ah + (size_t)bz * sAu;
    const uint32_t* Alb = Al + (size_t)bz * sAu;
    const uint32_t* Bhb = Bh + (size_t)bz * sBu;
    const uint32_t* Blb = B2 ? nullptr : (Bl + (size_t)bz * sBu);

    auto load_stage = [&](int st, int c) {
        const uint32_t stb = sb + st * STG;
        #pragma unroll
        for (int t = 0; t < 4; t++) {
            int id = tid + t * 256;
            int m = id >> 3, ch = id & 7;
            size_t go = (size_t)(by * 128 + m) * Ka2 + (size_t)c * 32 + ch * 4;
            uint32_t sa = stb + m * 128 + ((ch ^ (m & 7)) << 4);
            cpasync16(sa, Ahb + go);
            cpasync16(sa + 16384, Alb + go);
        }
        #pragma unroll
        for (int t = 0; t < 8; t++) {
            int id = tid + t * 256;
            int k = id >> 5, ch = id & 31;
            size_t go = (size_t)(c * 64 + k) * Nb2 + (size_t)bx * 128 + ch * 4;
            uint32_t sa = stb + 32768 + k * 512 + ((ch ^ (k & 15)) << 4);
            cpasync16(sa, Bhb + go);
            if (!B2) cpasync16(sa + 32768, Blb + go);
        }
    };

    float acc[4][8][4];
    #pragma unroll
    for (int i = 0; i < 4; i++)
        #pragma unroll
        for (int j = 0; j < 8; j++)
            #pragma unroll
            for (int r = 0; r < 4; r++) acc[i][j][r] = 0.f;

    load_stage(0, 0); CP_COMMIT();
    load_stage(1, 1); CP_COMMIT();

    const int q = lane >> 3, l7 = lane & 7;

    for (int c = 0; c < nc; ++c) {
        CP_WAIT1();
        __syncthreads();
        if (B2) {                       // 3-stage: prefetch before compute
            if (c + 2 < nc) load_stage((c + 2) % 3, c + 2);
            CP_COMMIT();
        }

        const uint32_t stb = sb + (B2 ? (c % 3) : (c & 1)) * STG;
        #pragma unroll
        for (int ks = 0; ks < 4; ks++) {
            uint32_t aH[4][4], aL[4][4];
            #pragma unroll
            for (int i = 0; i < 4; i++) {
                int m = wm * 64 + i * 16 + ((q & 1) << 3) + l7;
                int ch = 2 * ks + (q >> 1);
                uint32_t ad = stb + m * 128 + ((ch ^ (m & 7)) << 4);
                ldm_x4(aH[i], ad);
                ldm_x4(aL[i], ad + 16384);
            }
            #pragma unroll
            for (int g = 0; g < 4; g++) {
                uint32_t bH4[4], bL4[4];
                int k = ks * 16 + ((q & 1) << 3) + l7;
                int ch = wn * 8 + g * 2 + (q >> 1);
                uint32_t bd = stb + 32768 + k * 512 + ((ch ^ (k & 15)) << 4);
                ldm_x4_t(bH4, bd);
                if (!B2) ldm_x4_t(bL4, bd + 32768);
                #pragma unroll
                for (int i = 0; i < 4; i++) {
                    #pragma unroll
                    for (int jj = 0; jj < 2; jj++) {
                        const uint32_t* bh = &bH4[jj * 2];
                        float* a4 = acc[i][g * 2 + jj];
                        mma16816(a4, aH[i], bh);
                        mma16816(a4, aL[i], bh);
                        if (!B2) mma16816(a4, aH[i], &bL4[jj * 2]);
                    }
                }
            }
        }
        if (!B2) {                      // 2-stage: load after compute
            __syncthreads();
            if (c + 2 < nc) load_stage(c & 1, c + 2);
            CP_COMMIT();
        }
    }

    __syncthreads();
    float* Cs = (float*)smc;
    #pragma unroll
    for (int i = 0; i < 4; i++)
        #pragma unroll
        for (int j = 0; j < 8; j++) {
            int r0 = wm * 64 + i * 16 + (lane >> 2);
            int c0 = wn * 64 + j * 8 + 2 * (lane & 3);
            *(float2*)(Cs + r0 * 260 + c0)       = make_float2(acc[i][j][0], acc[i][j][1]);
            *(float2*)(Cs + (r0 + 8) * 260 + c0) = make_float2(acc[i][j][2], acc[i][j][3]);
        }
    __syncthreads();

    if (EMIT == EM_F32) {
        #pragma unroll
        for (int i = 0; i < 32; i++) {
            int u = tid + 256 * i;
            int row = u >> 6, c4 = (u & 63) * 4;
            float4 v = *(float4*)(Cs + row * 260 + c4);
            v.x *= alpha; v.y *= alpha; v.z *= alpha; v.w *= alpha;
            int gc = bx * 256 + c4;
            size_t gm = (size_t)by * 128 + row;
            if (EPI & 1) {
                float4 bb = *(const float4*)(bias + gc);
                v.x += bb.x; v.y += bb.y; v.z += bb.z; v.w += bb.w;
            }
            if (EPI & 2) { v.x = gelu1(v.x); v.y = gelu1(v.y); v.z = gelu1(v.z); v.w = gelu1(v.w); }
            if (EPI & 4) {
                float4 rr = *(const float4*)(res + gm * Nb + gc);
                v.x += rr.x; v.y += rr.y; v.z += rr.z; v.w += rr.w;
            }
            *(float4*)(outF + (size_t)bz * sCf + gm * Nb + gc) = v;
        }
    } else { // EM_BF
        #pragma unroll
        for (int i = 0; i < 64; i++) {
            int u = tid + 256 * i;
            int row = u >> 7, np = u & 127;
            float v0 = Cs[row * 260 + 2 * np]     * alpha;
            float v1 = Cs[row * 260 + 2 * np + 1] * alpha;
            int gc = bx * 256 + 2 * np;
            if (EPI & 1) { v0 += __ldg(bias + gc); v1 += __ldg(bias + gc + 1); }
            if (EPI & 2) { v0 = gelu1(v0); v1 = gelu1(v1); }
            uint32_t h, l;
            split2(v0, v1, h, l);
            size_t gm = (size_t)by * 128 + row;
            size_t idx = gm * (Nb >> 1) + (size_t)bx * 128 + np;
            outH[idx] = h; outL[idx] = l;
        }
    }
}

// ---------------- launch sequence -------------------------------------------
extern "C" void kernel_launch(void* const* d_in, const int* in_sizes, int n_in,
                              void* d_out, int out_size)
{
    const float* x     = (const float*)d_in[0];
    const float* ln1_g = (const float*)d_in[1];
    const float* ln1_b = (const float*)d_in[2];
    const float* Wq    = (const float*)d_in[3];
    const float* bq    = (const float*)d_in[4];
    const float* Wk    = (const float*)d_in[5];
    const float* bk    = (const float*)d_in[6];
    const float* Wv    = (const float*)d_in[7];
    const float* bv    = (const float*)d_in[8];
    const float* Wo    = (const float*)d_in[9];
    const float* bo    = (const float*)d_in[10];
    const float* ln2_g = (const float*)d_in[11];
    const float* ln2_b = (const float*)d_in[12];
    const float* W1    = (const float*)d_in[13];
    const float* b1    = (const float*)d_in[14];
    const float* W2    = (const float*)d_in[15];
    const float* b2    = (const float*)d_in[16];
    float* out = (float*)d_out;

    float *xnF, *scF, *yF, *bqkv;
    uint32_t *xnH,*xnL,*hH,*hL,*qH,*qL,*ktH,*ktL,*vH,*vL,*pH,*pL,*atH,*atL,*acH,*acL;
    uint32_t *wqkvH,*wqkvL,*woH,*woL,*w1H,*w2H;
    cudaGetSymbolAddress((void**)&xnF, g_xnF); cudaGetSymbolAddress((void**)&scF, g_scF);
    cudaGetSymbolAddress((void**)&yF,  g_yF);  cudaGetSymbolAddress((void**)&bqkv, g_bqkv);
    cudaGetSymbolAddress((void**)&xnH, g_xnH); cudaGetSymbolAddress((void**)&xnL, g_xnL);
    cudaGetSymbolAddress((void**)&hH,  g_hH);  cudaGetSymbolAddress((void**)&hL,  g_hL);
    cudaGetSymbolAddress((void**)&qH,  g_qH);  cudaGetSymbolAddress((void**)&qL,  g_qL);
    cudaGetSymbolAddress((void**)&ktH, g_ktH); cudaGetSymbolAddress((void**)&ktL, g_ktL);
    cudaGetSymbolAddress((void**)&vH,  g_vH);  cudaGetSymbolAddress((void**)&vL,  g_vL);
    cudaGetSymbolAddress((void**)&pH,  g_pH);  cudaGetSymbolAddress((void**)&pL,  g_pL);
    cudaGetSymbolAddress((void**)&atH, g_atH); cudaGetSymbolAddress((void**)&atL, g_atL);
    cudaGetSymbolAddress((void**)&acH, g_acH); cudaGetSymbolAddress((void**)&acL, g_acL);
    cudaGetSymbolAddress((void**)&wqkvH, g_wqkvH); cudaGetSymbolAddress((void**)&wqkvL, g_wqkvL);
    cudaGetSymbolAddress((void**)&woH, g_woH); cudaGetSymbolAddress((void**)&woL, g_woL);
    cudaGetSymbolAddress((void**)&w1H, g_w1H);
    cudaGetSymbolAddress((void**)&w2H, g_w2H);

    const int SM_128 = 3 * 65536;   // 192 KB
    const int SM_3P  = 2 * 98304;   // 192 KB
    const int SM_2P  = 3 * 65536;   // 192 KB
    cudaFuncSetAttribute(hgemm<EM_QKV,1>,          cudaFuncAttributeMaxDynamicSharedMemorySize, SM_128);
    cudaFuncSetAttribute(hgemm<EM_BF, 0>,          cudaFuncAttributeMaxDynamicSharedMemorySize, SM_128);
    cudaFuncSetAttribute(hgemm256<EM_F32,0,false>, cudaFuncAttributeMaxDynamicSharedMemorySize, SM_3P);
    cudaFuncSetAttribute(hgemm256<EM_F32,5,false>, cudaFuncAttributeMaxDynamicSharedMemorySize, SM_3P);
    cudaFuncSetAttribute(hgemm256<EM_BF, 3,true>,  cudaFuncAttributeMaxDynamicSharedMemorySize, SM_2P);
    cudaFuncSetAttribute(hgemm256<EM_F32,5,true>,  cudaFuncAttributeMaxDynamicSharedMemorySize, SM_2P);

    const float scale = 0.08838834764831845f; // 1/sqrt(128)

    // ---- 1 launch: all weight conversions + qkv bias pack ----
    {
        WJobs jb;
        jb.src[0] = Wq; jb.H[0] = wqkvH; jb.L[0] = wqkvL; jb.np[0] = DMODEL*DKV/2; jb.srcP[0] = 64;  jb.dstP[0] = 192; jb.coff[0] = 0;
        jb.src[1] = Wk; jb.H[1] = wqkvH; jb.L[1] = wqkvL; jb.np[1] = DMODEL*DKV/2; jb.srcP[1] = 64;  jb.dstP[1] = 192; jb.coff[1] = 64;
        jb.src[2] = Wv; jb.H[2] = wqkvH; jb.L[2] = wqkvL; jb.np[2] = DMODEL*DKV/2; jb.srcP[2] = 64;  jb.dstP[2] = 192; jb.coff[2] = 128;
        jb.src[3] = Wo; jb.H[3] = woH;   jb.L[3] = woL;   jb.np[3] = DKV*DMODEL/2; jb.srcP[3] = 512; jb.dstP[3] = 512; jb.coff[3] = 0;
        jb.src[4] = W1; jb.H[4] = w1H;   jb.L[4] = nullptr; jb.np[4] = DMODEL*DFF/2; jb.srcP[4] = 2048; jb.dstP[4] = 2048; jb.coff[4] = 0;
        jb.src[5] = W2; jb.H[5] = w2H;   jb.L[5] = nullptr; jb.np[5] = DFF*DMODEL/2; jb.srcP[5] = 512;  jb.dstP[5] = 512;  jb.coff[5] = 0;
        int acc_ = 0;
        for (int s = 0; s < 6; s++) { jb.blkStart[s] = acc_; acc_ += (jb.np[s] + 255) / 256; }
        jb.blkStart[6] = acc_;
        jb.bq = bq; jb.bk = bk; jb.bv = bv; jb.bqkv = bqkv;
        wconv_all<<<acc_ + 1, 256>>>(jb);
    }

    // 2) ln1 -> xn (f32 + fp16 pairs)
    ln_frag<true><<<MS, 256>>>(x, ln1_g, ln1_b, xnF, xnH, xnL);

    // 3) fused QKV (16384 x 384 x 1024): bx=0 q, bx=1 kT, bx=2 v  [3-pass]
    hgemm<EM_QKV, 1><<<dim3(3,128,1), 256, SM_128>>>(xnH, xnL, wqkvH, wqkvL, bqkv, nullptr,
        nullptr, qH, qL, ktH, ktL, vH, vL, DMODEL, 384, 16, 0, 0, 0, 0, 1.f);

    // 4) scores = q @ kT * scale (per batch 2048 x 2048 x 128)  [3-pass]
    hgemm256<EM_F32, 0, false><<<dim3(8,16,8), 256, SM_3P>>>(qH, qL, ktH, ktL, nullptr, nullptr,
        scF, nullptr, nullptr, DKV, SEQ, 2,
        (long long)SEQ*DKV/2, (long long)DKV*SEQ/2, (long long)SEQ*SEQ, scale);

    // 5) softmax -> probs fp16 pairs
    softmax_frag<<<BATCH*SEQ, 256>>>(scF, pH, pL);

    // 6) att = probs @ v (per batch 2048 x 128 x 2048)  [3-pass]
    hgemm<EM_BF, 0><<<dim3(1,16,8), 256, SM_128>>>(pH, pL, vH, vL, nullptr, nullptr,
        nullptr, atH, atL, nullptr, nullptr, nullptr, nullptr, SEQ, DKV, 32,
        (long long)SEQ*SEQ/2, (long long)SEQ*DKV/2, 0, (long long)SEQ*DKV/2, 1.f);

    // 7) y = xn + att@Wo + bo (16384 x 1024 x 128)  [3-pass]
    hgemm256<EM_F32, 5, false><<<dim3(4,128,1), 256, SM_3P>>>(atH, atL, woH, woL, bo, xnF,
        yF, nullptr, nullptr, DKV, DMODEL, 2, 0, 0, 0, 1.f);

    // 8) ln2 -> h fp16 pairs
    ln_frag<false><<<MS, 256>>>(yF, ln2_g, ln2_b, nullptr, hH, hL);

    // 9) act = gelu(h@W1 + b1) (16384 x 4096 x 1024)  [2-pass, B single]
    hgemm256<EM_BF, 3, true><<<dim3(16,128,1), 256, SM_2P>>>(hH, hL, w1H, nullptr, b1, nullptr,
        nullptr, acH, acL, DMODEL, DFF, 16, 0, 0, 0, 1.f);

    // 10) out = y + act@W2 + b2 (16384 x 1024 x 4096)  [2-pass, B single]
    hgemm256<EM_F32, 5, true><<<dim3(4,128,1), 256, SM_2P>>>(acH, acL, w2H, nullptr, b2, yF,
        out, nullptr, nullptr, DFF, DMODEL, 64, 0, 0, 0, 1.f);
}

// round 7
// speedup vs baseline: 5.3476x; 1.4415x over previous
#include <cuda_runtime.h>
#include <cuda_fp16.h>
#include <math.h>
#include <stdint.h>

#define BATCH 8
#define SEQ   2048
#define DMODEL 1024
#define DKV   128
#define DFF   4096
#define MS    (BATCH*SEQ)

// ---------------- scratch (static device globals) ----------------------------
__device__ float    g_xnF[(size_t)MS*DMODEL];
__device__ float    g_scF[(size_t)BATCH*SEQ*SEQ];
__device__ float    g_yF [(size_t)MS*DMODEL];

__device__ uint32_t g_xnH[(size_t)MS*DMODEL/2],  g_xnL[(size_t)MS*DMODEL/2];
__device__ uint32_t g_hH [(size_t)MS*DMODEL/2];                      // single fp16
__device__ uint32_t g_qH [(size_t)MS*DKV/2],     g_qL [(size_t)MS*DKV/2];
__device__ uint32_t g_ktH[(size_t)BATCH*DKV*SEQ/2], g_ktL[(size_t)BATCH*DKV*SEQ/2];
__device__ uint32_t g_vH [(size_t)MS*DKV/2],     g_vL [(size_t)MS*DKV/2];
__device__ uint32_t g_pH [(size_t)BATCH*SEQ*SEQ/2], g_pL[(size_t)BATCH*SEQ*SEQ/2];
__device__ uint32_t g_atH[(size_t)MS*DKV/2],     g_atL[(size_t)MS*DKV/2];
__device__ uint32_t g_acH[(size_t)MS*DFF/2];                         // single fp16

__device__ uint32_t g_wqkvH[(size_t)DMODEL*384/2], g_wqkvL[(size_t)DMODEL*384/2];
__device__ float    g_bqkv[384];
__device__ uint32_t g_woH[(size_t)DKV*DMODEL/2], g_woL[(size_t)DKV*DMODEL/2];
__device__ uint32_t g_w1H[(size_t)DMODEL*DFF/2];   // single fp16
__device__ uint32_t g_w2H[(size_t)DFF*DMODEL/2];   // single fp16

// ---------------- helpers ----------------------------------------------------
__device__ __forceinline__ uint32_t smem_u32(const void* p) {
    uint32_t a;
    asm("{ .reg .u64 t; cvta.to.shared.u64 t, %1; cvt.u32.u64 %0, t; }" : "=r"(a) : "l"(p));
    return a;
}
__device__ __forceinline__ void cpasync16(uint32_t dst, const void* src) {
    asm volatile("cp.async.cg.shared.global [%0], [%1], 16;" :: "r"(dst), "l"(src));
}
#define CP_COMMIT() asm volatile("cp.async.commit_group;" ::: "memory")
#define CP_WAIT1()  asm volatile("cp.async.wait_group 1;" ::: "memory")
#define CP_WAIT2()  asm volatile("cp.async.wait_group 2;" ::: "memory")

__device__ __forceinline__ void ldm_x4(uint32_t r[4], uint32_t addr) {
    asm volatile("ldmatrix.sync.aligned.m8n8.x4.shared.b16 {%0,%1,%2,%3}, [%4];"
                 : "=r"(r[0]), "=r"(r[1]), "=r"(r[2]), "=r"(r[3]) : "r"(addr));
}
__device__ __forceinline__ void ldm_x4_t(uint32_t r[4], uint32_t addr) {
    asm volatile("ldmatrix.sync.aligned.m8n8.x4.trans.shared.b16 {%0,%1,%2,%3}, [%4];"
                 : "=r"(r[0]), "=r"(r[1]), "=r"(r[2]), "=r"(r[3]) : "r"(addr));
}
__device__ __forceinline__ void mma16816(float c[4], const uint32_t a[4], const uint32_t b[2]) {
    asm volatile("mma.sync.aligned.m16n8k16.row.col.f32.f16.f16.f32 "
                 "{%0,%1,%2,%3},{%4,%5,%6,%7},{%8,%9},{%0,%1,%2,%3};"
                 : "+f"(c[0]), "+f"(c[1]), "+f"(c[2]), "+f"(c[3])
                 : "r"(a[0]), "r"(a[1]), "r"(a[2]), "r"(a[3]), "r"(b[0]), "r"(b[1]));
}
__device__ __forceinline__ uint32_t packh(__half a, __half b) {
    return (uint32_t)__half_as_ushort(a) | ((uint32_t)__half_as_ushort(b) << 16);
}
__device__ __forceinline__ void split2(float a, float b, uint32_t& hi, uint32_t& lo) {
    __half ha = __float2half_rn(a);
    __half hb = __float2half_rn(b);
    __half la = __float2half_rn(a - __half2float(ha));
    __half lb = __float2half_rn(b - __half2float(hb));
    hi = packh(ha, hb);
    lo = packh(la, lb);
}
__device__ __forceinline__ uint32_t pack2(float a, float b) {
    return packh(__float2half_rn(a), __float2half_rn(b));
}
__device__ __forceinline__ float gelu1(float v) {
    return 0.5f * v * (1.0f + erff(v * 0.70710678118654752f));
}

// ---------------- one-shot weight conversion (all weights, one launch) -------
struct WJobs {
    const float* src[6];
    uint32_t* H[6];
    uint32_t* L[6];      // null -> single fp16
    int np[6];
    int srcP[6];
    int dstP[6];
    int coff[6];
    int blkStart[7];
    const float* bq; const float* bk; const float* bv;
    float* bqkv;
};

__global__ __launch_bounds__(256) void wconv_all(WJobs jb)
{
    const int blk = blockIdx.x, tid = threadIdx.x;
    if (blk >= jb.blkStart[6]) {
        if (tid < 128) {
            jb.bqkv[tid]       = jb.bq[tid];
            jb.bqkv[128 + tid] = jb.bk[tid];
            jb.bqkv[256 + tid] = jb.bv[tid];
        }
        return;
    }
    int seg = 0;
    #pragma unroll
    for (int s = 1; s < 6; s++) if (blk >= jb.blkStart[s]) seg = s;
    int u = (blk - jb.blkStart[seg]) * 256 + tid;
    if (u >= jb.np[seg]) return;
    int k = u / jb.srcP[seg], p = u - k * jb.srcP[seg];
    float2 v = *(const float2*)(jb.src[seg] + ((size_t)u) * 2);
    size_t di = (size_t)k * jb.dstP[seg] + jb.coff[seg] + p;
    if (jb.L[seg]) {
        uint32_t h, l;
        split2(v.x, v.y, h, l);
        jb.H[seg][di] = h; jb.L[seg][di] = l;
    } else {
        jb.H[seg][di] = pack2(v.x, v.y);
    }
}

// ---------------- LayerNorm: one row/block ------------------------------------
// WF32: also write f32. SPLIT: emit hi/lo pairs (else single fp16 pairs).
template<bool WF32, bool SPLIT>
__global__ __launch_bounds__(256) void ln_frag(const float* __restrict__ x,
                                               const float* __restrict__ g,
                                               const float* __restrict__ b,
                                               float* __restrict__ oF,
                                               uint32_t* __restrict__ H,
                                               uint32_t* __restrict__ L)
{
    const int row = blockIdx.x;
    const int tid = threadIdx.x;
    const float* xr = x + (size_t)row * DMODEL;
    float4 v = *(const float4*)(xr + tid * 4);

    float s  = v.x + v.y + v.z + v.w;
    float s2 = v.x*v.x + v.y*v.y + v.z*v.z + v.w*v.w;
    #pragma unroll
    for (int off = 16; off; off >>= 1) {
        s  += __shfl_xor_sync(0xffffffffu, s,  off);
        s2 += __shfl_xor_sync(0xffffffffu, s2, off);
    }
    __shared__ float ss[8], ss2[8], stats[2];
    const int wid = tid >> 5, lane = tid & 31;
    if (lane == 0) { ss[wid] = s; ss2[wid] = s2; }
    __syncthreads();
    if (wid == 0) {
        s  = (lane < 8) ? ss[lane]  : 0.f;
        s2 = (lane < 8) ? ss2[lane] : 0.f;
        #pragma unroll
        for (int off = 4; off; off >>= 1) {
            s  += __shfl_xor_sync(0xffffffffu, s,  off);
            s2 += __shfl_xor_sync(0xffffffffu, s2, off);
        }
        if (lane == 0) {
            float mean = s * (1.0f / DMODEL);
            float var  = s2 * (1.0f / DMODEL) - mean * mean;
            stats[0] = mean;
            stats[1] = rsqrtf(var + 1e-5f);
        }
    }
    __syncthreads();
    const float mean = stats[0], rstd = stats[1];
    float4 gg = *(const float4*)(g + tid * 4);
    float4 bb = *(const float4*)(b + tid * 4);
    float4 o;
    o.x = (v.x - mean) * rstd * gg.x + bb.x;
    o.y = (v.y - mean) * rstd * gg.y + bb.y;
    o.z = (v.z - mean) * rstd * gg.z + bb.z;
    o.w = (v.w - mean) * rstd * gg.w + bb.w;
    if (WF32) *(float4*)(oF + (size_t)row * DMODEL + tid * 4) = o;
    size_t base = (size_t)row * (DMODEL / 2) + tid * 2;
    if (SPLIT) {
        uint32_t h0, l0, h1, l1;
        split2(o.x, o.y, h0, l0);
        split2(o.z, o.w, h1, l1);
        H[base] = h0; H[base + 1] = h1;
        L[base] = l0; L[base + 1] = l1;
    } else {
        H[base]     = pack2(o.x, o.y);
        H[base + 1] = pack2(o.z, o.w);
    }
}

// ---------------- softmax: one row/block, emits probs fp16 pairs --------------
__global__ __launch_bounds__(256) void softmax_frag(const float* __restrict__ S,
                                                    uint32_t* __restrict__ H,
                                                    uint32_t* __restrict__ L)
{
    const size_t row = blockIdx.x;
    const float* p = S + row * (size_t)SEQ;
    const int tid = threadIdx.x;
    float4 a = *(const float4*)(p + tid * 4);
    float4 c = *(const float4*)(p + 1024 + tid * 4);

    float m = fmaxf(fmaxf(fmaxf(a.x, a.y), fmaxf(a.z, a.w)),
                    fmaxf(fmaxf(c.x, c.y), fmaxf(c.z, c.w)));
    #pragma unroll
    for (int off = 16; off; off >>= 1)
        m = fmaxf(m, __shfl_xor_sync(0xffffffffu, m, off));
    __shared__ float sm[8], sred[2];
    const int wid = tid >> 5, lane = tid & 31;
    if (lane == 0) sm[wid] = m;
    __syncthreads();
    if (wid == 0) {
        m = (lane < 8) ? sm[lane] : -1e30f;
        #pragma unroll
        for (int off = 4; off; off >>= 1)
            m = fmaxf(m, __shfl_xor_sync(0xffffffffu, m, off));
        if (lane == 0) sred[0] = m;
    }
    __syncthreads();
    m = sred[0];

    a.x = expf(a.x - m); a.y = expf(a.y - m); a.z = expf(a.z - m); a.w = expf(a.w - m);
    c.x = expf(c.x - m); c.y = expf(c.y - m); c.z = expf(c.z - m); c.w = expf(c.w - m);
    float s = a.x + a.y + a.z + a.w + c.x + c.y + c.z + c.w;
    #pragma unroll
    for (int off = 16; off; off >>= 1)
        s += __shfl_xor_sync(0xffffffffu, s, off);
    if (lane == 0) sm[wid] = s;
    __syncthreads();
    if (wid == 0) {
        s = (lane < 8) ? sm[lane] : 0.f;
        #pragma unroll
        for (int off = 4; off; off >>= 1)
            s += __shfl_xor_sync(0xffffffffu, s, off);
        if (lane == 0) sred[1] = 1.0f / s;
    }
    __syncthreads();
    const float r = sred[1];
    a.x *= r; a.y *= r; a.z *= r; a.w *= r;
    c.x *= r; c.y *= r; c.z *= r; c.w *= r;

    uint32_t h, l;
    size_t base = row * (SEQ / 2) + tid * 2;
    split2(a.x, a.y, h, l); H[base] = h;       L[base] = l;
    split2(a.z, a.w, h, l); H[base + 1] = h;   L[base + 1] = l;
    base += 512;
    split2(c.x, c.y, h, l); H[base] = h;       L[base] = l;
    split2(c.z, c.w, h, l); H[base + 1] = h;   L[base + 1] = l;
}

// ================= HMMA GEMM, BN=128 (3-stage), BK=64, 3-pass fp16 ===========
#define EM_F32 0
#define EM_BF  1
#define EM_QKV 3
#define EM_HF  4

template<int EMIT, int EPI>
__global__ __launch_bounds__(256, 1)
void hgemm(const uint32_t* __restrict__ Ah, const uint32_t* __restrict__ Al,
           const uint32_t* __restrict__ Bh, const uint32_t* __restrict__ Bl,
           const float* __restrict__ bias, const float* __restrict__ res,
           float* __restrict__ outF, uint32_t* __restrict__ outH, uint32_t* __restrict__ outL,
           uint32_t* __restrict__ outH2, uint32_t* __restrict__ outL2,
           uint32_t* __restrict__ outH3, uint32_t* __restrict__ outL3,
           int Ka, int Nb, int nc,
           long long sAu, long long sBu, long long sCf, long long sOu,
           float alpha)
{
    extern __shared__ char smc[];
    const uint32_t sb = smem_u32(smc);
    const int tid = threadIdx.x, wid = tid >> 5, lane = tid & 31;
    const int wm = wid >> 2, wn = wid & 3;
    const int bx = blockIdx.x, by = blockIdx.y, bz = blockIdx.z;

    const uint32_t Ka2 = (uint32_t)Ka >> 1, Nb2 = (uint32_t)Nb >> 1;
    const uint32_t* Ahb = Ah + (size_t)bz * sAu;
    const uint32_t* Alb = Al + (size_t)bz * sAu;
    const uint32_t* Bhb = Bh + (size_t)bz * sBu;
    const uint32_t* Blb = Bl + (size_t)bz * sBu;

    auto load_stage = [&](int st, int c) {
        const uint32_t stb = sb + st * 65536;
        #pragma unroll
        for (int t = 0; t < 4; t++) {
            int id = tid + t * 256;
            int m = id >> 3, ch = id & 7;
            size_t go = (size_t)(by * 128 + m) * Ka2 + (size_t)c * 32 + ch * 4;
            uint32_t sa = stb + m * 128 + ((ch ^ (m & 7)) << 4);
            cpasync16(sa, Ahb + go);
            cpasync16(sa + 16384, Alb + go);
        }
        #pragma unroll
        for (int t = 0; t < 4; t++) {
            int id = tid + t * 256;
            int k = id >> 4, ch = id & 15;
            size_t go = (size_t)(c * 64 + k) * Nb2 + (size_t)bx * 64 + ch * 4;
            uint32_t sa = stb + 32768 + k * 256 + ((ch ^ (k & 15)) << 4);
            cpasync16(sa, Bhb + go);
            cpasync16(sa + 16384, Blb + go);
        }
    };

    float acc[4][4][4];
    #pragma unroll
    for (int i = 0; i < 4; i++)
        #pragma unroll
        for (int j = 0; j < 4; j++)
            #pragma unroll
            for (int r = 0; r < 4; r++) acc[i][j][r] = 0.f;

    load_stage(0, 0); CP_COMMIT();
    load_stage(1, 1); CP_COMMIT();

    const int q = lane >> 3, l7 = lane & 7;

    for (int c = 0; c < nc; ++c) {
        CP_WAIT1();
        __syncthreads();
        if (c + 2 < nc) load_stage((c + 2) % 3, c + 2);
        CP_COMMIT();

        const uint32_t stb = sb + (c % 3) * 65536;
        #pragma unroll
        for (int ks = 0; ks < 4; ks++) {
            uint32_t aH[4][4], aL[4][4], bH4[2][4], bL4[2][4];
            #pragma unroll
            for (int i = 0; i < 4; i++) {
                int m = wm * 64 + i * 16 + ((q & 1) << 3) + l7;
                int ch = 2 * ks + (q >> 1);
                uint32_t ad = stb + m * 128 + ((ch ^ (m & 7)) << 4);
                ldm_x4(aH[i], ad);
                ldm_x4(aL[i], ad + 16384);
            }
            #pragma unroll
            for (int g = 0; g < 2; g++) {
                int k = ks * 16 + ((q & 1) << 3) + l7;
                int ch = wn * 4 + g * 2 + (q >> 1);
                uint32_t bd = stb + 32768 + k * 256 + ((ch ^ (k & 15)) << 4);
                ldm_x4_t(bH4[g], bd);
                ldm_x4_t(bL4[g], bd + 16384);
            }
            #pragma unroll
            for (int i = 0; i < 4; i++)
                #pragma unroll
                for (int j = 0; j < 4; j++) {
                    const uint32_t* bh = &bH4[j >> 1][(j & 1) * 2];
                    const uint32_t* bl = &bL4[j >> 1][(j & 1) * 2];
                    mma16816(acc[i][j], aH[i], bh);
                    mma16816(acc[i][j], aH[i], bl);
                    mma16816(acc[i][j], aL[i], bh);
                }
        }
    }

    __syncthreads();
    float* Cs = (float*)smc;
    #pragma unroll
    for (int i = 0; i < 4; i++)
        #pragma unroll
        for (int j = 0; j < 4; j++) {
            int r0 = wm * 64 + i * 16 + (lane >> 2);
            int c0 = wn * 32 + j * 8 + 2 * (lane & 3);
            *(float2*)(Cs + r0 * 132 + c0)       = make_float2(acc[i][j][0], acc[i][j][1]);
            *(float2*)(Cs + (r0 + 8) * 132 + c0) = make_float2(acc[i][j][2], acc[i][j][3]);
        }
    __syncthreads();

    if (EMIT == EM_F32) {
        #pragma unroll
        for (int i = 0; i < 16; i++) {
            int u = tid + 256 * i;
            int row = u >> 5, c4 = (u & 31) * 4;
            float4 v = *(float4*)(Cs + row * 132 + c4);
            v.x *= alpha; v.y *= alpha; v.z *= alpha; v.w *= alpha;
            int gc = bx * 128 + c4;
            size_t gm = (size_t)by * 128 + row;
            if (EPI & 1) {
                float4 bb = *(const float4*)(bias + gc);
                v.x += bb.x; v.y += bb.y; v.z += bb.z; v.w += bb.w;
            }
            if (EPI & 2) { v.x = gelu1(v.x); v.y = gelu1(v.y); v.z = gelu1(v.z); v.w = gelu1(v.w); }
            if (EPI & 4) {
                float4 rr = *(const float4*)(res + gm * Nb + gc);
                v.x += rr.x; v.y += rr.y; v.z += rr.z; v.w += rr.w;
            }
            *(float4*)(outF + (size_t)bz * sCf + gm * Nb + gc) = v;
        }
    } else if (EMIT == EM_BF) {
        #pragma unroll
        for (int i = 0; i < 32; i++) {
            int u = tid + 256 * i;
            int row = u >> 6, np = u & 63;
            float v0 = Cs[row * 132 + 2 * np]     * alpha;
            float v1 = Cs[row * 132 + 2 * np + 1] * alpha;
            int gc = bx * 128 + 2 * np;
            if (EPI & 1) { v0 += __ldg(bias + gc); v1 += __ldg(bias + gc + 1); }
            if (EPI & 2) { v0 = gelu1(v0); v1 = gelu1(v1); }
            uint32_t h, l;
            split2(v0, v1, h, l);
            size_t gm = (size_t)by * 128 + row;
            size_t idx = (size_t)bz * sOu + gm * (Nb >> 1) + (size_t)bx * 64 + np;
            outH[idx] = h; outL[idx] = l;
        }
    } else { // EM_QKV
        if (bx == 1) {
            const int b = by >> 4;
            const int s0p = (by & 15) * 64;
            #pragma unroll
            for (int i = 0; i < 32; i++) {
                int u = tid + 256 * i;
                int d = u >> 6, sp = u & 63;
                float bb = __ldg(bias + 128 + d);
                float v0 = Cs[(2 * sp) * 132 + d]     + bb;
                float v1 = Cs[(2 * sp + 1) * 132 + d] + bb;
                uint32_t h, l;
                split2(v0, v1, h, l);
                size_t idx = (size_t)b * (DKV * SEQ / 2) + (size_t)d * (SEQ / 2) + s0p + sp;
                outH2[idx] = h; outL2[idx] = l;
            }
        } else {
            uint32_t* oh = (bx == 0) ? outH : outH3;
            uint32_t* ol = (bx == 0) ? outL : outL3;
            #pragma unroll
            for (int i = 0; i < 32; i++) {
                int u = tid + 256 * i;
                int row = u >> 6, np = u & 63;
                float v0 = Cs[row * 132 + 2 * np]     + __ldg(bias + bx * 128 + 2 * np);
                float v1 = Cs[row * 132 + 2 * np + 1] + __ldg(bias + bx * 128 + 2 * np + 1);
                uint32_t h, l;
                split2(v0, v1, h, l);
                size_t idx = ((size_t)by * 128 + row) * 64 + np;
                oh[idx] = h; ol[idx] = l;
            }
        }
    }
}

// ================= HMMA GEMM, BN=256, BK=64, 3-pass (2-stage) ================
template<int EMIT, int EPI>
__global__ __launch_bounds__(256, 1)
void hgemm256(const uint32_t* __restrict__ Ah, const uint32_t* __restrict__ Al,
              const uint32_t* __restrict__ Bh, const uint32_t* __restrict__ Bl,
              const float* __restrict__ bias, const float* __restrict__ res,
              float* __restrict__ outF, uint32_t* __restrict__ outH, uint32_t* __restrict__ outL,
              int Ka, int Nb, int nc,
              long long sAu, long long sBu, long long sCf,
              float alpha)
{
    extern __shared__ char smc[];
    const uint32_t sb = smem_u32(smc);
    const int tid = threadIdx.x, wid = tid >> 5, lane = tid & 31;
    const int wm = wid >> 2, wn = wid & 3;
    const int bx = blockIdx.x, by = blockIdx.y, bz = blockIdx.z;

    const uint32_t Ka2 = (uint32_t)Ka >> 1, Nb2 = (uint32_t)Nb >> 1;
    const uint32_t* Ahb = Ah + (size_t)bz * sAu;
    const uint32_t* Alb = Al + (size_t)bz * sAu;
    const uint32_t* Bhb = Bh + (size_t)bz * sBu;
    const uint32_t* Blb = Bl + (size_t)bz * sBu;

    auto load_stage = [&](int st, int c) {
        const uint32_t stb = sb + st * 98304;
        #pragma unroll
        for (int t = 0; t < 4; t++) {
            int id = tid + t * 256;
            int m = id >> 3, ch = id & 7;
            size_t go = (size_t)(by * 128 + m) * Ka2 + (size_t)c * 32 + ch * 4;
            uint32_t sa = stb + m * 128 + ((ch ^ (m & 7)) << 4);
            cpasync16(sa, Ahb + go);
            cpasync16(sa + 16384, Alb + go);
        }
        #pragma unroll
        for (int t = 0; t < 8; t++) {
            int id = tid + t * 256;
            int k = id >> 5, ch = id & 31;
            size_t go = (size_t)(c * 64 + k) * Nb2 + (size_t)bx * 128 + ch * 4;
            uint32_t sa = stb + 32768 + k * 512 + ((ch ^ (k & 15)) << 4);
            cpasync16(sa, Bhb + go);
            cpasync16(sa + 32768, Blb + go);
        }
    };

    float acc[4][8][4];
    #pragma unroll
    for (int i = 0; i < 4; i++)
        #pragma unroll
        for (int j = 0; j < 8; j++)
            #pragma unroll
            for (int r = 0; r < 4; r++) acc[i][j][r] = 0.f;

    load_stage(0, 0); CP_COMMIT();
    load_stage(1, 1); CP_COMMIT();

    const int q = lane >> 3, l7 = lane & 7;

    for (int c = 0; c < nc; ++c) {
        CP_WAIT1();
        __syncthreads();

        const uint32_t stb = sb + (c & 1) * 98304;
        #pragma unroll
        for (int ks = 0; ks < 4; ks++) {
            uint32_t aH[4][4], aL[4][4];
            #pragma unroll
            for (int i = 0; i < 4; i++) {
                int m = wm * 64 + i * 16 + ((q & 1) << 3) + l7;
                int ch = 2 * ks + (q >> 1);
                uint32_t ad = stb + m * 128 + ((ch ^ (m & 7)) << 4);
                ldm_x4(aH[i], ad);
                ldm_x4(aL[i], ad + 16384);
            }
            #pragma unroll
            for (int g = 0; g < 4; g++) {
                uint32_t bH4[4], bL4[4];
                int k = ks * 16 + ((q & 1) << 3) + l7;
                int ch = wn * 8 + g * 2 + (q >> 1);
                uint32_t bd = stb + 32768 + k * 512 + ((ch ^ (k & 15)) << 4);
                ldm_x4_t(bH4, bd);
                ldm_x4_t(bL4, bd + 32768);
                #pragma unroll
                for (int i = 0; i < 4; i++) {
                    #pragma unroll
                    for (int jj = 0; jj < 2; jj++) {
                        const uint32_t* bh = &bH4[jj * 2];
                        float* a4 = acc[i][g * 2 + jj];
                        mma16816(a4, aH[i], bh);
                        mma16816(a4, aL[i], bh);
                        mma16816(a4, aH[i], &bL4[jj * 2]);
                    }
                }
            }
        }
        __syncthreads();
        if (c + 2 < nc) load_stage(c & 1, c + 2);
        CP_COMMIT();
    }

    __syncthreads();
    float* Cs = (float*)smc;
    #pragma unroll
    for (int i = 0; i < 4; i++)
        #pragma unroll
        for (int j = 0; j < 8; j++) {
            int r0 = wm * 64 + i * 16 + (lane >> 2);
            int c0 = wn * 64 + j * 8 + 2 * (lane & 3);
            *(float2*)(Cs + r0 * 260 + c0)       = make_float2(acc[i][j][0], acc[i][j][1]);
            *(float2*)(Cs + (r0 + 8) * 260 + c0) = make_float2(acc[i][j][2], acc[i][j][3]);
        }
    __syncthreads();

    if (EMIT == EM_F32) {
        #pragma unroll
        for (int i = 0; i < 32; i++) {
            int u = tid + 256 * i;
            int row = u >> 6, c4 = (u & 63) * 4;
            float4 v = *(float4*)(Cs + row * 260 + c4);
            v.x *= alpha; v.y *= alpha; v.z *= alpha; v.w *= alpha;
            int gc = bx * 256 + c4;
            size_t gm = (size_t)by * 128 + row;
            if (EPI & 1) {
                float4 bb = *(const float4*)(bias + gc);
                v.x += bb.x; v.y += bb.y; v.z += bb.z; v.w += bb.w;
            }
            if (EPI & 2) { v.x = gelu1(v.x); v.y = gelu1(v.y); v.z = gelu1(v.z); v.w = gelu1(v.w); }
            if (EPI & 4) {
                float4 rr = *(const float4*)(res + gm * Nb + gc);
                v.x += rr.x; v.y += rr.y; v.z += rr.z; v.w += rr.w;
            }
            *(float4*)(outF + (size_t)bz * sCf + gm * Nb + gc) = v;
        }
    } else { // EM_BF
        #pragma unroll
        for (int i = 0; i < 64; i++) {
            int u = tid + 256 * i;
            int row = u >> 7, np = u & 127;
            float v0 = Cs[row * 260 + 2 * np]     * alpha;
            float v1 = Cs[row * 260 + 2 * np + 1] * alpha;
            int gc = bx * 256 + 2 * np;
            if (EPI & 1) { v0 += __ldg(bias + gc); v1 += __ldg(bias + gc + 1); }
            if (EPI & 2) { v0 = gelu1(v0); v1 = gelu1(v1); }
            uint32_t h, l;
            split2(v0, v1, h, l);
            size_t gm = (size_t)by * 128 + row;
            size_t idx = gm * (Nb >> 1) + (size_t)bx * 128 + np;
            outH[idx] = h; outL[idx] = l;
        }
    }
}

// ================= HMMA GEMM, BN=256, BK=64, 1-pass fp16 (4-stage) ===========
// A single fp16 pairs, B single fp16 pairs. EMITs: EM_F32, EM_HF.
template<int EMIT, int EPI>
__global__ __launch_bounds__(256, 1)
void hgemm1p(const uint32_t* __restrict__ Ah, const uint32_t* __restrict__ Bh,
             const float* __restrict__ bias, const float* __restrict__ res,
             float* __restrict__ outF, uint32_t* __restrict__ outH,
             int Ka, int Nb, int nc, float alpha)
{
    extern __shared__ char smc[];
    const uint32_t sb = smem_u32(smc);
    const int tid = threadIdx.x, wid = tid >> 5, lane = tid & 31;
    const int wm = wid >> 2, wn = wid & 3;
    const int bx = blockIdx.x, by = blockIdx.y;

    const uint32_t Ka2 = (uint32_t)Ka >> 1, Nb2 = (uint32_t)Nb >> 1;

    // stage: A 16KB at 0 | B 32KB at 16384.  4 stages x 48KB = 192KB.
    auto load_stage = [&](int st, int c) {
        const uint32_t stb = sb + st * 49152;
        #pragma unroll
        for (int t = 0; t < 4; t++) {
            int id = tid + t * 256;
            int m = id >> 3, ch = id & 7;
            size_t go = (size_t)(by * 128 + m) * Ka2 + (size_t)c * 32 + ch * 4;
            cpasync16(stb + m * 128 + ((ch ^ (m & 7)) << 4), Ah + go);
        }
        #pragma unroll
        for (int t = 0; t < 8; t++) {
            int id = tid + t * 256;
            int k = id >> 5, ch = id & 31;
            size_t go = (size_t)(c * 64 + k) * Nb2 + (size_t)bx * 128 + ch * 4;
            cpasync16(stb + 16384 + k * 512 + ((ch ^ (k & 15)) << 4), Bh + go);
        }
    };

    float acc[4][8][4];
    #pragma unroll
    for (int i = 0; i < 4; i++)
        #pragma unroll
        for (int j = 0; j < 8; j++)
            #pragma unroll
            for (int r = 0; r < 4; r++) acc[i][j][r] = 0.f;

    load_stage(0, 0); CP_COMMIT();
    load_stage(1, 1); CP_COMMIT();
    load_stage(2, 2); CP_COMMIT();

    const int q = lane >> 3, l7 = lane & 7;

    for (int c = 0; c < nc; ++c) {
        CP_WAIT2();
        __syncthreads();
        if (c + 3 < nc) load_stage((c + 3) & 3, c + 3);
        CP_COMMIT();

        const uint32_t stb = sb + (c & 3) * 49152;
        #pragma unroll
        for (int ks = 0; ks < 4; ks++) {
            uint32_t aH[4][4];
            #pragma unroll
            for (int i = 0; i < 4; i++) {
                int m = wm * 64 + i * 16 + ((q & 1) << 3) + l7;
                int ch = 2 * ks + (q >> 1);
                ldm_x4(aH[i], stb + m * 128 + ((ch ^ (m & 7)) << 4));
            }
            #pragma unroll
            for (int g = 0; g < 4; g++) {
                uint32_t bH4[4];
                int k = ks * 16 + ((q & 1) << 3) + l7;
                int ch = wn * 8 + g * 2 + (q >> 1);
                ldm_x4_t(bH4, stb + 16384 + k * 512 + ((ch ^ (k & 15)) << 4));
                #pragma unroll
                for (int i = 0; i < 4; i++) {
                    mma16816(acc[i][g * 2 + 0], aH[i], &bH4[0]);
                    mma16816(acc[i][g * 2 + 1], aH[i], &bH4[2]);
                }
            }
        }
    }

    __syncthreads();
    float* Cs = (float*)smc;
    #pragma unroll
    for (int i = 0; i < 4; i++)
        #pragma unroll
        for (int j = 0; j < 8; j++) {
            int r0 = wm * 64 + i * 16 + (lane >> 2);
            int c0 = wn * 64 + j * 8 + 2 * (lane & 3);
            *(float2*)(Cs + r0 * 260 + c0)       = make_float2(acc[i][j][0], acc[i][j][1]);
            *(float2*)(Cs + (r0 + 8) * 260 + c0) = make_float2(acc[i][j][2], acc[i][j][3]);
        }
    __syncthreads();

    if (EMIT == EM_F32) {
        #pragma unroll
        for (int i = 0; i < 32; i++) {
            int u = tid + 256 * i;
            int row = u >> 6, c4 = (u & 63) * 4;
            float4 v = *(float4*)(Cs + row * 260 + c4);
            v.x *= alpha; v.y *= alpha; v.z *= alpha; v.w *= alpha;
            int gc = bx * 256 + c4;
            size_t gm = (size_t)by * 128 + row;
            if (EPI & 1) {
                float4 bb = *(const float4*)(bias + gc);
                v.x += bb.x; v.y += bb.y; v.z += bb.z; v.w += bb.w;
            }
            if (EPI & 2) { v.x = gelu1(v.x); v.y = gelu1(v.y); v.z = gelu1(v.z); v.w = gelu1(v.w); }
            if (EPI & 4) {
                float4 rr = *(const float4*)(res + gm * Nb + gc);
                v.x += rr.x; v.y += rr.y; v.z += rr.z; v.w += rr.w;
            }
            *(float4*)(outF + gm * Nb + gc) = v;
        }
    } else { // EM_HF: single fp16 pairs
        #pragma unroll
        for (int i = 0; i < 64; i++) {
            int u = tid + 256 * i;
            int row = u >> 7, np = u & 127;
            float v0 = Cs[row * 260 + 2 * np]     * alpha;
            float v1 = Cs[row * 260 + 2 * np + 1] * alpha;
            int gc = bx * 256 + 2 * np;
            if (EPI & 1) { v0 += __ldg(bias + gc); v1 += __ldg(bias + gc + 1); }
            if (EPI & 2) { v0 = gelu1(v0); v1 = gelu1(v1); }
            size_t gm = (size_t)by * 128 + row;
            outH[gm * (Nb >> 1) + (size_t)bx * 128 + np] = pack2(v0, v1);
        }
    }
}

// ---------------- launch sequence -------------------------------------------
extern "C" void kernel_launch(void* const* d_in, const int* in_sizes, int n_in,
                              void* d_out, int out_size)
{
    const float* x     = (const float*)d_in[0];
    const float* ln1_g = (const float*)d_in[1];
    const float* ln1_b = (const float*)d_in[2];
    const float* Wq    = (const float*)d_in[3];
    const float* bq    = (const float*)d_in[4];
    const float* Wk    = (const float*)d_in[5];
    const float* bk    = (const float*)d_in[6];
    const float* Wv    = (const float*)d_in[7];
    const float* bv    = (const float*)d_in[8];
    const float* Wo    = (const float*)d_in[9];
    const float* bo    = (const float*)d_in[10];
    const float* ln2_g = (const float*)d_in[11];
    const float* ln2_b = (const float*)d_in[12];
    const float* W1    = (const float*)d_in[13];
    const float* b1    = (const float*)d_in[14];
    const float* W2    = (const float*)d_in[15];
    const float* b2    = (const float*)d_in[16];
    float* out = (float*)d_out;

    float *xnF, *scF, *yF, *bqkv;
    uint32_t *xnH,*xnL,*hH,*qH,*qL,*ktH,*ktL,*vH,*vL,*pH,*pL,*atH,*atL,*acH;
    uint32_t *wqkvH,*wqkvL,*woH,*woL,*w1H,*w2H;
    cudaGetSymbolAddress((void**)&xnF, g_xnF); cudaGetSymbolAddress((void**)&scF, g_scF);
    cudaGetSymbolAddress((void**)&yF,  g_yF);  cudaGetSymbolAddress((void**)&bqkv, g_bqkv);
    cudaGetSymbolAddress((void**)&xnH, g_xnH); cudaGetSymbolAddress((void**)&xnL, g_xnL);
    cudaGetSymbolAddress((void**)&hH,  g_hH);
    cudaGetSymbolAddress((void**)&qH,  g_qH);  cudaGetSymbolAddress((void**)&qL,  g_qL);
    cudaGetSymbolAddress((void**)&ktH, g_ktH); cudaGetSymbolAddress((void**)&ktL, g_ktL);
    cudaGetSymbolAddress((void**)&vH,  g_vH);  cudaGetSymbolAddress((void**)&vL,  g_vL);
    cudaGetSymbolAddress((void**)&pH,  g_pH);  cudaGetSymbolAddress((void**)&pL,  g_pL);
    cudaGetSymbolAddress((void**)&atH, g_atH); cudaGetSymbolAddress((void**)&atL, g_atL);
    cudaGetSymbolAddress((void**)&acH, g_acH);
    cudaGetSymbolAddress((void**)&wqkvH, g_wqkvH); cudaGetSymbolAddress((void**)&wqkvL, g_wqkvL);
    cudaGetSymbolAddress((void**)&woH, g_woH); cudaGetSymbolAddress((void**)&woL, g_woL);
    cudaGetSymbolAddress((void**)&w1H, g_w1H);
    cudaGetSymbolAddress((void**)&w2H, g_w2H);

    const int SM_128 = 3 * 65536;   // 192 KB
    const int SM_3P  = 2 * 98304;   // 192 KB
    const int SM_1P  = 4 * 49152;   // 192 KB
    cudaFuncSetAttribute(hgemm<EM_QKV,1>,     cudaFuncAttributeMaxDynamicSharedMemorySize, SM_128);
    cudaFuncSetAttribute(hgemm<EM_BF, 0>,     cudaFuncAttributeMaxDynamicSharedMemorySize, SM_128);
    cudaFuncSetAttribute(hgemm256<EM_F32,0>,  cudaFuncAttributeMaxDynamicSharedMemorySize, SM_3P);
    cudaFuncSetAttribute(hgemm256<EM_F32,5>,  cudaFuncAttributeMaxDynamicSharedMemorySize, SM_3P);
    cudaFuncSetAttribute(hgemm1p<EM_HF, 3>,   cudaFuncAttributeMaxDynamicSharedMemorySize, SM_1P);
    cudaFuncSetAttribute(hgemm1p<EM_F32,5>,   cudaFuncAttributeMaxDynamicSharedMemorySize, SM_1P);

    const float scale = 0.08838834764831845f; // 1/sqrt(128)

    // ---- 1 launch: all weight conversions + qkv bias pack ----
    {
        WJobs jb;
        jb.src[0] = Wq; jb.H[0] = wqkvH; jb.L[0] = wqkvL; jb.np[0] = DMODEL*DKV/2; jb.srcP[0] = 64;  jb.dstP[0] = 192; jb.coff[0] = 0;
        jb.src[1] = Wk; jb.H[1] = wqkvH; jb.L[1] = wqkvL; jb.np[1] = DMODEL*DKV/2; jb.srcP[1] = 64;  jb.dstP[1] = 192; jb.coff[1] = 64;
        jb.src[2] = Wv; jb.H[2] = wqkvH; jb.L[2] = wqkvL; jb.np[2] = DMODEL*DKV/2; jb.srcP[2] = 64;  jb.dstP[2] = 192; jb.coff[2] = 128;
        jb.src[3] = Wo; jb.H[3] = woH;   jb.L[3] = woL;   jb.np[3] = DKV*DMODEL/2; jb.srcP[3] = 512; jb.dstP[3] = 512; jb.coff[3] = 0;
        jb.src[4] = W1; jb.H[4] = w1H;   jb.L[4] = nullptr; jb.np[4] = DMODEL*DFF/2; jb.srcP[4] = 2048; jb.dstP[4] = 2048; jb.coff[4] = 0;
        jb.src[5] = W2; jb.H[5] = w2H;   jb.L[5] = nullptr; jb.np[5] = DFF*DMODEL/2; jb.srcP[5] = 512;  jb.dstP[5] = 512;  jb.coff[5] = 0;
        int acc_ = 0;
        for (int s = 0; s < 6; s++) { jb.blkStart[s] = acc_; acc_ += (jb.np[s] + 255) / 256; }
        jb.blkStart[6] = acc_;
        jb.bq = bq; jb.bk = bk; jb.bv = bv; jb.bqkv = bqkv;
        wconv_all<<<acc_ + 1, 256>>>(jb);
    }

    // 2) ln1 -> xn (f32 + split fp16 pairs)
    ln_frag<true, true><<<MS, 256>>>(x, ln1_g, ln1_b, xnF, xnH, xnL);

    // 3) fused QKV (16384 x 384 x 1024): bx=0 q, bx=1 kT, bx=2 v  [3-pass]
    hgemm<EM_QKV, 1><<<dim3(3,128,1), 256, SM_128>>>(xnH, xnL, wqkvH, wqkvL, bqkv, nullptr,
        nullptr, qH, qL, ktH, ktL, vH, vL, DMODEL, 384, 16, 0, 0, 0, 0, 1.f);

    // 4) scores = q @ kT * scale (per batch 2048 x 2048 x 128)  [3-pass]
    hgemm256<EM_F32, 0><<<dim3(8,16,8), 256, SM_3P>>>(qH, qL, ktH, ktL, nullptr, nullptr,
        scF, nullptr, nullptr, DKV, SEQ, 2,
        (long long)SEQ*DKV/2, (long long)DKV*SEQ/2, (long long)SEQ*SEQ, scale);

    // 5) softmax -> probs fp16 split pairs
    softmax_frag<<<BATCH*SEQ, 256>>>(scF, pH, pL);

    // 6) att = probs @ v (per batch 2048 x 128 x 2048)  [3-pass]
    hgemm<EM_BF, 0><<<dim3(1,16,8), 256, SM_128>>>(pH, pL, vH, vL, nullptr, nullptr,
        nullptr, atH, atL, nullptr, nullptr, nullptr, nullptr, SEQ, DKV, 32,
        (long long)SEQ*SEQ/2, (long long)SEQ*DKV/2, 0, (long long)SEQ*DKV/2, 1.f);

    // 7) y = xn + att@Wo + bo (16384 x 1024 x 128)  [3-pass]
    hgemm256<EM_F32, 5><<<dim3(4,128,1), 256, SM_3P>>>(atH, atL, woH, woL, bo, xnF,
        yF, nullptr, nullptr, DKV, DMODEL, 2, 0, 0, 0, 1.f);

    // 8) ln2 -> h single fp16 pairs
    ln_frag<false, false><<<MS, 256>>>(yF, ln2_g, ln2_b, nullptr, hH, nullptr);

    // 9) act = gelu(h@W1 + b1) (16384 x 4096 x 1024)  [1-pass]
    hgemm1p<EM_HF, 3><<<dim3(16,128,1), 256, SM_1P>>>(hH, w1H, b1, nullptr,
        nullptr, acH, DMODEL, DFF, 16, 1.f);

    // 10) out = y + act@W2 + b2 (16384 x 1024 x 4096)  [1-pass]
    hgemm1p<EM_F32, 5><<<dim3(4,128,1), 256, SM_1P>>>(acH, w2H, b2, yF,
        out, nullptr, DFF, DMODEL, 64, 1.f);
}

// round 8
// speedup vs baseline: 6.1743x; 1.1546x over previous
#include <cuda_runtime.h>
#include <cuda_fp16.h>
#include <math.h>
#include <stdint.h>

#define BATCH 8
#define SEQ   2048
#define DMODEL 1024
#define DKV   128
#define DFF   4096
#define MS    (BATCH*SEQ)

// ---------------- scratch (static device globals) ----------------------------
__device__ float    g_xnF[(size_t)MS*DMODEL];
__device__ float    g_scF[(size_t)BATCH*SEQ*SEQ];
__device__ float    g_yF [(size_t)MS*DMODEL];

__device__ uint32_t g_xnH[(size_t)MS*DMODEL/2],  g_xnL[(size_t)MS*DMODEL/2];
__device__ uint32_t g_hH [(size_t)MS*DMODEL/2];                      // single fp16
__device__ uint32_t g_qH [(size_t)MS*DKV/2],     g_qL [(size_t)MS*DKV/2];
__device__ uint32_t g_ktH[(size_t)BATCH*DKV*SEQ/2];                  // single fp16
__device__ uint32_t g_vH [(size_t)MS*DKV/2];                         // single fp16
__device__ uint32_t g_pH [(size_t)BATCH*SEQ*SEQ/2], g_pL[(size_t)BATCH*SEQ*SEQ/2];
__device__ uint32_t g_atH[(size_t)MS*DKV/2],     g_atL[(size_t)MS*DKV/2];
__device__ uint32_t g_acH[(size_t)MS*DFF/2];                         // single fp16

__device__ uint32_t g_wqkvH[(size_t)DMODEL*384/2];  // single fp16
__device__ float    g_bqkv[384];
__device__ uint32_t g_woH[(size_t)DKV*DMODEL/2];    // single fp16
__device__ uint32_t g_w1H[(size_t)DMODEL*DFF/2];    // single fp16
__device__ uint32_t g_w2H[(size_t)DFF*DMODEL/2];    // single fp16

// ---------------- helpers ----------------------------------------------------
__device__ __forceinline__ uint32_t smem_u32(const void* p) {
    uint32_t a;
    asm("{ .reg .u64 t; cvta.to.shared.u64 t, %1; cvt.u32.u64 %0, t; }" : "=r"(a) : "l"(p));
    return a;
}
__device__ __forceinline__ void cpasync16(uint32_t dst, const void* src) {
    asm volatile("cp.async.cg.shared.global [%0], [%1], 16;" :: "r"(dst), "l"(src));
}
#define CP_COMMIT() asm volatile("cp.async.commit_group;" ::: "memory")
#define CP_WAIT1()  asm volatile("cp.async.wait_group 1;" ::: "memory")
#define CP_WAIT2()  asm volatile("cp.async.wait_group 2;" ::: "memory")

__device__ __forceinline__ void ldm_x4(uint32_t r[4], uint32_t addr) {
    asm volatile("ldmatrix.sync.aligned.m8n8.x4.shared.b16 {%0,%1,%2,%3}, [%4];"
                 : "=r"(r[0]), "=r"(r[1]), "=r"(r[2]), "=r"(r[3]) : "r"(addr));
}
__device__ __forceinline__ void ldm_x4_t(uint32_t r[4], uint32_t addr) {
    asm volatile("ldmatrix.sync.aligned.m8n8.x4.trans.shared.b16 {%0,%1,%2,%3}, [%4];"
                 : "=r"(r[0]), "=r"(r[1]), "=r"(r[2]), "=r"(r[3]) : "r"(addr));
}
__device__ __forceinline__ void mma16816(float c[4], const uint32_t a[4], const uint32_t b[2]) {
    asm volatile("mma.sync.aligned.m16n8k16.row.col.f32.f16.f16.f32 "
                 "{%0,%1,%2,%3},{%4,%5,%6,%7},{%8,%9},{%0,%1,%2,%3};"
                 : "+f"(c[0]), "+f"(c[1]), "+f"(c[2]), "+f"(c[3])
                 : "r"(a[0]), "r"(a[1]), "r"(a[2]), "r"(a[3]), "r"(b[0]), "r"(b[1]));
}
__device__ __forceinline__ uint32_t packh(__half a, __half b) {
    return (uint32_t)__half_as_ushort(a) | ((uint32_t)__half_as_ushort(b) << 16);
}
__device__ __forceinline__ void split2(float a, float b, uint32_t& hi, uint32_t& lo) {
    __half ha = __float2half_rn(a);
    __half hb = __float2half_rn(b);
    __half la = __float2half_rn(a - __half2float(ha));
    __half lb = __float2half_rn(b - __half2float(hb));
    hi = packh(ha, hb);
    lo = packh(la, lb);
}
__device__ __forceinline__ uint32_t pack2(float a, float b) {
    return packh(__float2half_rn(a), __float2half_rn(b));
}
__device__ __forceinline__ float gelu1(float v) {
    return 0.5f * v * (1.0f + erff(v * 0.70710678118654752f));
}

// ---------------- one-shot weight conversion (all single fp16) ---------------
struct WJobs {
    const float* src[6];
    uint32_t* H[6];
    int np[6];
    int srcP[6];
    int dstP[6];
    int coff[6];
    int blkStart[7];
    const float* bq; const float* bk; const float* bv;
    float* bqkv;
};

__global__ __launch_bounds__(256) void wconv_all(WJobs jb)
{
    const int blk = blockIdx.x, tid = threadIdx.x;
    if (blk >= jb.blkStart[6]) {
        if (tid < 128) {
            jb.bqkv[tid]       = jb.bq[tid];
            jb.bqkv[128 + tid] = jb.bk[tid];
            jb.bqkv[256 + tid] = jb.bv[tid];
        }
        return;
    }
    int seg = 0;
    #pragma unroll
    for (int s = 1; s < 6; s++) if (blk >= jb.blkStart[s]) seg = s;
    int u = (blk - jb.blkStart[seg]) * 256 + tid;
    if (u >= jb.np[seg]) return;
    int k = u / jb.srcP[seg], p = u - k * jb.srcP[seg];
    float2 v = *(const float2*)(jb.src[seg] + ((size_t)u) * 2);
    jb.H[seg][(size_t)k * jb.dstP[seg] + jb.coff[seg] + p] = pack2(v.x, v.y);
}

// ---------------- LayerNorm: one row/block ------------------------------------
template<bool WF32, bool SPLIT>
__global__ __launch_bounds__(256) void ln_frag(const float* __restrict__ x,
                                               const float* __restrict__ g,
                                               const float* __restrict__ b,
                                               float* __restrict__ oF,
                                               uint32_t* __restrict__ H,
                                               uint32_t* __restrict__ L)
{
    const int row = blockIdx.x;
    const int tid = threadIdx.x;
    const float* xr = x + (size_t)row * DMODEL;
    float4 v = *(const float4*)(xr + tid * 4);

    float s  = v.x + v.y + v.z + v.w;
    float s2 = v.x*v.x + v.y*v.y + v.z*v.z + v.w*v.w;
    #pragma unroll
    for (int off = 16; off; off >>= 1) {
        s  += __shfl_xor_sync(0xffffffffu, s,  off);
        s2 += __shfl_xor_sync(0xffffffffu, s2, off);
    }
    __shared__ float ss[8], ss2[8], stats[2];
    const int wid = tid >> 5, lane = tid & 31;
    if (lane == 0) { ss[wid] = s; ss2[wid] = s2; }
    __syncthreads();
    if (wid == 0) {
        s  = (lane < 8) ? ss[lane]  : 0.f;
        s2 = (lane < 8) ? ss2[lane] : 0.f;
        #pragma unroll
        for (int off = 4; off; off >>= 1) {
            s  += __shfl_xor_sync(0xffffffffu, s,  off);
            s2 += __shfl_xor_sync(0xffffffffu, s2, off);
        }
        if (lane == 0) {
            float mean = s * (1.0f / DMODEL);
            float var  = s2 * (1.0f / DMODEL) - mean * mean;
            stats[0] = mean;
            stats[1] = rsqrtf(var + 1e-5f);
        }
    }
    __syncthreads();
    const float mean = stats[0], rstd = stats[1];
    float4 gg = *(const float4*)(g + tid * 4);
    float4 bb = *(const float4*)(b + tid * 4);
    float4 o;
    o.x = (v.x - mean) * rstd * gg.x + bb.x;
    o.y = (v.y - mean) * rstd * gg.y + bb.y;
    o.z = (v.z - mean) * rstd * gg.z + bb.z;
    o.w = (v.w - mean) * rstd * gg.w + bb.w;
    if (WF32) *(float4*)(oF + (size_t)row * DMODEL + tid * 4) = o;
    size_t base = (size_t)row * (DMODEL / 2) + tid * 2;
    if (SPLIT) {
        uint32_t h0, l0, h1, l1;
        split2(o.x, o.y, h0, l0);
        split2(o.z, o.w, h1, l1);
        H[base] = h0; H[base + 1] = h1;
        L[base] = l0; L[base + 1] = l1;
    } else {
        H[base]     = pack2(o.x, o.y);
        H[base + 1] = pack2(o.z, o.w);
    }
}

// ---------------- softmax: one row/block, emits probs split fp16 pairs --------
__global__ __launch_bounds__(256) void softmax_frag(const float* __restrict__ S,
                                                    uint32_t* __restrict__ H,
                                                    uint32_t* __restrict__ L)
{
    const size_t row = blockIdx.x;
    const float* p = S + row * (size_t)SEQ;
    const int tid = threadIdx.x;
    float4 a = *(const float4*)(p + tid * 4);
    float4 c = *(const float4*)(p + 1024 + tid * 4);

    float m = fmaxf(fmaxf(fmaxf(a.x, a.y), fmaxf(a.z, a.w)),
                    fmaxf(fmaxf(c.x, c.y), fmaxf(c.z, c.w)));
    #pragma unroll
    for (int off = 16; off; off >>= 1)
        m = fmaxf(m, __shfl_xor_sync(0xffffffffu, m, off));
    __shared__ float sm[8], sred[2];
    const int wid = tid >> 5, lane = tid & 31;
    if (lane == 0) sm[wid] = m;
    __syncthreads();
    if (wid == 0) {
        m = (lane < 8) ? sm[lane] : -1e30f;
        #pragma unroll
        for (int off = 4; off; off >>= 1)
            m = fmaxf(m, __shfl_xor_sync(0xffffffffu, m, off));
        if (lane == 0) sred[0] = m;
    }
    __syncthreads();
    m = sred[0];

    a.x = expf(a.x - m); a.y = expf(a.y - m); a.z = expf(a.z - m); a.w = expf(a.w - m);
    c.x = expf(c.x - m); c.y = expf(c.y - m); c.z = expf(c.z - m); c.w = expf(c.w - m);
    float s = a.x + a.y + a.z + a.w + c.x + c.y + c.z + c.w;
    #pragma unroll
    for (int off = 16; off; off >>= 1)
        s += __shfl_xor_sync(0xffffffffu, s, off);
    if (lane == 0) sm[wid] = s;
    __syncthreads();
    if (wid == 0) {
        s = (lane < 8) ? sm[lane] : 0.f;
        #pragma unroll
        for (int off = 4; off; off >>= 1)
            s += __shfl_xor_sync(0xffffffffu, s, off);
        if (lane == 0) sred[1] = 1.0f / s;
    }
    __syncthreads();
    const float r = sred[1];
    a.x *= r; a.y *= r; a.z *= r; a.w *= r;
    c.x *= r; c.y *= r; c.z *= r; c.w *= r;

    uint32_t h, l;
    size_t base = row * (SEQ / 2) + tid * 2;
    split2(a.x, a.y, h, l); H[base] = h;       L[base] = l;
    split2(a.z, a.w, h, l); H[base + 1] = h;   L[base + 1] = l;
    base += 512;
    split2(c.x, c.y, h, l); H[base] = h;       L[base] = l;
    split2(c.z, c.w, h, l); H[base + 1] = h;   L[base + 1] = l;
}

#define EM_F32 0
#define EM_SP  1
#define EM_QKV 3
#define EM_HF  4

// ================= 2-pass GEMM, BN=128, BK=64, 4-stage (A split, B single) ===
template<int EMIT, int EPI>
__global__ __launch_bounds__(256, 1)
void hg2p(const uint32_t* __restrict__ Ah, const uint32_t* __restrict__ Al,
          const uint32_t* __restrict__ Bh,
          const float* __restrict__ bias, const float* __restrict__ res,
          float* __restrict__ outF, uint32_t* __restrict__ outH, uint32_t* __restrict__ outL,
          uint32_t* __restrict__ outH2, uint32_t* __restrict__ outH3,
          int Ka, int Nb, int nc,
          long long sAu, long long sBu, long long sCf, long long sOu,
          float alpha)
{
    extern __shared__ char smc[];
    const uint32_t sb = smem_u32(smc);
    const int tid = threadIdx.x, wid = tid >> 5, lane = tid & 31;
    const int wm = wid >> 2, wn = wid & 3;
    const int bx = blockIdx.x, by = blockIdx.y, bz = blockIdx.z;

    const uint32_t Ka2 = (uint32_t)Ka >> 1, Nb2 = (uint32_t)Nb >> 1;
    const uint32_t* Ahb = Ah + (size_t)bz * sAu;
    const uint32_t* Alb = Al + (size_t)bz * sAu;
    const uint32_t* Bhb = Bh + (size_t)bz * sBu;

    // stage 48KB: Ahi@0 16K | Alo@16K | B@32K 16K. 4 stages.
    auto load_stage = [&](int st, int c) {
        const uint32_t stb = sb + st * 49152;
        #pragma unroll
        for (int t = 0; t < 4; t++) {
            int id = tid + t * 256;
            int m = id >> 3, ch = id & 7;
            size_t go = (size_t)(by * 128 + m) * Ka2 + (size_t)c * 32 + ch * 4;
            uint32_t sa = stb + m * 128 + ((ch ^ (m & 7)) << 4);
            cpasync16(sa, Ahb + go);
            cpasync16(sa + 16384, Alb + go);
        }
        #pragma unroll
        for (int t = 0; t < 4; t++) {
            int id = tid + t * 256;
            int k = id >> 4, ch = id & 15;
            size_t go = (size_t)(c * 64 + k) * Nb2 + (size_t)bx * 64 + ch * 4;
            cpasync16(stb + 32768 + k * 256 + ((ch ^ (k & 15)) << 4), Bhb + go);
        }
    };

    float acc[4][4][4];
    #pragma unroll
    for (int i = 0; i < 4; i++)
        #pragma unroll
        for (int j = 0; j < 4; j++)
            #pragma unroll
            for (int r = 0; r < 4; r++) acc[i][j][r] = 0.f;

    load_stage(0, 0); CP_COMMIT();
    load_stage(1, 1); CP_COMMIT();
    load_stage(2, 2); CP_COMMIT();

    const int q = lane >> 3, l7 = lane & 7;

    for (int c = 0; c < nc; ++c) {
        CP_WAIT2();
        __syncthreads();
        if (c + 3 < nc) load_stage((c + 3) & 3, c + 3);
        CP_COMMIT();

        const uint32_t stb = sb + (c & 3) * 49152;
        #pragma unroll
        for (int ks = 0; ks < 4; ks++) {
            uint32_t aH[4][4], aL[4][4], bH4[2][4];
            #pragma unroll
            for (int i = 0; i < 4; i++) {
                int m = wm * 64 + i * 16 + ((q & 1) << 3) + l7;
                int ch = 2 * ks + (q >> 1);
                uint32_t ad = stb + m * 128 + ((ch ^ (m & 7)) << 4);
                ldm_x4(aH[i], ad);
                ldm_x4(aL[i], ad + 16384);
            }
            #pragma unroll
            for (int g = 0; g < 2; g++) {
                int k = ks * 16 + ((q & 1) << 3) + l7;
                int ch = wn * 4 + g * 2 + (q >> 1);
                ldm_x4_t(bH4[g], stb + 32768 + k * 256 + ((ch ^ (k & 15)) << 4));
            }
            #pragma unroll
            for (int i = 0; i < 4; i++)
                #pragma unroll
                for (int j = 0; j < 4; j++) {
                    const uint32_t* bh = &bH4[j >> 1][(j & 1) * 2];
                    mma16816(acc[i][j], aH[i], bh);
                    mma16816(acc[i][j], aL[i], bh);
                }
        }
    }

    __syncthreads();
    float* Cs = (float*)smc;
    #pragma unroll
    for (int i = 0; i < 4; i++)
        #pragma unroll
        for (int j = 0; j < 4; j++) {
            int r0 = wm * 64 + i * 16 + (lane >> 2);
            int c0 = wn * 32 + j * 8 + 2 * (lane & 3);
            *(float2*)(Cs + r0 * 132 + c0)       = make_float2(acc[i][j][0], acc[i][j][1]);
            *(float2*)(Cs + (r0 + 8) * 132 + c0) = make_float2(acc[i][j][2], acc[i][j][3]);
        }
    __syncthreads();

    if (EMIT == EM_SP) {
        #pragma unroll
        for (int i = 0; i < 32; i++) {
            int u = tid + 256 * i;
            int row = u >> 6, np = u & 63;
            float v0 = Cs[row * 132 + 2 * np]     * alpha;
            float v1 = Cs[row * 132 + 2 * np + 1] * alpha;
            int gc = bx * 128 + 2 * np;
            if (EPI & 1) { v0 += __ldg(bias + gc); v1 += __ldg(bias + gc + 1); }
            if (EPI & 2) { v0 = gelu1(v0); v1 = gelu1(v1); }
            uint32_t h, l;
            split2(v0, v1, h, l);
            size_t gm = (size_t)by * 128 + row;
            size_t idx = (size_t)bz * sOu + gm * (Nb >> 1) + (size_t)bx * 64 + np;
            outH[idx] = h; outL[idx] = l;
        }
    } else { // EM_QKV: bx=0 q split, bx=1 kT single transposed, bx=2 v single
        if (bx == 1) {
            const int b = by >> 4;
            const int s0p = (by & 15) * 64;
            #pragma unroll
            for (int i = 0; i < 32; i++) {
                int u = tid + 256 * i;
                int d = u >> 6, sp = u & 63;
                float bb = __ldg(bias + 128 + d);
                float v0 = Cs[(2 * sp) * 132 + d]     + bb;
                float v1 = Cs[(2 * sp + 1) * 132 + d] + bb;
                size_t idx = (size_t)b * (DKV * SEQ / 2) + (size_t)d * (SEQ / 2) + s0p + sp;
                outH2[idx] = pack2(v0, v1);
            }
        } else if (bx == 0) {
            #pragma unroll
            for (int i = 0; i < 32; i++) {
                int u = tid + 256 * i;
                int row = u >> 6, np = u & 63;
                float v0 = Cs[row * 132 + 2 * np]     + __ldg(bias + 2 * np);
                float v1 = Cs[row * 132 + 2 * np + 1] + __ldg(bias + 2 * np + 1);
                uint32_t h, l;
                split2(v0, v1, h, l);
                size_t idx = ((size_t)by * 128 + row) * 64 + np;
                outH[idx] = h; outL[idx] = l;
            }
        } else {
            #pragma unroll
            for (int i = 0; i < 32; i++) {
                int u = tid + 256 * i;
                int row = u >> 6, np = u & 63;
                float v0 = Cs[row * 132 + 2 * np]     + __ldg(bias + 256 + 2 * np);
                float v1 = Cs[row * 132 + 2 * np + 1] + __ldg(bias + 256 + 2 * np + 1);
                size_t idx = ((size_t)by * 128 + row) * 64 + np;
                outH3[idx] = pack2(v0, v1);
            }
        }
    }
}

// ================= 2-pass GEMM, BN=256, BK=64, 3-stage (A split, B single) ===
template<int EPI>
__global__ __launch_bounds__(256, 1)
void hg2p256(const uint32_t* __restrict__ Ah, const uint32_t* __restrict__ Al,
             const uint32_t* __restrict__ Bh,
             const float* __restrict__ bias, const float* __restrict__ res,
             float* __restrict__ outF,
             int Ka, int Nb, int nc,
             long long sAu, long long sBu, long long sCf,
             float alpha)
{
    extern __shared__ char smc[];
    const uint32_t sb = smem_u32(smc);
    const int tid = threadIdx.x, wid = tid >> 5, lane = tid & 31;
    const int wm = wid >> 2, wn = wid & 3;
    const int bx = blockIdx.x, by = blockIdx.y, bz = blockIdx.z;

    const uint32_t Ka2 = (uint32_t)Ka >> 1, Nb2 = (uint32_t)Nb >> 1;
    const uint32_t* Ahb = Ah + (size_t)bz * sAu;
    const uint32_t* Alb = Al + (size_t)bz * sAu;
    const uint32_t* Bhb = Bh + (size_t)bz * sBu;

    // stage 64KB: Ahi@0 | Alo@16K | B@32K 32K.  3 stages.
    auto load_stage = [&](int st, int c) {
        const uint32_t stb = sb + st * 65536;
        #pragma unroll
        for (int t = 0; t < 4; t++) {
            int id = tid + t * 256;
            int m = id >> 3, ch = id & 7;
            size_t go = (size_t)(by * 128 + m) * Ka2 + (size_t)c * 32 + ch * 4;
            uint32_t sa = stb + m * 128 + ((ch ^ (m & 7)) << 4);
            cpasync16(sa, Ahb + go);
            cpasync16(sa + 16384, Alb + go);
        }
        #pragma unroll
        for (int t = 0; t < 8; t++) {
            int id = tid + t * 256;
            int k = id >> 5, ch = id & 31;
            size_t go = (size_t)(c * 64 + k) * Nb2 + (size_t)bx * 128 + ch * 4;
            cpasync16(stb + 32768 + k * 512 + ((ch ^ (k & 15)) << 4), Bhb + go);
        }
    };

    float acc[4][8][4];
    #pragma unroll
    for (int i = 0; i < 4; i++)
        #pragma unroll
        for (int j = 0; j < 8; j++)
            #pragma unroll
            for (int r = 0; r < 4; r++) acc[i][j][r] = 0.f;

    load_stage(0, 0); CP_COMMIT();
    load_stage(1, 1); CP_COMMIT();

    const int q = lane >> 3, l7 = lane & 7;

    for (int c = 0; c < nc; ++c) {
        CP_WAIT1();
        __syncthreads();
        if (c + 2 < nc) load_stage((c + 2) % 3, c + 2);
        CP_COMMIT();

        const uint32_t stb = sb + (c % 3) * 65536;
        #pragma unroll
        for (int ks = 0; ks < 4; ks++) {
            uint32_t aH[4][4], aL[4][4];
            #pragma unroll
            for (int i = 0; i < 4; i++) {
                int m = wm * 64 + i * 16 + ((q & 1) << 3) + l7;
                int ch = 2 * ks + (q >> 1);
                uint32_t ad = stb + m * 128 + ((ch ^ (m & 7)) << 4);
                ldm_x4(aH[i], ad);
                ldm_x4(aL[i], ad + 16384);
            }
            #pragma unroll
            for (int g = 0; g < 4; g++) {
                uint32_t bH4[4];
                int k = ks * 16 + ((q & 1) << 3) + l7;
                int ch = wn * 8 + g * 2 + (q >> 1);
                ldm_x4_t(bH4, stb + 32768 + k * 512 + ((ch ^ (k & 15)) << 4));
                #pragma unroll
                for (int i = 0; i < 4; i++) {
                    #pragma unroll
                    for (int jj = 0; jj < 2; jj++) {
                        const uint32_t* bh = &bH4[jj * 2];
                        float* a4 = acc[i][g * 2 + jj];
                        mma16816(a4, aH[i], bh);
                        mma16816(a4, aL[i], bh);
                    }
                }
            }
        }
    }

    __syncthreads();
    float* Cs = (float*)smc;
    #pragma unroll
    for (int i = 0; i < 4; i++)
        #pragma unroll
        for (int j = 0; j < 8; j++) {
            int r0 = wm * 64 + i * 16 + (lane >> 2);
            int c0 = wn * 64 + j * 8 + 2 * (lane & 3);
            *(float2*)(Cs + r0 * 260 + c0)       = make_float2(acc[i][j][0], acc[i][j][1]);
            *(float2*)(Cs + (r0 + 8) * 260 + c0) = make_float2(acc[i][j][2], acc[i][j][3]);
        }
    __syncthreads();

    #pragma unroll
    for (int i = 0; i < 32; i++) {
        int u = tid + 256 * i;
        int row = u >> 6, c4 = (u & 63) * 4;
        float4 v = *(float4*)(Cs + row * 260 + c4);
        v.x *= alpha; v.y *= alpha; v.z *= alpha; v.w *= alpha;
        int gc = bx * 256 + c4;
        size_t gm = (size_t)by * 128 + row;
        if (EPI & 1) {
            float4 bb = *(const float4*)(bias + gc);
            v.x += bb.x; v.y += bb.y; v.z += bb.z; v.w += bb.w;
        }
        if (EPI & 2) { v.x = gelu1(v.x); v.y = gelu1(v.y); v.z = gelu1(v.z); v.w = gelu1(v.w); }
        if (EPI & 4) {
            float4 rr = *(const float4*)(res + gm * Nb + gc);
            v.x += rr.x; v.y += rr.y; v.z += rr.z; v.w += rr.w;
        }
        *(float4*)(outF + (size_t)bz * sCf + gm * Nb + gc) = v;
    }
}

// ================= 1-pass GEMM, BN=128, BK=64, 3-stage, 2 CTAs/SM ============
template<int EMIT, int EPI>
__global__ __launch_bounds__(256, 2)
void hg1p128(const uint32_t* __restrict__ Ah, const uint32_t* __restrict__ Bh,
             const float* __restrict__ bias, const float* __restrict__ res,
             float* __restrict__ outF, uint32_t* __restrict__ outH,
             int Ka, int Nb, int nc, float alpha)
{
    extern __shared__ char smc[];
    const uint32_t sb = smem_u32(smc);
    const int tid = threadIdx.x, wid = tid >> 5, lane = tid & 31;
    const int wm = wid >> 2, wn = wid & 3;
    const int bx = blockIdx.x, by = blockIdx.y;

    const uint32_t Ka2 = (uint32_t)Ka >> 1, Nb2 = (uint32_t)Nb >> 1;

    // stage 32KB: A@0 16K | B@16K 16K. 3 stages = 96KB.
    auto load_stage = [&](int st, int c) {
        const uint32_t stb = sb + st * 32768;
        #pragma unroll
        for (int t = 0; t < 4; t++) {
            int id = tid + t * 256;
            int m = id >> 3, ch = id & 7;
            size_t go = (size_t)(by * 128 + m) * Ka2 + (size_t)c * 32 + ch * 4;
            cpasync16(stb + m * 128 + ((ch ^ (m & 7)) << 4), Ah + go);
        }
        #pragma unroll
        for (int t = 0; t < 4; t++) {
            int id = tid + t * 256;
            int k = id >> 4, ch = id & 15;
            size_t go = (size_t)(c * 64 + k) * Nb2 + (size_t)bx * 64 + ch * 4;
            cpasync16(stb + 16384 + k * 256 + ((ch ^ (k & 15)) << 4), Bh + go);
        }
    };

    float acc[4][4][4];
    #pragma unroll
    for (int i = 0; i < 4; i++)
        #pragma unroll
        for (int j = 0; j < 4; j++)
            #pragma unroll
            for (int r = 0; r < 4; r++) acc[i][j][r] = 0.f;

    load_stage(0, 0); CP_COMMIT();
    load_stage(1, 1); CP_COMMIT();

    const int q = lane >> 3, l7 = lane & 7;

    for (int c = 0; c < nc; ++c) {
        CP_WAIT1();
        __syncthreads();
        if (c + 2 < nc) load_stage((c + 2) % 3, c + 2);
        CP_COMMIT();

        const uint32_t stb = sb + (c % 3) * 32768;
        #pragma unroll
        for (int ks = 0; ks < 4; ks++) {
            uint32_t aH[4][4], bH4[2][4];
            #pragma unroll
            for (int i = 0; i < 4; i++) {
                int m = wm * 64 + i * 16 + ((q & 1) << 3) + l7;
                int ch = 2 * ks + (q >> 1);
                ldm_x4(aH[i], stb + m * 128 + ((ch ^ (m & 7)) << 4));
            }
            #pragma unroll
            for (int g = 0; g < 2; g++) {
                int k = ks * 16 + ((q & 1) << 3) + l7;
                int ch = wn * 4 + g * 2 + (q >> 1);
                ldm_x4_t(bH4[g], stb + 16384 + k * 256 + ((ch ^ (k & 15)) << 4));
            }
            #pragma unroll
            for (int i = 0; i < 4; i++)
                #pragma unroll
                for (int j = 0; j < 4; j++)
                    mma16816(acc[i][j], aH[i], &bH4[j >> 1][(j & 1) * 2]);
        }
    }

    __syncthreads();
    float* Cs = (float*)smc;
    #pragma unroll
    for (int i = 0; i < 4; i++)
        #pragma unroll
        for (int j = 0; j < 4; j++) {
            int r0 = wm * 64 + i * 16 + (lane >> 2);
            int c0 = wn * 32 + j * 8 + 2 * (lane & 3);
            *(float2*)(Cs + r0 * 132 + c0)       = make_float2(acc[i][j][0], acc[i][j][1]);
            *(float2*)(Cs + (r0 + 8) * 132 + c0) = make_float2(acc[i][j][2], acc[i][j][3]);
        }
    __syncthreads();

    if (EMIT == EM_F32) {
        #pragma unroll
        for (int i = 0; i < 16; i++) {
            int u = tid + 256 * i;
            int row = u >> 5, c4 = (u & 31) * 4;
            float4 v = *(float4*)(Cs + row * 132 + c4);
            v.x *= alpha; v.y *= alpha; v.z *= alpha; v.w *= alpha;
            int gc = bx * 128 + c4;
            size_t gm = (size_t)by * 128 + row;
            if (EPI & 1) {
                float4 bb = *(const float4*)(bias + gc);
                v.x += bb.x; v.y += bb.y; v.z += bb.z; v.w += bb.w;
            }
            if (EPI & 2) { v.x = gelu1(v.x); v.y = gelu1(v.y); v.z = gelu1(v.z); v.w = gelu1(v.w); }
            if (EPI & 4) {
                float4 rr = *(const float4*)(res + gm * Nb + gc);
                v.x += rr.x; v.y += rr.y; v.z += rr.z; v.w += rr.w;
            }
            *(float4*)(outF + gm * Nb + gc) = v;
        }
    } else { // EM_HF single pairs
        #pragma unroll
        for (int i = 0; i < 32; i++) {
            int u = tid + 256 * i;
            int row = u >> 6, np = u & 63;
            float v0 = Cs[row * 132 + 2 * np]     * alpha;
            float v1 = Cs[row * 132 + 2 * np + 1] * alpha;
            int gc = bx * 128 + 2 * np;
            if (EPI & 1) { v0 += __ldg(bias + gc); v1 += __ldg(bias + gc + 1); }
            if (EPI & 2) { v0 = gelu1(v0); v1 = gelu1(v1); }
            size_t gm = (size_t)by * 128 + row;
            outH[gm * (Nb >> 1) + (size_t)bx * 64 + np] = pack2(v0, v1);
        }
    }
}

// ---------------- launch sequence -------------------------------------------
extern "C" void kernel_launch(void* const* d_in, const int* in_sizes, int n_in,
                              void* d_out, int out_size)
{
    const float* x     = (const float*)d_in[0];
    const float* ln1_g = (const float*)d_in[1];
    const float* ln1_b = (const float*)d_in[2];
    const float* Wq    = (const float*)d_in[3];
    const float* bq    = (const float*)d_in[4];
    const float* Wk    = (const float*)d_in[5];
    const float* bk    = (const float*)d_in[6];
    const float* Wv    = (const float*)d_in[7];
    const float* bv    = (const float*)d_in[8];
    const float* Wo    = (const float*)d_in[9];
    const float* bo    = (const float*)d_in[10];
    const float* ln2_g = (const float*)d_in[11];
    const float* ln2_b = (const float*)d_in[12];
    const float* W1    = (const float*)d_in[13];
    const float* b1    = (const float*)d_in[14];
    const float* W2    = (const float*)d_in[15];
    const float* b2    = (const float*)d_in[16];
    float* out = (float*)d_out;

    float *xnF, *scF, *yF, *bqkv;
    uint32_t *xnH,*xnL,*hH,*qH,*qL,*ktH,*vH,*pH,*pL,*atH,*atL,*acH;
    uint32_t *wqkvH,*woH,*w1H,*w2H;
    cudaGetSymbolAddress((void**)&xnF, g_xnF); cudaGetSymbolAddress((void**)&scF, g_scF);
    cudaGetSymbolAddress((void**)&yF,  g_yF);  cudaGetSymbolAddress((void**)&bqkv, g_bqkv);
    cudaGetSymbolAddress((void**)&xnH, g_xnH); cudaGetSymbolAddress((void**)&xnL, g_xnL);
    cudaGetSymbolAddress((void**)&hH,  g_hH);
    cudaGetSymbolAddress((void**)&qH,  g_qH);  cudaGetSymbolAddress((void**)&qL,  g_qL);
    cudaGetSymbolAddress((void**)&ktH, g_ktH);
    cudaGetSymbolAddress((void**)&vH,  g_vH);
    cudaGetSymbolAddress((void**)&pH,  g_pH);  cudaGetSymbolAddress((void**)&pL,  g_pL);
    cudaGetSymbolAddress((void**)&atH, g_atH); cudaGetSymbolAddress((void**)&atL, g_atL);
    cudaGetSymbolAddress((void**)&acH, g_acH);
    cudaGetSymbolAddress((void**)&wqkvH, g_wqkvH);
    cudaGetSymbolAddress((void**)&woH, g_woH);
    cudaGetSymbolAddress((void**)&w1H, g_w1H);
    cudaGetSymbolAddress((void**)&w2H, g_w2H);

    const int SM_2P   = 4 * 49152;   // 192 KB
    const int SM_2P256= 3 * 65536;   // 192 KB
    const int SM_1P   = 3 * 32768;   // 96 KB (2 CTAs/SM)
    cudaFuncSetAttribute(hg2p<EM_QKV,1>, cudaFuncAttributeMaxDynamicSharedMemorySize, SM_2P);
    cudaFuncSetAttribute(hg2p<EM_SP, 0>, cudaFuncAttributeMaxDynamicSharedMemorySize, SM_2P);
    cudaFuncSetAttribute(hg2p256<0>,     cudaFuncAttributeMaxDynamicSharedMemorySize, SM_2P256);
    cudaFuncSetAttribute(hg2p256<5>,     cudaFuncAttributeMaxDynamicSharedMemorySize, SM_2P256);
    cudaFuncSetAttribute(hg1p128<EM_HF, 3>, cudaFuncAttributeMaxDynamicSharedMemorySize, SM_1P);
    cudaFuncSetAttribute(hg1p128<EM_F32,5>, cudaFuncAttributeMaxDynamicSharedMemorySize, SM_1P);

    const float scale = 0.08838834764831845f; // 1/sqrt(128)

    // ---- 1 launch: all weight conversions (single fp16) + qkv bias pack ----
    {
        WJobs jb;
        jb.src[0] = Wq; jb.H[0] = wqkvH; jb.np[0] = DMODEL*DKV/2; jb.srcP[0] = 64;  jb.dstP[0] = 192; jb.coff[0] = 0;
        jb.src[1] = Wk; jb.H[1] = wqkvH; jb.np[1] = DMODEL*DKV/2; jb.srcP[1] = 64;  jb.dstP[1] = 192; jb.coff[1] = 64;
        jb.src[2] = Wv; jb.H[2] = wqkvH; jb.np[2] = DMODEL*DKV/2; jb.srcP[2] = 64;  jb.dstP[2] = 192; jb.coff[2] = 128;
        jb.src[3] = Wo; jb.H[3] = woH;   jb.np[3] = DKV*DMODEL/2; jb.srcP[3] = 512; jb.dstP[3] = 512; jb.coff[3] = 0;
        jb.src[4] = W1; jb.H[4] = w1H;   jb.np[4] = DMODEL*DFF/2; jb.srcP[4] = 2048;jb.dstP[4] = 2048;jb.coff[4] = 0;
        jb.src[5] = W2; jb.H[5] = w2H;   jb.np[5] = DFF*DMODEL/2; jb.srcP[5] = 512; jb.dstP[5] = 512; jb.coff[5] = 0;
        int acc_ = 0;
        for (int s = 0; s < 6; s++) { jb.blkStart[s] = acc_; acc_ += (jb.np[s] + 255) / 256; }
        jb.blkStart[6] = acc_;
        jb.bq = bq; jb.bk = bk; jb.bv = bv; jb.bqkv = bqkv;
        wconv_all<<<acc_ + 1, 256>>>(jb);
    }

    // 2) ln1 -> xn (f32 + split pairs)
    ln_frag<true, true><<<MS, 256>>>(x, ln1_g, ln1_b, xnF, xnH, xnL);

    // 3) fused QKV (16384 x 384 x 1024) [2-pass]: bx=0 q(split), 1 kT, 2 v
    hg2p<EM_QKV, 1><<<dim3(3,128,1), 256, SM_2P>>>(xnH, xnL, wqkvH, bqkv, nullptr,
        nullptr, qH, qL, ktH, vH, DMODEL, 384, 16, 0, 0, 0, 0, 1.f);

    // 4) scores = q @ kT * scale (per batch 2048x2048x128) [2-pass]
    hg2p256<0><<<dim3(8,16,8), 256, SM_2P256>>>(qH, qL, ktH, nullptr, nullptr,
        scF, DKV, SEQ, 2,
        (long long)SEQ*DKV/2, (long long)DKV*SEQ/2, (long long)SEQ*SEQ, scale);

    // 5) softmax -> probs split pairs
    softmax_frag<<<BATCH*SEQ, 256>>>(scF, pH, pL);

    // 6) att = probs @ v (per batch 2048x128x2048) [2-pass] -> at split pairs
    hg2p<EM_SP, 0><<<dim3(1,16,8), 256, SM_2P>>>(pH, pL, vH, nullptr, nullptr,
        nullptr, atH, atL, nullptr, nullptr, SEQ, DKV, 32,
        (long long)SEQ*SEQ/2, (long long)SEQ*DKV/2, 0, (long long)SEQ*DKV/2, 1.f);

    // 7) y = xn + att@Wo + bo (16384x1024x128) [2-pass]
    hg2p256<5><<<dim3(4,128,1), 256, SM_2P256>>>(atH, atL, woH, bo, xnF,
        yF, DKV, DMODEL, 2, 0, 0, 0, 1.f);

    // 8) ln2 -> h single pairs
    ln_frag<false, false><<<MS, 256>>>(yF, ln2_g, ln2_b, nullptr, hH, nullptr);

    // 9) act = gelu(h@W1 + b1) (16384x4096x1024) [1-pass, 2 CTA/SM]
    hg1p128<EM_HF, 3><<<dim3(32,128,1), 256, SM_1P>>>(hH, w1H, b1, nullptr,
        nullptr, acH, DMODEL, DFF, 16, 1.f);

    // 10) out = y + act@W2 + b2 (16384x1024x4096) [1-pass, 2 CTA/SM]
    hg1p128<EM_F32, 5><<<dim3(8,128,1), 256, SM_1P>>>(acH, w2H, b2, yF,
        out, nullptr, DFF, DMODEL, 64, 1.f);
}

// round 9
// speedup vs baseline: 6.7269x; 1.0895x over previous
#include <cuda_runtime.h>
#include <cuda_fp16.h>
#include <math.h>
#include <stdint.h>

#define BATCH 8
#define SEQ   2048
#define DMODEL 1024
#define DKV   128
#define DFF   4096
#define MS    (BATCH*SEQ)

// ---------------- scratch (static device globals) ----------------------------
__device__ float    g_xnF[(size_t)MS*DMODEL];
__device__ float    g_yF [(size_t)MS*DMODEL];

__device__ uint32_t g_xnH[(size_t)MS*DMODEL/2],  g_xnL[(size_t)MS*DMODEL/2];
__device__ uint32_t g_hH [(size_t)MS*DMODEL/2];                      // single fp16
__device__ uint32_t g_qH [(size_t)MS*DKV/2],     g_qL [(size_t)MS*DKV/2];
__device__ uint32_t g_ktH[(size_t)BATCH*DKV*SEQ/2];                  // single fp16
__device__ uint32_t g_vH [(size_t)MS*DKV/2];                         // single fp16
__device__ uint32_t g_atH[(size_t)MS*DKV/2],     g_atL[(size_t)MS*DKV/2];
__device__ uint32_t g_acH[(size_t)MS*DFF/2];                         // single fp16

__device__ uint32_t g_wqkvH[(size_t)DMODEL*384/2];  // single fp16
__device__ float    g_bqkv[384];
__device__ uint32_t g_woH[(size_t)DKV*DMODEL/2];    // single fp16
__device__ uint32_t g_w1H[(size_t)DMODEL*DFF/2];    // single fp16
__device__ uint32_t g_w2H[(size_t)DFF*DMODEL/2];    // single fp16

// ---------------- helpers ----------------------------------------------------
__device__ __forceinline__ uint32_t smem_u32(const void* p) {
    uint32_t a;
    asm("{ .reg .u64 t; cvta.to.shared.u64 t, %1; cvt.u32.u64 %0, t; }" : "=r"(a) : "l"(p));
    return a;
}
__device__ __forceinline__ void cpasync16(uint32_t dst, const void* src) {
    asm volatile("cp.async.cg.shared.global [%0], [%1], 16;" :: "r"(dst), "l"(src));
}
#define CP_COMMIT() asm volatile("cp.async.commit_group;" ::: "memory")
#define CP_WAIT1()  asm volatile("cp.async.wait_group 1;" ::: "memory")
#define CP_WAIT2()  asm volatile("cp.async.wait_group 2;" ::: "memory")

__device__ __forceinline__ void ldm_x4(uint32_t r[4], uint32_t addr) {
    asm volatile("ldmatrix.sync.aligned.m8n8.x4.shared.b16 {%0,%1,%2,%3}, [%4];"
                 : "=r"(r[0]), "=r"(r[1]), "=r"(r[2]), "=r"(r[3]) : "r"(addr));
}
__device__ __forceinline__ void ldm_x4_t(uint32_t r[4], uint32_t addr) {
    asm volatile("ldmatrix.sync.aligned.m8n8.x4.trans.shared.b16 {%0,%1,%2,%3}, [%4];"
                 : "=r"(r[0]), "=r"(r[1]), "=r"(r[2]), "=r"(r[3]) : "r"(addr));
}
__device__ __forceinline__ void mma16816(float c[4], const uint32_t a[4], const uint32_t b[2]) {
    asm volatile("mma.sync.aligned.m16n8k16.row.col.f32.f16.f16.f32 "
                 "{%0,%1,%2,%3},{%4,%5,%6,%7},{%8,%9},{%0,%1,%2,%3};"
                 : "+f"(c[0]), "+f"(c[1]), "+f"(c[2]), "+f"(c[3])
                 : "r"(a[0]), "r"(a[1]), "r"(a[2]), "r"(a[3]), "r"(b[0]), "r"(b[1]));
}
__device__ __forceinline__ uint32_t packh(__half a, __half b) {
    return (uint32_t)__half_as_ushort(a) | ((uint32_t)__half_as_ushort(b) << 16);
}
__device__ __forceinline__ void split2(float a, float b, uint32_t& hi, uint32_t& lo) {
    __half ha = __float2half_rn(a);
    __half hb = __float2half_rn(b);
    __half la = __float2half_rn(a - __half2float(ha));
    __half lb = __float2half_rn(b - __half2float(hb));
    hi = packh(ha, hb);
    lo = packh(la, lb);
}
__device__ __forceinline__ uint32_t pack2(float a, float b) {
    return packh(__float2half_rn(a), __float2half_rn(b));
}
__device__ __forceinline__ float gelu1(float v) {
    return 0.5f * v * (1.0f + erff(v * 0.70710678118654752f));
}

// ---------------- one-shot weight conversion (all single fp16) ---------------
struct WJobs {
    const float* src[6];
    uint32_t* H[6];
    int np[6];
    int srcP[6];
    int dstP[6];
    int coff[6];
    int blkStart[7];
    const float* bq; const float* bk; const float* bv;
    float* bqkv;
};

__global__ __launch_bounds__(256) void wconv_all(WJobs jb)
{
    const int blk = blockIdx.x, tid = threadIdx.x;
    if (blk >= jb.blkStart[6]) {
        if (tid < 128) {
            jb.bqkv[tid]       = jb.bq[tid];
            jb.bqkv[128 + tid] = jb.bk[tid];
            jb.bqkv[256 + tid] = jb.bv[tid];
        }
        return;
    }
    int seg = 0;
    #pragma unroll
    for (int s = 1; s < 6; s++) if (blk >= jb.blkStart[s]) seg = s;
    int u = (blk - jb.blkStart[seg]) * 256 + tid;
    if (u >= jb.np[seg]) return;
    int k = u / jb.srcP[seg], p = u - k * jb.srcP[seg];
    float2 v = *(const float2*)(jb.src[seg] + ((size_t)u) * 2);
    jb.H[seg][(size_t)k * jb.dstP[seg] + jb.coff[seg] + p] = pack2(v.x, v.y);
}

// ---------------- LayerNorm: one row/block ------------------------------------
template<bool WF32, bool SPLIT>
__global__ __launch_bounds__(256) void ln_frag(const float* __restrict__ x,
                                               const float* __restrict__ g,
                                               const float* __restrict__ b,
                                               float* __restrict__ oF,
                                               uint32_t* __restrict__ H,
                                               uint32_t* __restrict__ L)
{
    const int row = blockIdx.x;
    const int tid = threadIdx.x;
    const float* xr = x + (size_t)row * DMODEL;
    float4 v = *(const float4*)(xr + tid * 4);

    float s  = v.x + v.y + v.z + v.w;
    float s2 = v.x*v.x + v.y*v.y + v.z*v.z + v.w*v.w;
    #pragma unroll
    for (int off = 16; off; off >>= 1) {
        s  += __shfl_xor_sync(0xffffffffu, s,  off);
        s2 += __shfl_xor_sync(0xffffffffu, s2, off);
    }
    __shared__ float ss[8], ss2[8], stats[2];
    const int wid = tid >> 5, lane = tid & 31;
    if (lane == 0) { ss[wid] = s; ss2[wid] = s2; }
    __syncthreads();
    if (wid == 0) {
        s  = (lane < 8) ? ss[lane]  : 0.f;
        s2 = (lane < 8) ? ss2[lane] : 0.f;
        #pragma unroll
        for (int off = 4; off; off >>= 1) {
            s  += __shfl_xor_sync(0xffffffffu, s,  off);
            s2 += __shfl_xor_sync(0xffffffffu, s2, off);
        }
        if (lane == 0) {
            float mean = s * (1.0f / DMODEL);
            float var  = s2 * (1.0f / DMODEL) - mean * mean;
            stats[0] = mean;
            stats[1] = rsqrtf(var + 1e-5f);
        }
    }
    __syncthreads();
    const float mean = stats[0], rstd = stats[1];
    float4 gg = *(const float4*)(g + tid * 4);
    float4 bb = *(const float4*)(b + tid * 4);
    float4 o;
    o.x = (v.x - mean) * rstd * gg.x + bb.x;
    o.y = (v.y - mean) * rstd * gg.y + bb.y;
    o.z = (v.z - mean) * rstd * gg.z + bb.z;
    o.w = (v.w - mean) * rstd * gg.w + bb.w;
    if (WF32) *(float4*)(oF + (size_t)row * DMODEL + tid * 4) = o;
    size_t base = (size_t)row * (DMODEL / 2) + tid * 2;
    if (SPLIT) {
        uint32_t h0, l0, h1, l1;
        split2(o.x, o.y, h0, l0);
        split2(o.z, o.w, h1, l1);
        H[base] = h0; H[base + 1] = h1;
        L[base] = l0; L[base + 1] = l1;
    } else {
        H[base]     = pack2(o.x, o.y);
        H[base + 1] = pack2(o.z, o.w);
    }
}

#define EM_F32 0
#define EM_SP  1
#define EM_QKV 3
#define EM_HF  4

// ================= flash attention: scores+softmax+AV fused ==================
// Per CTA: 128 q rows (blockIdx.x), batch b (blockIdx.y). 8 warps x 16 q rows.
// Q: split hi/lo fp16 in smem (64KB). KV tiles double-buffered (2 x 64KB).
// S = 2-pass (qH+qL)@kT; online softmax in registers; PV 1-pass fp16.
__global__ __launch_bounds__(256, 1)
void flash_attn(const uint32_t* __restrict__ qH, const uint32_t* __restrict__ qL,
                const uint32_t* __restrict__ ktH, const uint32_t* __restrict__ vH,
                uint32_t* __restrict__ atH, uint32_t* __restrict__ atL,
                float scale)
{
    extern __shared__ char smc[];
    const uint32_t sb = smem_u32(smc);
    const int tid = threadIdx.x, wid = tid >> 5, lane = tid & 31;
    const int q = lane >> 3, l7 = lane & 7;
    const int b = blockIdx.y, qt = blockIdx.x;

    // ---- loads ----
    auto load_q = [&] {
        #pragma unroll
        for (int t = 0; t < 8; t++) {
            int id = tid + t * 256;
            int m = id >> 4, ch = id & 15;
            size_t src = ((size_t)(b * 2048 + qt * 128 + m)) * 64 + ch * 4;
            uint32_t dst = sb + m * 256 + ((ch ^ (m & 15)) << 4);
            cpasync16(dst, qH + src);
            cpasync16(dst + 32768, qL + src);
        }
    };
    auto load_kv = [&](int st, int j) {
        const uint32_t stb = sb + 65536 + st * 65536;
        #pragma unroll
        for (int t = 0; t < 8; t++) {
            int id = tid + t * 256;
            int d = id >> 4, ch = id & 15;
            cpasync16(stb + d * 256 + ((ch ^ (d & 15)) << 4),
                      ktH + ((size_t)b * 128 + d) * 1024 + j * 64 + ch * 4);
        }
        #pragma unroll
        for (int t = 0; t < 8; t++) {
            int id = tid + t * 256;
            int s = id >> 4, ch = id & 15;
            cpasync16(stb + 32768 + s * 256 + ((ch ^ (s & 15)) << 4),
                      vH + ((size_t)(b * 2048 + j * 128 + s)) * 64 + ch * 4);
        }
    };

    load_q(); load_kv(0, 0); CP_COMMIT();
    load_kv(1, 1); CP_COMMIT();

    float oa[16][4];
    #pragma unroll
    for (int jd = 0; jd < 16; jd++)
        #pragma unroll
        for (int r = 0; r < 4; r++) oa[jd][r] = 0.f;
    float m0 = -1e30f, m1 = -1e30f, l0 = 0.f, l1 = 0.f;

    for (int j = 0; j < 16; ++j) {
        CP_WAIT1();
        __syncthreads();
        const uint32_t stb = sb + 65536 + (j & 1) * 65536;

        // ---- S = q @ kT (2-pass) ----
        float sa[16][4];
        #pragma unroll
        for (int jn = 0; jn < 16; jn++)
            #pragma unroll
            for (int r = 0; r < 4; r++) sa[jn][r] = 0.f;

        #pragma unroll
        for (int ks = 0; ks < 8; ks++) {
            uint32_t aH4[4], aL4[4];
            int m = wid * 16 + ((q & 1) << 3) + l7;
            int ch = 2 * ks + (q >> 1);
            uint32_t ad = sb + m * 256 + ((ch ^ (m & 15)) << 4);
            ldm_x4(aH4, ad);
            ldm_x4(aL4, ad + 32768);
            #pragma unroll
            for (int g = 0; g < 8; g++) {
                uint32_t b4[4];
                int k = ks * 16 + ((q & 1) << 3) + l7;
                int bch = g * 2 + (q >> 1);
                ldm_x4_t(b4, stb + k * 256 + ((bch ^ (k & 15)) << 4));
                mma16816(sa[2 * g],     aH4, &b4[0]);
                mma16816(sa[2 * g],     aL4, &b4[0]);
                mma16816(sa[2 * g + 1], aH4, &b4[2]);
                mma16816(sa[2 * g + 1], aL4, &b4[2]);
            }
        }

        // ---- online softmax ----
        float mx0 = -1e30f, mx1 = -1e30f;
        #pragma unroll
        for (int jn = 0; jn < 16; jn++) {
            sa[jn][0] *= scale; sa[jn][1] *= scale;
            sa[jn][2] *= scale; sa[jn][3] *= scale;
            mx0 = fmaxf(mx0, fmaxf(sa[jn][0], sa[jn][1]));
            mx1 = fmaxf(mx1, fmaxf(sa[jn][2], sa[jn][3]));
        }
        mx0 = fmaxf(mx0, __shfl_xor_sync(0xffffffffu, mx0, 1));
        mx0 = fmaxf(mx0, __shfl_xor_sync(0xffffffffu, mx0, 2));
        mx1 = fmaxf(mx1, __shfl_xor_sync(0xffffffffu, mx1, 1));
        mx1 = fmaxf(mx1, __shfl_xor_sync(0xffffffffu, mx1, 2));

        float mn0 = fmaxf(m0, mx0), mn1 = fmaxf(m1, mx1);
        float c0 = expf(m0 - mn0), c1 = expf(m1 - mn1);
        m0 = mn0; m1 = mn1;

        float rs0 = 0.f, rs1 = 0.f;
        #pragma unroll
        for (int jn = 0; jn < 16; jn++) {
            sa[jn][0] = expf(sa[jn][0] - mn0);
            sa[jn][1] = expf(sa[jn][1] - mn0);
            sa[jn][2] = expf(sa[jn][2] - mn1);
            sa[jn][3] = expf(sa[jn][3] - mn1);
            rs0 += sa[jn][0] + sa[jn][1];
            rs1 += sa[jn][2] + sa[jn][3];
        }
        rs0 += __shfl_xor_sync(0xffffffffu, rs0, 1);
        rs0 += __shfl_xor_sync(0xffffffffu, rs0, 2);
        rs1 += __shfl_xor_sync(0xffffffffu, rs1, 1);
        rs1 += __shfl_xor_sync(0xffffffffu, rs1, 2);
        l0 = l0 * c0 + rs0;
        l1 = l1 * c1 + rs1;
        #pragma unroll
        for (int jd = 0; jd < 16; jd++) {
            oa[jd][0] *= c0; oa[jd][1] *= c0;
            oa[jd][2] *= c1; oa[jd][3] *= c1;
        }

        // ---- PV (1-pass fp16 P) ----
        #pragma unroll
        for (int t = 0; t < 8; t++) {
            uint32_t pa[4];
            pa[0] = pack2(sa[2 * t][0],     sa[2 * t][1]);
            pa[1] = pack2(sa[2 * t][2],     sa[2 * t][3]);
            pa[2] = pack2(sa[2 * t + 1][0], sa[2 * t + 1][1]);
            pa[3] = pack2(sa[2 * t + 1][2], sa[2 * t + 1][3]);
            int k = t * 16 + ((q & 1) << 3) + l7;
            #pragma unroll
            for (int g = 0; g < 8; g++) {
                uint32_t b4[4];
                int bch = g * 2 + (q >> 1);
                ldm_x4_t(b4, stb + 32768 + k * 256 + ((bch ^ (k & 15)) << 4));
                mma16816(oa[2 * g],     pa, &b4[0]);
                mma16816(oa[2 * g + 1], pa, &b4[2]);
            }
        }

        __syncthreads();
        if (j + 2 < 16) load_kv(j & 1, j + 2);
        CP_COMMIT();
    }

    // ---- finalize + emit att split pairs ----
    const float i0 = 1.0f / l0, i1 = 1.0f / l1;
    const size_t row0 = (size_t)(b * 2048 + qt * 128 + wid * 16 + (lane >> 2));
    const int qc = lane & 3;
    #pragma unroll
    for (int jd = 0; jd < 16; jd++) {
        uint32_t h, l;
        split2(oa[jd][0] * i0, oa[jd][1] * i0, h, l);
        size_t idx = row0 * 64 + 4 * jd + qc;
        atH[idx] = h; atL[idx] = l;
        split2(oa[jd][2] * i1, oa[jd][3] * i1, h, l);
        idx = (row0 + 8) * 64 + 4 * jd + qc;
        atH[idx] = h; atL[idx] = l;
    }
}

// ================= 2-pass GEMM, BN=128, BK=64, 4-stage (A split, B single) ===
template<int EMIT, int EPI>
__global__ __launch_bounds__(256, 1)
void hg2p(const uint32_t* __restrict__ Ah, const uint32_t* __restrict__ Al,
          const uint32_t* __restrict__ Bh,
          const float* __restrict__ bias, const float* __restrict__ res,
          float* __restrict__ outF, uint32_t* __restrict__ outH, uint32_t* __restrict__ outL,
          uint32_t* __restrict__ outH2, uint32_t* __restrict__ outH3,
          int Ka, int Nb, int nc,
          long long sAu, long long sBu, long long sCf, long long sOu,
          float alpha)
{
    extern __shared__ char smc[];
    const uint32_t sb = smem_u32(smc);
    const int tid = threadIdx.x, wid = tid >> 5, lane = tid & 31;
    const int wm = wid >> 2, wn = wid & 3;
    const int bx = blockIdx.x, by = blockIdx.y, bz = blockIdx.z;

    const uint32_t Ka2 = (uint32_t)Ka >> 1, Nb2 = (uint32_t)Nb >> 1;
    const uint32_t* Ahb = Ah + (size_t)bz * sAu;
    const uint32_t* Alb = Al + (size_t)bz * sAu;
    const uint32_t* Bhb = Bh + (size_t)bz * sBu;

    auto load_stage = [&](int st, int c) {
        const uint32_t stb = sb + st * 49152;
        #pragma unroll
        for (int t = 0; t < 4; t++) {
            int id = tid + t * 256;
            int m = id >> 3, ch = id & 7;
            size_t go = (size_t)(by * 128 + m) * Ka2 + (size_t)c * 32 + ch * 4;
            uint32_t sa = stb + m * 128 + ((ch ^ (m & 7)) << 4);
            cpasync16(sa, Ahb + go);
            cpasync16(sa + 16384, Alb + go);
        }
        #pragma unroll
        for (int t = 0; t < 4; t++) {
            int id = tid + t * 256;
            int k = id >> 4, ch = id & 15;
            size_t go = (size_t)(c * 64 + k) * Nb2 + (size_t)bx * 64 + ch * 4;
            cpasync16(stb + 32768 + k * 256 + ((ch ^ (k & 15)) << 4), Bhb + go);
        }
    };

    float acc[4][4][4];
    #pragma unroll
    for (int i = 0; i < 4; i++)
        #pragma unroll
        for (int j = 0; j < 4; j++)
            #pragma unroll
            for (int r = 0; r < 4; r++) acc[i][j][r] = 0.f;

    load_stage(0, 0); CP_COMMIT();
    load_stage(1, 1); CP_COMMIT();
    load_stage(2, 2); CP_COMMIT();

    const int q = lane >> 3, l7 = lane & 7;

    for (int c = 0; c < nc; ++c) {
        CP_WAIT2();
        __syncthreads();
        if (c + 3 < nc) load_stage((c + 3) & 3, c + 3);
        CP_COMMIT();

        const uint32_t stb = sb + (c & 3) * 49152;
        #pragma unroll
        for (int ks = 0; ks < 4; ks++) {
            uint32_t aH[4][4], aL[4][4], bH4[2][4];
            #pragma unroll
            for (int i = 0; i < 4; i++) {
                int m = wm * 64 + i * 16 + ((q & 1) << 3) + l7;
                int ch = 2 * ks + (q >> 1);
                uint32_t ad = stb + m * 128 + ((ch ^ (m & 7)) << 4);
                ldm_x4(aH[i], ad);
                ldm_x4(aL[i], ad + 16384);
            }
            #pragma unroll
            for (int g = 0; g < 2; g++) {
                int k = ks * 16 + ((q & 1) << 3) + l7;
                int ch = wn * 4 + g * 2 + (q >> 1);
                ldm_x4_t(bH4[g], stb + 32768 + k * 256 + ((ch ^ (k & 15)) << 4));
            }
            #pragma unroll
            for (int i = 0; i < 4; i++)
                #pragma unroll
                for (int j = 0; j < 4; j++) {
                    const uint32_t* bh = &bH4[j >> 1][(j & 1) * 2];
                    mma16816(acc[i][j], aH[i], bh);
                    mma16816(acc[i][j], aL[i], bh);
                }
        }
    }

    __syncthreads();
    float* Cs = (float*)smc;
    #pragma unroll
    for (int i = 0; i < 4; i++)
        #pragma unroll
        for (int j = 0; j < 4; j++) {
            int r0 = wm * 64 + i * 16 + (lane >> 2);
            int c0 = wn * 32 + j * 8 + 2 * (lane & 3);
            *(float2*)(Cs + r0 * 132 + c0)       = make_float2(acc[i][j][0], acc[i][j][1]);
            *(float2*)(Cs + (r0 + 8) * 132 + c0) = make_float2(acc[i][j][2], acc[i][j][3]);
        }
    __syncthreads();

    if (EMIT == EM_SP) {
        #pragma unroll
        for (int i = 0; i < 32; i++) {
            int u = tid + 256 * i;
            int row = u >> 6, np = u & 63;
            float v0 = Cs[row * 132 + 2 * np]     * alpha;
            float v1 = Cs[row * 132 + 2 * np + 1] * alpha;
            int gc = bx * 128 + 2 * np;
            if (EPI & 1) { v0 += __ldg(bias + gc); v1 += __ldg(bias + gc + 1); }
            if (EPI & 2) { v0 = gelu1(v0); v1 = gelu1(v1); }
            uint32_t h, l;
            split2(v0, v1, h, l);
            size_t gm = (size_t)by * 128 + row;
            size_t idx = (size_t)bz * sOu + gm * (Nb >> 1) + (size_t)bx * 64 + np;
            outH[idx] = h; outL[idx] = l;
        }
    } else { // EM_QKV: bx=0 q split, bx=1 kT single transposed, bx=2 v single
        if (bx == 1) {
            const int b = by >> 4;
            const int s0p = (by & 15) * 64;
            #pragma unroll
            for (int i = 0; i < 32; i++) {
                int u = tid + 256 * i;
                int d = u >> 6, sp = u & 63;
                float bb = __ldg(bias + 128 + d);
                float v0 = Cs[(2 * sp) * 132 + d]     + bb;
                float v1 = Cs[(2 * sp + 1) * 132 + d] + bb;
                size_t idx = (size_t)b * (DKV * SEQ / 2) + (size_t)d * (SEQ / 2) + s0p + sp;
                outH2[idx] = pack2(v0, v1);
            }
        } else if (bx == 0) {
            #pragma unroll
            for (int i = 0; i < 32; i++) {
                int u = tid + 256 * i;
                int row = u >> 6, np = u & 63;
                float v0 = Cs[row * 132 + 2 * np]     + __ldg(bias + 2 * np);
                float v1 = Cs[row * 132 + 2 * np + 1] + __ldg(bias + 2 * np + 1);
                uint32_t h, l;
                split2(v0, v1, h, l);
                size_t idx = ((size_t)by * 128 + row) * 64 + np;
                outH[idx] = h; outL[idx] = l;
            }
        } else {
            #pragma unroll
            for (int i = 0; i < 32; i++) {
                int u = tid + 256 * i;
                int row = u >> 6, np = u & 63;
                float v0 = Cs[row * 132 + 2 * np]     + __ldg(bias + 256 + 2 * np);
                float v1 = Cs[row * 132 + 2 * np + 1] + __ldg(bias + 256 + 2 * np + 1);
                size_t idx = ((size_t)by * 128 + row) * 64 + np;
                outH3[idx] = pack2(v0, v1);
            }
        }
    }
}

// ================= 2-pass GEMM, BN=256, BK=64, 3-stage (A split, B single) ===
template<int EPI>
__global__ __launch_bounds__(256, 1)
void hg2p256(const uint32_t* __restrict__ Ah, const uint32_t* __restrict__ Al,
             const uint32_t* __restrict__ Bh,
             const float* __restrict__ bias, const float* __restrict__ res,
             float* __restrict__ outF,
             int Ka, int Nb, int nc,
             long long sAu, long long sBu, long long sCf,
             float alpha)
{
    extern __shared__ char smc[];
    const uint32_t sb = smem_u32(smc);
    const int tid = threadIdx.x, wid = tid >> 5, lane = tid & 31;
    const int wm = wid >> 2, wn = wid & 3;
    const int bx = blockIdx.x, by = blockIdx.y, bz = blockIdx.z;

    const uint32_t Ka2 = (uint32_t)Ka >> 1, Nb2 = (uint32_t)Nb >> 1;
    const uint32_t* Ahb = Ah + (size_t)bz * sAu;
    const uint32_t* Alb = Al + (size_t)bz * sAu;
    const uint32_t* Bhb = Bh + (size_t)bz * sBu;

    auto load_stage = [&](int st, int c) {
        const uint32_t stb = sb + st * 65536;
        #pragma unroll
        for (int t = 0; t < 4; t++) {
            int id = tid + t * 256;
            int m = id >> 3, ch = id & 7;
            size_t go = (size_t)(by * 128 + m) * Ka2 + (size_t)c * 32 + ch * 4;
            uint32_t sa = stb + m * 128 + ((ch ^ (m & 7)) << 4);
            cpasync16(sa, Ahb + go);
            cpasync16(sa + 16384, Alb + go);
        }
        #pragma unroll
        for (int t = 0; t < 8; t++) {
            int id = tid + t * 256;
            int k = id >> 5, ch = id & 31;
            size_t go = (size_t)(c * 64 + k) * Nb2 + (size_t)bx * 128 + ch * 4;
            cpasync16(stb + 32768 + k * 512 + ((ch ^ (k & 15)) << 4), Bhb + go);
        }
    };

    float acc[4][8][4];
    #pragma unroll
    for (int i = 0; i < 4; i++)
        #pragma unroll
        for (int j = 0; j < 8; j++)
            #pragma unroll
            for (int r = 0; r < 4; r++) acc[i][j][r] = 0.f;

    load_stage(0, 0); CP_COMMIT();
    load_stage(1, 1); CP_COMMIT();

    const int q = lane >> 3, l7 = lane & 7;

    for (int c = 0; c < nc; ++c) {
        CP_WAIT1();
        __syncthreads();
        if (c + 2 < nc) load_stage((c + 2) % 3, c + 2);
        CP_COMMIT();

        const uint32_t stb = sb + (c % 3) * 65536;
        #pragma unroll
        for (int ks = 0; ks < 4; ks++) {
            uint32_t aH[4][4], aL[4][4];
            #pragma unroll
            for (int i = 0; i < 4; i++) {
                int m = wm * 64 + i * 16 + ((q & 1) << 3) + l7;
                int ch = 2 * ks + (q >> 1);
                uint32_t ad = stb + m * 128 + ((ch ^ (m & 7)) << 4);
                ldm_x4(aH[i], ad);
                ldm_x4(aL[i], ad + 16384);
            }
            #pragma unroll
            for (int g = 0; g < 4; g++) {
                uint32_t bH4[4];
                int k = ks * 16 + ((q & 1) << 3) + l7;
                int ch = wn * 8 + g * 2 + (q >> 1);
                ldm_x4_t(bH4, stb + 32768 + k * 512 + ((ch ^ (k & 15)) << 4));
                #pragma unroll
                for (int i = 0; i < 4; i++) {
                    #pragma unroll
                    for (int jj = 0; jj < 2; jj++) {
                        const uint32_t* bh = &bH4[jj * 2];
                        float* a4 = acc[i][g * 2 + jj];
                        mma16816(a4, aH[i], bh);
                        mma16816(a4, aL[i], bh);
                    }
                }
            }
        }
    }

    __syncthreads();
    float* Cs = (float*)smc;
    #pragma unroll
    for (int i = 0; i < 4; i++)
        #pragma unroll
        for (int j = 0; j < 8; j++) {
            int r0 = wm * 64 + i * 16 + (lane >> 2);
            int c0 = wn * 64 + j * 8 + 2 * (lane & 3);
            *(float2*)(Cs + r0 * 260 + c0)       = make_float2(acc[i][j][0], acc[i][j][1]);
            *(float2*)(Cs + (r0 + 8) * 260 + c0) = make_float2(acc[i][j][2], acc[i][j][3]);
        }
    __syncthreads();

    #pragma unroll
    for (int i = 0; i < 32; i++) {
        int u = tid + 256 * i;
        int row = u >> 6, c4 = (u & 63) * 4;
        float4 v = *(float4*)(Cs + row * 260 + c4);
        v.x *= alpha; v.y *= alpha; v.z *= alpha; v.w *= alpha;
        int gc = bx * 256 + c4;
        size_t gm = (size_t)by * 128 + row;
        if (EPI & 1) {
            float4 bb = *(const float4*)(bias + gc);
            v.x += bb.x; v.y += bb.y; v.z += bb.z; v.w += bb.w;
        }
        if (EPI & 2) { v.x = gelu1(v.x); v.y = gelu1(v.y); v.z = gelu1(v.z); v.w = gelu1(v.w); }
        if (EPI & 4) {
            float4 rr = *(const float4*)(res + gm * Nb + gc);
            v.x += rr.x; v.y += rr.y; v.z += rr.z; v.w += rr.w;
        }
        *(float4*)(outF + (size_t)bz * sCf + gm * Nb + gc) = v;
    }
}

// ================= 1-pass GEMM, BN=128, BK=64, 3-stage, 2 CTAs/SM ============
template<int EMIT, int EPI>
__global__ __launch_bounds__(256, 2)
void hg1p128(const uint32_t* __restrict__ Ah, const uint32_t* __restrict__ Bh,
             const float* __restrict__ bias, const float* __restrict__ res,
             float* __restrict__ outF, uint32_t* __restrict__ outH,
             int Ka, int Nb, int nc, float alpha)
{
    extern __shared__ char smc[];
    const uint32_t sb = smem_u32(smc);
    const int tid = threadIdx.x, wid = tid >> 5, lane = tid & 31;
    const int wm = wid >> 2, wn = wid & 3;
    const int bx = blockIdx.x, by = blockIdx.y;

    const uint32_t Ka2 = (uint32_t)Ka >> 1, Nb2 = (uint32_t)Nb >> 1;

    auto load_stage = [&](int st, int c) {
        const uint32_t stb = sb + st * 32768;
        #pragma unroll
        for (int t = 0; t < 4; t++) {
            int id = tid + t * 256;
            int m = id >> 3, ch = id & 7;
            size_t go = (size_t)(by * 128 + m) * Ka2 + (size_t)c * 32 + ch * 4;
            cpasync16(stb + m * 128 + ((ch ^ (m & 7)) << 4), Ah + go);
        }
        #pragma unroll
        for (int t = 0; t < 4; t++) {
            int id = tid + t * 256;
            int k = id >> 4, ch = id & 15;
            size_t go = (size_t)(c * 64 + k) * Nb2 + (size_t)bx * 64 + ch * 4;
            cpasync16(stb + 16384 + k * 256 + ((ch ^ (k & 15)) << 4), Bh + go);
        }
    };

    float acc[4][4][4];
    #pragma unroll
    for (int i = 0; i < 4; i++)
        #pragma unroll
        for (int j = 0; j < 4; j++)
            #pragma unroll
            for (int r = 0; r < 4; r++) acc[i][j][r] = 0.f;

    load_stage(0, 0); CP_COMMIT();
    load_stage(1, 1); CP_COMMIT();

    const int q = lane >> 3, l7 = lane & 7;

    for (int c = 0; c < nc; ++c) {
        CP_WAIT1();
        __syncthreads();
        if (c + 2 < nc) load_stage((c + 2) % 3, c + 2);
        CP_COMMIT();

        const uint32_t stb = sb + (c % 3) * 32768;
        #pragma unroll
        for (int ks = 0; ks < 4; ks++) {
            uint32_t aH[4][4], bH4[2][4];
            #pragma unroll
            for (int i = 0; i < 4; i++) {
                int m = wm * 64 + i * 16 + ((q & 1) << 3) + l7;
                int ch = 2 * ks + (q >> 1);
                ldm_x4(aH[i], stb + m * 128 + ((ch ^ (m & 7)) << 4));
            }
            #pragma unroll
            for (int g = 0; g < 2; g++) {
                int k = ks * 16 + ((q & 1) << 3) + l7;
                int ch = wn * 4 + g * 2 + (q >> 1);
                ldm_x4_t(bH4[g], stb + 16384 + k * 256 + ((ch ^ (k & 15)) << 4));
            }
            #pragma unroll
            for (int i = 0; i < 4; i++)
                #pragma unroll
                for (int j = 0; j < 4; j++)
                    mma16816(acc[i][j], aH[i], &bH4[j >> 1][(j & 1) * 2]);
        }
    }

    __syncthreads();
    float* Cs = (float*)smc;
    #pragma unroll
    for (int i = 0; i < 4; i++)
        #pragma unroll
        for (int j = 0; j < 4; j++) {
            int r0 = wm * 64 + i * 16 + (lane >> 2);
            int c0 = wn * 32 + j * 8 + 2 * (lane & 3);
            *(float2*)(Cs + r0 * 132 + c0)       = make_float2(acc[i][j][0], acc[i][j][1]);
            *(float2*)(Cs + (r0 + 8) * 132 + c0) = make_float2(acc[i][j][2], acc[i][j][3]);
        }
    __syncthreads();

    if (EMIT == EM_F32) {
        #pragma unroll
        for (int i = 0; i < 16; i++) {
            int u = tid + 256 * i;
            int row = u >> 5, c4 = (u & 31) * 4;
            float4 v = *(float4*)(Cs + row * 132 + c4);
            v.x *= alpha; v.y *= alpha; v.z *= alpha; v.w *= alpha;
            int gc = bx * 128 + c4;
            size_t gm = (size_t)by * 128 + row;
            if (EPI & 1) {
                float4 bb = *(const float4*)(bias + gc);
                v.x += bb.x; v.y += bb.y; v.z += bb.z; v.w += bb.w;
            }
            if (EPI & 2) { v.x = gelu1(v.x); v.y = gelu1(v.y); v.z = gelu1(v.z); v.w = gelu1(v.w); }
            if (EPI & 4) {
                float4 rr = *(const float4*)(res + gm * Nb + gc);
                v.x += rr.x; v.y += rr.y; v.z += rr.z; v.w += rr.w;
            }
            *(float4*)(outF + gm * Nb + gc) = v;
        }
    } else { // EM_HF single pairs
        #pragma unroll
        for (int i = 0; i < 32; i++) {
            int u = tid + 256 * i;
            int row = u >> 6, np = u & 63;
            float v0 = Cs[row * 132 + 2 * np]     * alpha;
            float v1 = Cs[row * 132 + 2 * np + 1] * alpha;
            int gc = bx * 128 + 2 * np;
            if (EPI & 1) { v0 += __ldg(bias + gc); v1 += __ldg(bias + gc + 1); }
            if (EPI & 2) { v0 = gelu1(v0); v1 = gelu1(v1); }
            size_t gm = (size_t)by * 128 + row;
            outH[gm * (Nb >> 1) + (size_t)bx * 64 + np] = pack2(v0, v1);
        }
    }
}

// ---------------- launch sequence -------------------------------------------
extern "C" void kernel_launch(void* const* d_in, const int* in_sizes, int n_in,
                              void* d_out, int out_size)
{
    const float* x     = (const float*)d_in[0];
    const float* ln1_g = (const float*)d_in[1];
    const float* ln1_b = (const float*)d_in[2];
    const float* Wq    = (const float*)d_in[3];
    const float* bq    = (const float*)d_in[4];
    const float* Wk    = (const float*)d_in[5];
    const float* bk    = (const float*)d_in[6];
    const float* Wv    = (const float*)d_in[7];
    const float* bv    = (const float*)d_in[8];
    const float* Wo    = (const float*)d_in[9];
    const float* bo    = (const float*)d_in[10];
    const float* ln2_g = (const float*)d_in[11];
    const float* ln2_b = (const float*)d_in[12];
    const float* W1    = (const float*)d_in[13];
    const float* b1    = (const float*)d_in[14];
    const float* W2    = (const float*)d_in[15];
    const float* b2    = (const float*)d_in[16];
    float* out = (float*)d_out;

    float *xnF, *yF, *bqkv;
    uint32_t *xnH,*xnL,*hH,*qH,*qL,*ktH,*vH,*atH,*atL,*acH;
    uint32_t *wqkvH,*woH,*w1H,*w2H;
    cudaGetSymbolAddress((void**)&xnF, g_xnF);
    cudaGetSymbolAddress((void**)&yF,  g_yF);  cudaGetSymbolAddress((void**)&bqkv, g_bqkv);
    cudaGetSymbolAddress((void**)&xnH, g_xnH); cudaGetSymbolAddress((void**)&xnL, g_xnL);
    cudaGetSymbolAddress((void**)&hH,  g_hH);
    cudaGetSymbolAddress((void**)&qH,  g_qH);  cudaGetSymbolAddress((void**)&qL,  g_qL);
    cudaGetSymbolAddress((void**)&ktH, g_ktH);
    cudaGetSymbolAddress((void**)&vH,  g_vH);
    cudaGetSymbolAddress((void**)&atH, g_atH); cudaGetSymbolAddress((void**)&atL, g_atL);
    cudaGetSymbolAddress((void**)&acH, g_acH);
    cudaGetSymbolAddress((void**)&wqkvH, g_wqkvH);
    cudaGetSymbolAddress((void**)&woH, g_woH);
    cudaGetSymbolAddress((void**)&w1H, g_w1H);
    cudaGetSymbolAddress((void**)&w2H, g_w2H);

    const int SM_2P   = 4 * 49152;   // 192 KB
    const int SM_2P256= 3 * 65536;   // 192 KB
    const int SM_1P   = 3 * 32768;   // 96 KB (2 CTAs/SM)
    const int SM_FL   = 3 * 65536;   // 192 KB (Q + 2 KV stages)
    cudaFuncSetAttribute(hg2p<EM_QKV,1>, cudaFuncAttributeMaxDynamicSharedMemorySize, SM_2P);
    cudaFuncSetAttribute(flash_attn,     cudaFuncAttributeMaxDynamicSharedMemorySize, SM_FL);
    cudaFuncSetAttribute(hg2p256<5>,     cudaFuncAttributeMaxDynamicSharedMemorySize, SM_2P256);
    cudaFuncSetAttribute(hg1p128<EM_HF, 3>, cudaFuncAttributeMaxDynamicSharedMemorySize, SM_1P);
    cudaFuncSetAttribute(hg1p128<EM_F32,5>, cudaFuncAttributeMaxDynamicSharedMemorySize, SM_1P);

    const float scale = 0.08838834764831845f; // 1/sqrt(128)

    // ---- 1 launch: all weight conversions (single fp16) + qkv bias pack ----
    {
        WJobs jb;
        jb.src[0] = Wq; jb.H[0] = wqkvH; jb.np[0] = DMODEL*DKV/2; jb.srcP[0] = 64;  jb.dstP[0] = 192; jb.coff[0] = 0;
        jb.src[1] = Wk; jb.H[1] = wqkvH; jb.np[1] = DMODEL*DKV/2; jb.srcP[1] = 64;  jb.dstP[1] = 192; jb.coff[1] = 64;
        jb.src[2] = Wv; jb.H[2] = wqkvH; jb.np[2] = DMODEL*DKV/2; jb.srcP[2] = 64;  jb.dstP[2] = 192; jb.coff[2] = 128;
        jb.src[3] = Wo; jb.H[3] = woH;   jb.np[3] = DKV*DMODEL/2; jb.srcP[3] = 512; jb.dstP[3] = 512; jb.coff[3] = 0;
        jb.src[4] = W1; jb.H[4] = w1H;   jb.np[4] = DMODEL*DFF/2; jb.srcP[4] = 2048;jb.dstP[4] = 2048;jb.coff[4] = 0;
        jb.src[5] = W2; jb.H[5] = w2H;   jb.np[5] = DFF*DMODEL/2; jb.srcP[5] = 512; jb.dstP[5] = 512; jb.coff[5] = 0;
        int acc_ = 0;
        for (int s = 0; s < 6; s++) { jb.blkStart[s] = acc_; acc_ += (jb.np[s] + 255) / 256; }
        jb.blkStart[6] = acc_;
        jb.bq = bq; jb.bk = bk; jb.bv = bv; jb.bqkv = bqkv;
        wconv_all<<<acc_ + 1, 256>>>(jb);
    }

    // 2) ln1 -> xn (f32 + split pairs)
    ln_frag<true, true><<<MS, 256>>>(x, ln1_g, ln1_b, xnF, xnH, xnL);

    // 3) fused QKV (16384 x 384 x 1024) [2-pass]: bx=0 q(split), 1 kT, 2 v
    hg2p<EM_QKV, 1><<<dim3(3,128,1), 256, SM_2P>>>(xnH, xnL, wqkvH, bqkv, nullptr,
        nullptr, qH, qL, ktH, vH, DMODEL, 384, 16, 0, 0, 0, 0, 1.f);

    // 4) flash attention: scores+softmax+AV fused -> att split pairs
    flash_attn<<<dim3(SEQ/128, BATCH), 256, SM_FL>>>(qH, qL, ktH, vH, atH, atL, scale);

    // 5) y = xn + att@Wo + bo (16384x1024x128) [2-pass]
    hg2p256<5><<<dim3(4,128,1), 256, SM_2P256>>>(atH, atL, woH, bo, xnF,
        yF, DKV, DMODEL, 2, 0, 0, 0, 1.f);

    // 6) ln2 -> h single pairs
    ln_frag<false, false><<<MS, 256>>>(yF, ln2_g, ln2_b, nullptr, hH, nullptr);

    // 7) act = gelu(h@W1 + b1) (16384x4096x1024) [1-pass, 2 CTA/SM]
    hg1p128<EM_HF, 3><<<dim3(32,128,1), 256, SM_1P>>>(hH, w1H, b1, nullptr,
        nullptr, acH, DMODEL, DFF, 16, 1.f);

    // 8) out = y + act@W2 + b2 (16384x1024x4096) [1-pass, 2 CTA/SM]
    hg1p128<EM_F32, 5><<<dim3(8,128,1), 256, SM_1P>>>(acH, w2H, b2, yF,
        out, nullptr, DFF, DMODEL, 64, 1.f);
}

// round 10
// speedup vs baseline: 7.1641x; 1.0650x over previous
#include <cuda_runtime.h>
#include <cuda_fp16.h>
#include <math.h>
#include <stdint.h>

#define BATCH 8
#define SEQ   2048
#define DMODEL 1024
#define DKV   128
#define DFF   4096
#define MS    (BATCH*SEQ)

// ---------------- scratch (static device globals) ----------------------------
__device__ float    g_xnF[(size_t)MS*DMODEL];
__device__ float    g_yF [(size_t)MS*DMODEL];

__device__ uint32_t g_xnH[(size_t)MS*DMODEL/2];                      // single fp16
__device__ uint32_t g_hH [(size_t)MS*DMODEL/2];                      // single fp16
__device__ uint32_t g_qH [(size_t)MS*DKV/2];                         // single fp16
__device__ uint32_t g_ktH[(size_t)BATCH*DKV*SEQ/2];                  // single fp16
__device__ uint32_t g_vH [(size_t)MS*DKV/2];                         // single fp16
__device__ uint32_t g_atH[(size_t)MS*DKV/2],     g_atL[(size_t)MS*DKV/2];
__device__ uint32_t g_acH[(size_t)MS*DFF/2];                         // single fp16

__device__ uint32_t g_wqkvH[(size_t)DMODEL*384/2];  // single fp16
__device__ float    g_bqkv[384];
__device__ uint32_t g_woH[(size_t)DKV*DMODEL/2];    // single fp16
__device__ uint32_t g_w1H[(size_t)DMODEL*DFF/2];    // single fp16
__device__ uint32_t g_w2H[(size_t)DFF*DMODEL/2];    // single fp16

// ---------------- helpers ----------------------------------------------------
__device__ __forceinline__ uint32_t smem_u32(const void* p) {
    uint32_t a;
    asm("{ .reg .u64 t; cvta.to.shared.u64 t, %1; cvt.u32.u64 %0, t; }" : "=r"(a) : "l"(p));
    return a;
}
__device__ __forceinline__ void cpasync16(uint32_t dst, const void* src) {
    asm volatile("cp.async.cg.shared.global [%0], [%1], 16;" :: "r"(dst), "l"(src));
}
#define CP_COMMIT() asm volatile("cp.async.commit_group;" ::: "memory")
#define CP_WAIT1()  asm volatile("cp.async.wait_group 1;" ::: "memory")
#define CP_WAIT2()  asm volatile("cp.async.wait_group 2;" ::: "memory")

__device__ __forceinline__ void ldm_x4(uint32_t r[4], uint32_t addr) {
    asm volatile("ldmatrix.sync.aligned.m8n8.x4.shared.b16 {%0,%1,%2,%3}, [%4];"
                 : "=r"(r[0]), "=r"(r[1]), "=r"(r[2]), "=r"(r[3]) : "r"(addr));
}
__device__ __forceinline__ void ldm_x4_t(uint32_t r[4], uint32_t addr) {
    asm volatile("ldmatrix.sync.aligned.m8n8.x4.trans.shared.b16 {%0,%1,%2,%3}, [%4];"
                 : "=r"(r[0]), "=r"(r[1]), "=r"(r[2]), "=r"(r[3]) : "r"(addr));
}
__device__ __forceinline__ void mma16816(float c[4], const uint32_t a[4], const uint32_t b[2]) {
    asm volatile("mma.sync.aligned.m16n8k16.row.col.f32.f16.f16.f32 "
                 "{%0,%1,%2,%3},{%4,%5,%6,%7},{%8,%9},{%0,%1,%2,%3};"
                 : "+f"(c[0]), "+f"(c[1]), "+f"(c[2]), "+f"(c[3])
                 : "r"(a[0]), "r"(a[1]), "r"(a[2]), "r"(a[3]), "r"(b[0]), "r"(b[1]));
}
__device__ __forceinline__ uint32_t packh(__half a, __half b) {
    return (uint32_t)__half_as_ushort(a) | ((uint32_t)__half_as_ushort(b) << 16);
}
__device__ __forceinline__ void split2(float a, float b, uint32_t& hi, uint32_t& lo) {
    __half ha = __float2half_rn(a);
    __half hb = __float2half_rn(b);
    __half la = __float2half_rn(a - __half2float(ha));
    __half lb = __float2half_rn(b - __half2float(hb));
    hi = packh(ha, hb);
    lo = packh(la, lb);
}
__device__ __forceinline__ uint32_t pack2(float a, float b) {
    return packh(__float2half_rn(a), __float2half_rn(b));
}
__device__ __forceinline__ float gelu1(float v) {
    return 0.5f * v * (1.0f + erff(v * 0.70710678118654752f));
}

// ---------------- one-shot weight conversion (all single fp16) ---------------
struct WJobs {
    const float* src[6];
    uint32_t* H[6];
    int np[6];
    int srcP[6];
    int dstP[6];
    int coff[6];
    int blkStart[7];
    const float* bq; const float* bk; const float* bv;
    float* bqkv;
};

__global__ __launch_bounds__(256) void wconv_all(WJobs jb)
{
    const int blk = blockIdx.x, tid = threadIdx.x;
    if (blk >= jb.blkStart[6]) {
        if (tid < 128) {
            jb.bqkv[tid]       = jb.bq[tid];
            jb.bqkv[128 + tid] = jb.bk[tid];
            jb.bqkv[256 + tid] = jb.bv[tid];
        }
        return;
    }
    int seg = 0;
    #pragma unroll
    for (int s = 1; s < 6; s++) if (blk >= jb.blkStart[s]) seg = s;
    int u = (blk - jb.blkStart[seg]) * 256 + tid;
    if (u >= jb.np[seg]) return;
    int k = u / jb.srcP[seg], p = u - k * jb.srcP[seg];
    float2 v = *(const float2*)(jb.src[seg] + ((size_t)u) * 2);
    jb.H[seg][(size_t)k * jb.dstP[seg] + jb.coff[seg] + p] = pack2(v.x, v.y);
}

// ---------------- LayerNorm: one row/block ------------------------------------
template<bool WF32, bool SPLIT>
__global__ __launch_bounds__(256) void ln_frag(const float* __restrict__ x,
                                               const float* __restrict__ g,
                                               const float* __restrict__ b,
                                               float* __restrict__ oF,
                                               uint32_t* __restrict__ H,
                                               uint32_t* __restrict__ L)
{
    const int row = blockIdx.x;
    const int tid = threadIdx.x;
    const float* xr = x + (size_t)row * DMODEL;
    float4 v = *(const float4*)(xr + tid * 4);

    float s  = v.x + v.y + v.z + v.w;
    float s2 = v.x*v.x + v.y*v.y + v.z*v.z + v.w*v.w;
    #pragma unroll
    for (int off = 16; off; off >>= 1) {
        s  += __shfl_xor_sync(0xffffffffu, s,  off);
        s2 += __shfl_xor_sync(0xffffffffu, s2, off);
    }
    __shared__ float ss[8], ss2[8], stats[2];
    const int wid = tid >> 5, lane = tid & 31;
    if (lane == 0) { ss[wid] = s; ss2[wid] = s2; }
    __syncthreads();
    if (wid == 0) {
        s  = (lane < 8) ? ss[lane]  : 0.f;
        s2 = (lane < 8) ? ss2[lane] : 0.f;
        #pragma unroll
        for (int off = 4; off; off >>= 1) {
            s  += __shfl_xor_sync(0xffffffffu, s,  off);
            s2 += __shfl_xor_sync(0xffffffffu, s2, off);
        }
        if (lane == 0) {
            float mean = s * (1.0f / DMODEL);
            float var  = s2 * (1.0f / DMODEL) - mean * mean;
            stats[0] = mean;
            stats[1] = rsqrtf(var + 1e-5f);
        }
    }
    __syncthreads();
    const float mean = stats[0], rstd = stats[1];
    float4 gg = *(const float4*)(g + tid * 4);
    float4 bb = *(const float4*)(b + tid * 4);
    float4 o;
    o.x = (v.x - mean) * rstd * gg.x + bb.x;
    o.y = (v.y - mean) * rstd * gg.y + bb.y;
    o.z = (v.z - mean) * rstd * gg.z + bb.z;
    o.w = (v.w - mean) * rstd * gg.w + bb.w;
    if (WF32) *(float4*)(oF + (size_t)row * DMODEL + tid * 4) = o;
    size_t base = (size_t)row * (DMODEL / 2) + tid * 2;
    if (SPLIT) {
        uint32_t h0, l0, h1, l1;
        split2(o.x, o.y, h0, l0);
        split2(o.z, o.w, h1, l1);
        H[base] = h0; H[base + 1] = h1;
        L[base] = l0; L[base + 1] = l1;
    } else {
        H[base]     = pack2(o.x, o.y);
        H[base + 1] = pack2(o.z, o.w);
    }
}

#define EM_F32 0
#define EM_QKV 3
#define EM_HF  4

// ================= flash attention: scores+softmax+AV fused ==================
// Q single fp16 (32KB smem). KV double-buffered (2 x 64KB). QK 1-pass, PV 1-pass.
__global__ __launch_bounds__(256, 1)
void flash_attn(const uint32_t* __restrict__ qH,
                const uint32_t* __restrict__ ktH, const uint32_t* __restrict__ vH,
                uint32_t* __restrict__ atH, uint32_t* __restrict__ atL,
                float scale)
{
    extern __shared__ char smc[];
    const uint32_t sb = smem_u32(smc);
    const int tid = threadIdx.x, wid = tid >> 5, lane = tid & 31;
    const int q = lane >> 3, l7 = lane & 7;
    const int b = blockIdx.y, qt = blockIdx.x;

    auto load_q = [&] {
        #pragma unroll
        for (int t = 0; t < 8; t++) {
            int id = tid + t * 256;
            int m = id >> 4, ch = id & 15;
            cpasync16(sb + m * 256 + ((ch ^ (m & 15)) << 4),
                      qH + ((size_t)(b * 2048 + qt * 128 + m)) * 64 + ch * 4);
        }
    };
    auto load_kv = [&](int st, int j) {
        const uint32_t stb = sb + 32768 + st * 65536;
        #pragma unroll
        for (int t = 0; t < 8; t++) {
            int id = tid + t * 256;
            int d = id >> 4, ch = id & 15;
            cpasync16(stb + d * 256 + ((ch ^ (d & 15)) << 4),
                      ktH + ((size_t)b * 128 + d) * 1024 + j * 64 + ch * 4);
        }
        #pragma unroll
        for (int t = 0; t < 8; t++) {
            int id = tid + t * 256;
            int s = id >> 4, ch = id & 15;
            cpasync16(stb + 32768 + s * 256 + ((ch ^ (s & 15)) << 4),
                      vH + ((size_t)(b * 2048 + j * 128 + s)) * 64 + ch * 4);
        }
    };

    load_q(); load_kv(0, 0); CP_COMMIT();
    load_kv(1, 1); CP_COMMIT();

    float oa[16][4];
    #pragma unroll
    for (int jd = 0; jd < 16; jd++)
        #pragma unroll
        for (int r = 0; r < 4; r++) oa[jd][r] = 0.f;
    float m0 = -1e30f, m1 = -1e30f, l0 = 0.f, l1 = 0.f;

    for (int j = 0; j < 16; ++j) {
        CP_WAIT1();
        __syncthreads();
        const uint32_t stb = sb + 32768 + (j & 1) * 65536;

        // ---- S = q @ kT (1-pass) ----
        float sa[16][4];
        #pragma unroll
        for (int jn = 0; jn < 16; jn++)
            #pragma unroll
            for (int r = 0; r < 4; r++) sa[jn][r] = 0.f;

        #pragma unroll
        for (int ks = 0; ks < 8; ks++) {
            uint32_t aH4[4];
            int m = wid * 16 + ((q & 1) << 3) + l7;
            int ch = 2 * ks + (q >> 1);
            ldm_x4(aH4, sb + m * 256 + ((ch ^ (m & 15)) << 4));
            #pragma unroll
            for (int g = 0; g < 8; g++) {
                uint32_t b4[4];
                int k = ks * 16 + ((q & 1) << 3) + l7;
                int bch = g * 2 + (q >> 1);
                ldm_x4_t(b4, stb + k * 256 + ((bch ^ (k & 15)) << 4));
                mma16816(sa[2 * g],     aH4, &b4[0]);
                mma16816(sa[2 * g + 1], aH4, &b4[2]);
            }
        }

        // ---- online softmax ----
        float mx0 = -1e30f, mx1 = -1e30f;
        #pragma unroll
        for (int jn = 0; jn < 16; jn++) {
            sa[jn][0] *= scale; sa[jn][1] *= scale;
            sa[jn][2] *= scale; sa[jn][3] *= scale;
            mx0 = fmaxf(mx0, fmaxf(sa[jn][0], sa[jn][1]));
            mx1 = fmaxf(mx1, fmaxf(sa[jn][2], sa[jn][3]));
        }
        mx0 = fmaxf(mx0, __shfl_xor_sync(0xffffffffu, mx0, 1));
        mx0 = fmaxf(mx0, __shfl_xor_sync(0xffffffffu, mx0, 2));
        mx1 = fmaxf(mx1, __shfl_xor_sync(0xffffffffu, mx1, 1));
        mx1 = fmaxf(mx1, __shfl_xor_sync(0xffffffffu, mx1, 2));

        float mn0 = fmaxf(m0, mx0), mn1 = fmaxf(m1, mx1);
        float c0 = expf(m0 - mn0), c1 = expf(m1 - mn1);
        m0 = mn0; m1 = mn1;

        float rs0 = 0.f, rs1 = 0.f;
        #pragma unroll
        for (int jn = 0; jn < 16; jn++) {
            sa[jn][0] = expf(sa[jn][0] - mn0);
            sa[jn][1] = expf(sa[jn][1] - mn0);
            sa[jn][2] = expf(sa[jn][2] - mn1);
            sa[jn][3] = expf(sa[jn][3] - mn1);
            rs0 += sa[jn][0] + sa[jn][1];
            rs1 += sa[jn][2] + sa[jn][3];
        }
        rs0 += __shfl_xor_sync(0xffffffffu, rs0, 1);
        rs0 += __shfl_xor_sync(0xffffffffu, rs0, 2);
        rs1 += __shfl_xor_sync(0xffffffffu, rs1, 1);
        rs1 += __shfl_xor_sync(0xffffffffu, rs1, 2);
        l0 = l0 * c0 + rs0;
        l1 = l1 * c1 + rs1;
        #pragma unroll
        for (int jd = 0; jd < 16; jd++) {
            oa[jd][0] *= c0; oa[jd][1] *= c0;
            oa[jd][2] *= c1; oa[jd][3] *= c1;
        }

        // ---- PV (1-pass fp16 P) ----
        #pragma unroll
        for (int t = 0; t < 8; t++) {
            uint32_t pa[4];
            pa[0] = pack2(sa[2 * t][0],     sa[2 * t][1]);
            pa[1] = pack2(sa[2 * t][2],     sa[2 * t][3]);
            pa[2] = pack2(sa[2 * t + 1][0], sa[2 * t + 1][1]);
            pa[3] = pack2(sa[2 * t + 1][2], sa[2 * t + 1][3]);
            int k = t * 16 + ((q & 1) << 3) + l7;
            #pragma unroll
            for (int g = 0; g < 8; g++) {
                uint32_t b4[4];
                int bch = g * 2 + (q >> 1);
                ldm_x4_t(b4, stb + 32768 + k * 256 + ((bch ^ (k & 15)) << 4));
                mma16816(oa[2 * g],     pa, &b4[0]);
                mma16816(oa[2 * g + 1], pa, &b4[2]);
            }
        }

        __syncthreads();
        if (j + 2 < 16) load_kv(j & 1, j + 2);
        CP_COMMIT();
    }

    // ---- finalize + emit att split pairs ----
    const float i0 = 1.0f / l0, i1 = 1.0f / l1;
    const size_t row0 = (size_t)(b * 2048 + qt * 128 + wid * 16 + (lane >> 2));
    const int qc = lane & 3;
    #pragma unroll
    for (int jd = 0; jd < 16; jd++) {
        uint32_t h, l;
        split2(oa[jd][0] * i0, oa[jd][1] * i0, h, l);
        size_t idx = row0 * 64 + 4 * jd + qc;
        atH[idx] = h; atL[idx] = l;
        split2(oa[jd][2] * i1, oa[jd][3] * i1, h, l);
        idx = (row0 + 8) * 64 + 4 * jd + qc;
        atH[idx] = h; atL[idx] = l;
    }
}

// ================= 2-pass GEMM, BN=128, BK=64, 4-stage (A split, B single) ===
// Used for O-proj: EMIT=EM_F32 with bias+res.
template<int EPI>
__global__ __launch_bounds__(256, 1)
void hg2p(const uint32_t* __restrict__ Ah, const uint32_t* __restrict__ Al,
          const uint32_t* __restrict__ Bh,
          const float* __restrict__ bias, const float* __restrict__ res,
          float* __restrict__ outF,
          int Ka, int Nb, int nc, float alpha)
{
    extern __shared__ char smc[];
    const uint32_t sb = smem_u32(smc);
    const int tid = threadIdx.x, wid = tid >> 5, lane = tid & 31;
    const int wm = wid >> 2, wn = wid & 3;
    const int bx = blockIdx.x, by = blockIdx.y;

    const uint32_t Ka2 = (uint32_t)Ka >> 1, Nb2 = (uint32_t)Nb >> 1;

    auto load_stage = [&](int st, int c) {
        const uint32_t stb = sb + st * 49152;
        #pragma unroll
        for (int t = 0; t < 4; t++) {
            int id = tid + t * 256;
            int m = id >> 3, ch = id & 7;
            size_t go = (size_t)(by * 128 + m) * Ka2 + (size_t)c * 32 + ch * 4;
            uint32_t sa = stb + m * 128 + ((ch ^ (m & 7)) << 4);
            cpasync16(sa, Ah + go);
            cpasync16(sa + 16384, Al + go);
        }
        #pragma unroll
        for (int t = 0; t < 4; t++) {
            int id = tid + t * 256;
            int k = id >> 4, ch = id & 15;
            size_t go = (size_t)(c * 64 + k) * Nb2 + (size_t)bx * 64 + ch * 4;
            cpasync16(stb + 32768 + k * 256 + ((ch ^ (k & 15)) << 4), Bh + go);
        }
    };

    float acc[4][4][4];
    #pragma unroll
    for (int i = 0; i < 4; i++)
        #pragma unroll
        for (int j = 0; j < 4; j++)
            #pragma unroll
            for (int r = 0; r < 4; r++) acc[i][j][r] = 0.f;

    load_stage(0, 0); CP_COMMIT();
    if (nc > 1) load_stage(1, 1);
    CP_COMMIT();
    if (nc > 2) load_stage(2, 2);
    CP_COMMIT();

    const int q = lane >> 3, l7 = lane & 7;

    for (int c = 0; c < nc; ++c) {
        CP_WAIT2();
        __syncthreads();
        if (c + 3 < nc) load_stage((c + 3) & 3, c + 3);
        CP_COMMIT();

        const uint32_t stb = sb + (c & 3) * 49152;
        #pragma unroll
        for (int ks = 0; ks < 4; ks++) {
            uint32_t aH[4][4], aL[4][4], bH4[2][4];
            #pragma unroll
            for (int i = 0; i < 4; i++) {
                int m = wm * 64 + i * 16 + ((q & 1) << 3) + l7;
                int ch = 2 * ks + (q >> 1);
                uint32_t ad = stb + m * 128 + ((ch ^ (m & 7)) << 4);
                ldm_x4(aH[i], ad);
                ldm_x4(aL[i], ad + 16384);
            }
            #pragma unroll
            for (int g = 0; g < 2; g++) {
                int k = ks * 16 + ((q & 1) << 3) + l7;
                int ch = wn * 4 + g * 2 + (q >> 1);
                ldm_x4_t(bH4[g], stb + 32768 + k * 256 + ((ch ^ (k & 15)) << 4));
            }
            #pragma unroll
            for (int i = 0; i < 4; i++)
                #pragma unroll
                for (int j = 0; j < 4; j++) {
                    const uint32_t* bh = &bH4[j >> 1][(j & 1) * 2];
                    mma16816(acc[i][j], aH[i], bh);
                    mma16816(acc[i][j], aL[i], bh);
                }
        }
    }

    __syncthreads();
    float* Cs = (float*)smc;
    #pragma unroll
    for (int i = 0; i < 4; i++)
        #pragma unroll
        for (int j = 0; j < 4; j++) {
            int r0 = wm * 64 + i * 16 + (lane >> 2);
            int c0 = wn * 32 + j * 8 + 2 * (lane & 3);
            *(float2*)(Cs + r0 * 132 + c0)       = make_float2(acc[i][j][0], acc[i][j][1]);
            *(float2*)(Cs + (r0 + 8) * 132 + c0) = make_float2(acc[i][j][2], acc[i][j][3]);
        }
    __syncthreads();

    #pragma unroll
    for (int i = 0; i < 16; i++) {
        int u = tid + 256 * i;
        int row = u >> 5, c4 = (u & 31) * 4;
        float4 v = *(float4*)(Cs + row * 132 + c4);
        v.x *= alpha; v.y *= alpha; v.z *= alpha; v.w *= alpha;
        int gc = bx * 128 + c4;
        size_t gm = (size_t)by * 128 + row;
        if (EPI & 1) {
            float4 bb = *(const float4*)(bias + gc);
            v.x += bb.x; v.y += bb.y; v.z += bb.z; v.w += bb.w;
        }
        if (EPI & 2) { v.x = gelu1(v.x); v.y = gelu1(v.y); v.z = gelu1(v.z); v.w = gelu1(v.w); }
        if (EPI & 4) {
            float4 rr = *(const float4*)(res + gm * Nb + gc);
            v.x += rr.x; v.y += rr.y; v.z += rr.z; v.w += rr.w;
        }
        *(float4*)(outF + gm * Nb + gc) = v;
    }
}

// ================= 1-pass GEMM, BN=128, BK=64, 3-stage, 2 CTAs/SM ============
// EMIT: EM_F32 (bias/gelu/res), EM_HF (single pairs), EM_QKV (q/kT/v by bx).
template<int EMIT, int EPI>
__global__ __launch_bounds__(256, 2)
void hg1p128(const uint32_t* __restrict__ Ah, const uint32_t* __restrict__ Bh,
             const float* __restrict__ bias, const float* __restrict__ res,
             float* __restrict__ outF, uint32_t* __restrict__ outH,
             uint32_t* __restrict__ outH2, uint32_t* __restrict__ outH3,
             int Ka, int Nb, int nc, float alpha)
{
    extern __shared__ char smc[];
    const uint32_t sb = smem_u32(smc);
    const int tid = threadIdx.x, wid = tid >> 5, lane = tid & 31;
    const int wm = wid >> 2, wn = wid & 3;
    const int bx = blockIdx.x, by = blockIdx.y;

    const uint32_t Ka2 = (uint32_t)Ka >> 1, Nb2 = (uint32_t)Nb >> 1;

    auto load_stage = [&](int st, int c) {
        const uint32_t stb = sb + st * 32768;
        #pragma unroll
        for (int t = 0; t < 4; t++) {
            int id = tid + t * 256;
            int m = id >> 3, ch = id & 7;
            size_t go = (size_t)(by * 128 + m) * Ka2 + (size_t)c * 32 + ch * 4;
            cpasync16(stb + m * 128 + ((ch ^ (m & 7)) << 4), Ah + go);
        }
        #pragma unroll
        for (int t = 0; t < 4; t++) {
            int id = tid + t * 256;
            int k = id >> 4, ch = id & 15;
            size_t go = (size_t)(c * 64 + k) * Nb2 + (size_t)bx * 64 + ch * 4;
            cpasync16(stb + 16384 + k * 256 + ((ch ^ (k & 15)) << 4), Bh + go);
        }
    };

    float acc[4][4][4];
    #pragma unroll
    for (int i = 0; i < 4; i++)
        #pragma unroll
        for (int j = 0; j < 4; j++)
            #pragma unroll
            for (int r = 0; r < 4; r++) acc[i][j][r] = 0.f;

    load_stage(0, 0); CP_COMMIT();
    if (nc > 1) load_stage(1, 1);
    CP_COMMIT();

    const int q = lane >> 3, l7 = lane & 7;

    for (int c = 0; c < nc; ++c) {
        CP_WAIT1();
        __syncthreads();
        if (c + 2 < nc) load_stage((c + 2) % 3, c + 2);
        CP_COMMIT();

        const uint32_t stb = sb + (c % 3) * 32768;
        #pragma unroll
        for (int ks = 0; ks < 4; ks++) {
            uint32_t aH[4][4], bH4[2][4];
            #pragma unroll
            for (int i = 0; i < 4; i++) {
                int m = wm * 64 + i * 16 + ((q & 1) << 3) + l7;
                int ch = 2 * ks + (q >> 1);
                ldm_x4(aH[i], stb + m * 128 + ((ch ^ (m & 7)) << 4));
            }
            #pragma unroll
            for (int g = 0; g < 2; g++) {
                int k = ks * 16 + ((q & 1) << 3) + l7;
                int ch = wn * 4 + g * 2 + (q >> 1);
                ldm_x4_t(bH4[g], stb + 16384 + k * 256 + ((ch ^ (k & 15)) << 4));
            }
            #pragma unroll
            for (int i = 0; i < 4; i++)
                #pragma unroll
                for (int j = 0; j < 4; j++)
                    mma16816(acc[i][j], aH[i], &bH4[j >> 1][(j & 1) * 2]);
        }
    }

    __syncthreads();
    float* Cs = (float*)smc;
    #pragma unroll
    for (int i = 0; i < 4; i++)
        #pragma unroll
        for (int j = 0; j < 4; j++) {
            int r0 = wm * 64 + i * 16 + (lane >> 2);
            int c0 = wn * 32 + j * 8 + 2 * (lane & 3);
            *(float2*)(Cs + r0 * 132 + c0)       = make_float2(acc[i][j][0], acc[i][j][1]);
            *(float2*)(Cs + (r0 + 8) * 132 + c0) = make_float2(acc[i][j][2], acc[i][j][3]);
        }
    __syncthreads();

    if (EMIT == EM_F32) {
        #pragma unroll
        for (int i = 0; i < 16; i++) {
            int u = tid + 256 * i;
            int row = u >> 5, c4 = (u & 31) * 4;
            float4 v = *(float4*)(Cs + row * 132 + c4);
            v.x *= alpha; v.y *= alpha; v.z *= alpha; v.w *= alpha;
            int gc = bx * 128 + c4;
            size_t gm = (size_t)by * 128 + row;
            if (EPI & 1) {
                float4 bb = *(const float4*)(bias + gc);
                v.x += bb.x; v.y += bb.y; v.z += bb.z; v.w += bb.w;
            }
            if (EPI & 2) { v.x = gelu1(v.x); v.y = gelu1(v.y); v.z = gelu1(v.z); v.w = gelu1(v.w); }
            if (EPI & 4) {
                float4 rr = *(const float4*)(res + gm * Nb + gc);
                v.x += rr.x; v.y += rr.y; v.z += rr.z; v.w += rr.w;
            }
            *(float4*)(outF + gm * Nb + gc) = v;
        }
    } else if (EMIT == EM_HF) {
        #pragma unroll
        for (int i = 0; i < 32; i++) {
            int u = tid + 256 * i;
            int row = u >> 6, np = u & 63;
            float v0 = Cs[row * 132 + 2 * np]     * alpha;
            float v1 = Cs[row * 132 + 2 * np + 1] * alpha;
            int gc = bx * 128 + 2 * np;
            if (EPI & 1) { v0 += __ldg(bias + gc); v1 += __ldg(bias + gc + 1); }
            if (EPI & 2) { v0 = gelu1(v0); v1 = gelu1(v1); }
            size_t gm = (size_t)by * 128 + row;
            outH[gm * (Nb >> 1) + (size_t)bx * 64 + np] = pack2(v0, v1);
        }
    } else { // EM_QKV: bx=0 q single pairs, bx=1 kT transposed single, bx=2 v single
        if (bx == 1) {
            const int b = by >> 4;
            const int s0p = (by & 15) * 64;
            #pragma unroll
            for (int i = 0; i < 32; i++) {
                int u = tid + 256 * i;
                int d = u >> 6, sp = u & 63;
                float bb = __ldg(bias + 128 + d);
                float v0 = Cs[(2 * sp) * 132 + d]     + bb;
                float v1 = Cs[(2 * sp + 1) * 132 + d] + bb;
                outH2[(size_t)b * (DKV * SEQ / 2) + (size_t)d * (SEQ / 2) + s0p + sp] = pack2(v0, v1);
            }
        } else {
            uint32_t* oh = (bx == 0) ? outH : outH3;
            const int boff = (bx == 0) ? 0 : 256;
            #pragma unroll
            for (int i = 0; i < 32; i++) {
                int u = tid + 256 * i;
                int row = u >> 6, np = u & 63;
                float v0 = Cs[row * 132 + 2 * np]     + __ldg(bias + boff + 2 * np);
                float v1 = Cs[row * 132 + 2 * np + 1] + __ldg(bias + boff + 2 * np + 1);
                oh[((size_t)by * 128 + row) * 64 + np] = pack2(v0, v1);
            }
        }
    }
}

// ---------------- launch sequence -------------------------------------------
extern "C" void kernel_launch(void* const* d_in, const int* in_sizes, int n_in,
                              void* d_out, int out_size)
{
    const float* x     = (const float*)d_in[0];
    const float* ln1_g = (const float*)d_in[1];
    const float* ln1_b = (const float*)d_in[2];
    const float* Wq    = (const float*)d_in[3];
    const float* bq    = (const float*)d_in[4];
    const float* Wk    = (const float*)d_in[5];
    const float* bk    = (const float*)d_in[6];
    const float* Wv    = (const float*)d_in[7];
    const float* bv    = (const float*)d_in[8];
    const float* Wo    = (const float*)d_in[9];
    const float* bo    = (const float*)d_in[10];
    const float* ln2_g = (const float*)d_in[11];
    const float* ln2_b = (const float*)d_in[12];
    const float* W1    = (const float*)d_in[13];
    const float* b1    = (const float*)d_in[14];
    const float* W2    = (const float*)d_in[15];
    const float* b2    = (const float*)d_in[16];
    float* out = (float*)d_out;

    float *xnF, *yF, *bqkv;
    uint32_t *xnH,*hH,*qH,*ktH,*vH,*atH,*atL,*acH;
    uint32_t *wqkvH,*woH,*w1H,*w2H;
    cudaGetSymbolAddress((void**)&xnF, g_xnF);
    cudaGetSymbolAddress((void**)&yF,  g_yF);  cudaGetSymbolAddress((void**)&bqkv, g_bqkv);
    cudaGetSymbolAddress((void**)&xnH, g_xnH);
    cudaGetSymbolAddress((void**)&hH,  g_hH);
    cudaGetSymbolAddress((void**)&qH,  g_qH);
    cudaGetSymbolAddress((void**)&ktH, g_ktH);
    cudaGetSymbolAddress((void**)&vH,  g_vH);
    cudaGetSymbolAddress((void**)&atH, g_atH); cudaGetSymbolAddress((void**)&atL, g_atL);
    cudaGetSymbolAddress((void**)&acH, g_acH);
    cudaGetSymbolAddress((void**)&wqkvH, g_wqkvH);
    cudaGetSymbolAddress((void**)&woH, g_woH);
    cudaGetSymbolAddress((void**)&w1H, g_w1H);
    cudaGetSymbolAddress((void**)&w2H, g_w2H);

    const int SM_2P = 4 * 49152;            // 192 KB
    const int SM_1P = 3 * 32768;            // 96 KB (2 CTAs/SM)
    const int SM_FL = 32768 + 2 * 65536;    // 160 KB
    cudaFuncSetAttribute(flash_attn,        cudaFuncAttributeMaxDynamicSharedMemorySize, SM_FL);
    cudaFuncSetAttribute(hg2p<5>,           cudaFuncAttributeMaxDynamicSharedMemorySize, SM_2P);
    cudaFuncSetAttribute(hg1p128<EM_QKV,1>, cudaFuncAttributeMaxDynamicSharedMemorySize, SM_1P);
    cudaFuncSetAttribute(hg1p128<EM_HF, 3>, cudaFuncAttributeMaxDynamicSharedMemorySize, SM_1P);
    cudaFuncSetAttribute(hg1p128<EM_F32,5>, cudaFuncAttributeMaxDynamicSharedMemorySize, SM_1P);

    const float scale = 0.08838834764831845f; // 1/sqrt(128)

    // ---- 1 launch: all weight conversions (single fp16) + qkv bias pack ----
    {
        WJobs jb;
        jb.src[0] = Wq; jb.H[0] = wqkvH; jb.np[0] = DMODEL*DKV/2; jb.srcP[0] = 64;  jb.dstP[0] = 192; jb.coff[0] = 0;
        jb.src[1] = Wk; jb.H[1] = wqkvH; jb.np[1] = DMODEL*DKV/2; jb.srcP[1] = 64;  jb.dstP[1] = 192; jb.coff[1] = 64;
        jb.src[2] = Wv; jb.H[2] = wqkvH; jb.np[2] = DMODEL*DKV/2; jb.srcP[2] = 64;  jb.dstP[2] = 192; jb.coff[2] = 128;
        jb.src[3] = Wo; jb.H[3] = woH;   jb.np[3] = DKV*DMODEL/2; jb.srcP[3] = 512; jb.dstP[3] = 512; jb.coff[3] = 0;
        jb.src[4] = W1; jb.H[4] = w1H;   jb.np[4] = DMODEL*DFF/2; jb.srcP[4] = 2048;jb.dstP[4] = 2048;jb.coff[4] = 0;
        jb.src[5] = W2; jb.H[5] = w2H;   jb.np[5] = DFF*DMODEL/2; jb.srcP[5] = 512; jb.dstP[5] = 512; jb.coff[5] = 0;
        int acc_ = 0;
        for (int s = 0; s < 6; s++) { jb.blkStart[s] = acc_; acc_ += (jb.np[s] + 255) / 256; }
        jb.blkStart[6] = acc_;
        jb.bq = bq; jb.bk = bk; jb.bv = bv; jb.bqkv = bqkv;
        wconv_all<<<acc_ + 1, 256>>>(jb);
    }

    // 2) ln1 -> xn (f32 + single fp16 pairs)
    ln_frag<true, false><<<MS, 256>>>(x, ln1_g, ln1_b, xnF, xnH, nullptr);

    // 3) fused QKV (16384 x 384 x 1024) [1-pass, 2 CTA/SM]: bx=0 q, 1 kT, 2 v
    hg1p128<EM_QKV, 1><<<dim3(3,128,1), 256, SM_1P>>>(xnH, wqkvH, bqkv, nullptr,
        nullptr, qH, ktH, vH, DMODEL, 384, 16, 1.f);

    // 4) flash attention (QK 1-pass, PV 1-pass) -> att split pairs
    flash_attn<<<dim3(SEQ/128, BATCH), 256, SM_FL>>>(qH, ktH, vH, atH, atL, scale);

    // 5) y = xn + att@Wo + bo (16384x1024x128) [2-pass, BN=128, 1024 CTAs]
    hg2p<5><<<dim3(8,128,1), 256, SM_2P>>>(atH, atL, woH, bo, xnF,
        yF, DKV, DMODEL, 2, 1.f);

    // 6) ln2 -> h single pairs
    ln_frag<false, false><<<MS, 256>>>(yF, ln2_g, ln2_b, nullptr, hH, nullptr);

    // 7) act = gelu(h@W1 + b1) (16384x4096x1024) [1-pass, 2 CTA/SM]
    hg1p128<EM_HF, 3><<<dim3(32,128,1), 256, SM_1P>>>(hH, w1H, b1, nullptr,
        nullptr, acH, nullptr, nullptr, DMODEL, DFF, 16, 1.f);

    // 8) out = y + act@W2 + b2 (16384x1024x4096) [1-pass, 2 CTA/SM]
    hg1p128<EM_F32, 5><<<dim3(8,128,1), 256, SM_1P>>>(acH, w2H, b2, yF,
        out, nullptr, nullptr, nullptr, DFF, DMODEL, 64, 1.f);
}

// round 11
// speedup vs baseline: 7.5850x; 1.0587x over previous
#include <cuda_runtime.h>
#include <cuda_fp16.h>
#include <math.h>
#include <stdint.h>

#define BATCH 8
#define SEQ   2048
#define DMODEL 1024
#define DKV   128
#define DFF   4096
#define MS    (BATCH*SEQ)

// ---------------- scratch (static device globals) ----------------------------
__device__ float    g_xnF[(size_t)MS*DMODEL];
__device__ float    g_yF [(size_t)MS*DMODEL];

__device__ uint32_t g_xnH[(size_t)MS*DMODEL/2];
__device__ uint32_t g_hH [(size_t)MS*DMODEL/2];
__device__ uint32_t g_qH [(size_t)MS*DKV/2];
__device__ uint32_t g_ktH[(size_t)BATCH*DKV*SEQ/2];
__device__ uint32_t g_vH [(size_t)MS*DKV/2];
__device__ uint32_t g_atH[(size_t)MS*DKV/2];
__device__ uint32_t g_acH[(size_t)MS*DFF/2];

__device__ uint32_t g_wqkvH[(size_t)DMODEL*384/2];
__device__ float    g_bqkv[384];
__device__ uint32_t g_woH[(size_t)DKV*DMODEL/2];
__device__ uint32_t g_w1H[(size_t)DMODEL*DFF/2];
__device__ uint32_t g_w2H[(size_t)DFF*DMODEL/2];

// ---------------- helpers ----------------------------------------------------
__device__ __forceinline__ uint32_t smem_u32(const void* p) {
    uint32_t a;
    asm("{ .reg .u64 t; cvta.to.shared.u64 t, %1; cvt.u32.u64 %0, t; }" : "=r"(a) : "l"(p));
    return a;
}
__device__ __forceinline__ void cpasync16(uint32_t dst, const void* src) {
    asm volatile("cp.async.cg.shared.global [%0], [%1], 16;" :: "r"(dst), "l"(src));
}
#define CP_COMMIT() asm volatile("cp.async.commit_group;" ::: "memory")
#define CP_WAIT1()  asm volatile("cp.async.wait_group 1;" ::: "memory")

__device__ __forceinline__ void ldm_x4(uint32_t r[4], uint32_t addr) {
    asm volatile("ldmatrix.sync.aligned.m8n8.x4.shared.b16 {%0,%1,%2,%3}, [%4];"
                 : "=r"(r[0]), "=r"(r[1]), "=r"(r[2]), "=r"(r[3]) : "r"(addr));
}
__device__ __forceinline__ void ldm_x4_t(uint32_t r[4], uint32_t addr) {
    asm volatile("ldmatrix.sync.aligned.m8n8.x4.trans.shared.b16 {%0,%1,%2,%3}, [%4];"
                 : "=r"(r[0]), "=r"(r[1]), "=r"(r[2]), "=r"(r[3]) : "r"(addr));
}
__device__ __forceinline__ void mma16816(float c[4], const uint32_t a[4], const uint32_t b[2]) {
    asm volatile("mma.sync.aligned.m16n8k16.row.col.f32.f16.f16.f32 "
                 "{%0,%1,%2,%3},{%4,%5,%6,%7},{%8,%9},{%0,%1,%2,%3};"
                 : "+f"(c[0]), "+f"(c[1]), "+f"(c[2]), "+f"(c[3])
                 : "r"(a[0]), "r"(a[1]), "r"(a[2]), "r"(a[3]), "r"(b[0]), "r"(b[1]));
}
__device__ __forceinline__ uint32_t packh(__half a, __half b) {
    return (uint32_t)__half_as_ushort(a) | ((uint32_t)__half_as_ushort(b) << 16);
}
__device__ __forceinline__ uint32_t pack2(float a, float b) {
    return packh(__float2half_rn(a), __float2half_rn(b));
}
__device__ __forceinline__ float gelu1(float v) {
    return 0.5f * v * (1.0f + erff(v * 0.70710678118654752f));
}

// ---------------- one-shot weight conversion ---------------------------------
struct WJobs {
    const float* src[6];
    uint32_t* H[6];
    int np[6];
    int srcP[6];
    int dstP[6];
    int coff[6];
    int blkStart[7];
    const float* bq; const float* bk; const float* bv;
    float* bqkv;
};

__global__ __launch_bounds__(256) void wconv_all(WJobs jb)
{
    const int blk = blockIdx.x, tid = threadIdx.x;
    if (blk >= jb.blkStart[6]) {
        if (tid < 128) {
            jb.bqkv[tid]       = jb.bq[tid];
            jb.bqkv[128 + tid] = jb.bk[tid];
            jb.bqkv[256 + tid] = jb.bv[tid];
        }
        return;
    }
    int seg = 0;
    #pragma unroll
    for (int s = 1; s < 6; s++) if (blk >= jb.blkStart[s]) seg = s;
    int u = (blk - jb.blkStart[seg]) * 256 + tid;
    if (u >= jb.np[seg]) return;
    int k = u / jb.srcP[seg], p = u - k * jb.srcP[seg];
    float2 v = *(const float2*)(jb.src[seg] + ((size_t)u) * 2);
    jb.H[seg][(size_t)k * jb.dstP[seg] + jb.coff[seg] + p] = pack2(v.x, v.y);
}

// ---------------- LayerNorm ---------------------------------------------------
template<bool WF32>
__global__ __launch_bounds__(256) void ln_frag(const float* __restrict__ x,
                                               const float* __restrict__ g,
                                               const float* __restrict__ b,
                                               float* __restrict__ oF,
                                               uint32_t* __restrict__ H)
{
    const int row = blockIdx.x;
    const int tid = threadIdx.x;
    const float* xr = x + (size_t)row * DMODEL;
    float4 v = *(const float4*)(xr + tid * 4);

    float s  = v.x + v.y + v.z + v.w;
    float s2 = v.x*v.x + v.y*v.y + v.z*v.z + v.w*v.w;
    #pragma unroll
    for (int off = 16; off; off >>= 1) {
        s  += __shfl_xor_sync(0xffffffffu, s,  off);
        s2 += __shfl_xor_sync(0xffffffffu, s2, off);
    }
    __shared__ float ss[8], ss2[8], stats[2];
    const int wid = tid >> 5, lane = tid & 31;
    if (lane == 0) { ss[wid] = s; ss2[wid] = s2; }
    __syncthreads();
    if (wid == 0) {
        s  = (lane < 8) ? ss[lane]  : 0.f;
        s2 = (lane < 8) ? ss2[lane] : 0.f;
        #pragma unroll
        for (int off = 4; off; off >>= 1) {
            s  += __shfl_xor_sync(0xffffffffu, s,  off);
            s2 += __shfl_xor_sync(0xffffffffu, s2, off);
        }
        if (lane == 0) {
            float mean = s * (1.0f / DMODEL);
            float var  = s2 * (1.0f / DMODEL) - mean * mean;
            stats[0] = mean;
            stats[1] = rsqrtf(var + 1e-5f);
        }
    }
    __syncthreads();
    const float mean = stats[0], rstd = stats[1];
    float4 gg = *(const float4*)(g + tid * 4);
    float4 bb = *(const float4*)(b + tid * 4);
    float4 o;
    o.x = (v.x - mean) * rstd * gg.x + bb.x;
    o.y = (v.y - mean) * rstd * gg.y + bb.y;
    o.z = (v.z - mean) * rstd * gg.z + bb.z;
    o.w = (v.w - mean) * rstd * gg.w + bb.w;
    if (WF32) *(float4*)(oF + (size_t)row * DMODEL + tid * 4) = o;
    size_t base = (size_t)row * (DMODEL / 2) + tid * 2;
    H[base]     = pack2(o.x, o.y);
    H[base + 1] = pack2(o.z, o.w);
}

#define EM_F32 0
#define EM_QKV 3
#define EM_HF  4

// ================= flash attention: 64-row Q tiles, 64-col KV tiles ==========
// 128 threads, 4 warps x 16 q rows. Q 16KB; KV double-buffered 2x32KB. 2 CTAs/SM.
__global__ __launch_bounds__(128, 2)
void flash_attn(const uint32_t* __restrict__ qH,
                const uint32_t* __restrict__ ktH, const uint32_t* __restrict__ vH,
                uint32_t* __restrict__ atH, float scl2)
{
    extern __shared__ char smc[];
    const uint32_t sb = smem_u32(smc);
    const int tid = threadIdx.x, wid = tid >> 5, lane = tid & 31;
    const int q = lane >> 3, l7 = lane & 7;
    const int b = blockIdx.y, qt = blockIdx.x;

    auto load_q = [&] {
        #pragma unroll
        for (int t = 0; t < 8; t++) {
            int id = tid + t * 128;
            int m = id >> 4, ch = id & 15;
            cpasync16(sb + m * 256 + ((ch ^ (m & 15)) << 4),
                      qH + ((size_t)(b * 2048 + qt * 64 + m)) * 64 + ch * 4);
        }
    };
    auto load_kv = [&](int st, int j) {
        const uint32_t stb = sb + 16384 + st * 32768;
        #pragma unroll
        for (int t = 0; t < 8; t++) {          // K: 128 d-rows x 64 s (128B rows)
            int id = tid + t * 128;
            int d = id >> 3, ch = id & 7;
            cpasync16(stb + d * 128 + ((ch ^ (d & 7)) << 4),
                      ktH + ((size_t)b * 128 + d) * 1024 + j * 32 + ch * 4);
        }
        #pragma unroll
        for (int t = 0; t < 8; t++) {          // V: 64 s-rows x 128 d (256B rows)
            int id = tid + t * 128;
            int s = id >> 4, ch = id & 15;
            cpasync16(stb + 16384 + s * 256 + ((ch ^ (s & 15)) << 4),
                      vH + ((size_t)(b * 2048 + j * 64 + s)) * 64 + ch * 4);
        }
    };

    load_q(); load_kv(0, 0); CP_COMMIT();
    load_kv(1, 1); CP_COMMIT();

    float oa[16][4];
    #pragma unroll
    for (int jd = 0; jd < 16; jd++)
        #pragma unroll
        for (int r = 0; r < 4; r++) oa[jd][r] = 0.f;
    float m0 = -1e30f, m1 = -1e30f, l0 = 0.f, l1 = 0.f;

    for (int j = 0; j < 32; ++j) {
        CP_WAIT1();
        __syncthreads();
        const uint32_t stb = sb + 16384 + (j & 1) * 32768;

        // ---- S = q @ kT (1-pass), 16q x 64s per warp ----
        float sa[8][4];
        #pragma unroll
        for (int jn = 0; jn < 8; jn++)
            #pragma unroll
            for (int r = 0; r < 4; r++) sa[jn][r] = 0.f;

        #pragma unroll
        for (int ks = 0; ks < 8; ks++) {
            uint32_t aH4[4];
            int m = wid * 16 + ((q & 1) << 3) + l7;
            int ch = 2 * ks + (q >> 1);
            ldm_x4(aH4, sb + m * 256 + ((ch ^ (m & 15)) << 4));
            #pragma unroll
            for (int g = 0; g < 4; g++) {
                uint32_t b4[4];
                int k = ks * 16 + ((q & 1) << 3) + l7;
                int bch = g * 2 + (q >> 1);
                ldm_x4_t(b4, stb + k * 128 + ((bch ^ (k & 7)) << 4));
                mma16816(sa[2 * g],     aH4, &b4[0]);
                mma16816(sa[2 * g + 1], aH4, &b4[2]);
            }
        }

        // ---- online softmax (base-2 domain) ----
        float mx0 = -1e30f, mx1 = -1e30f;
        #pragma unroll
        for (int jn = 0; jn < 8; jn++) {
            sa[jn][0] *= scl2; sa[jn][1] *= scl2;
            sa[jn][2] *= scl2; sa[jn][3] *= scl2;
            mx0 = fmaxf(mx0, fmaxf(sa[jn][0], sa[jn][1]));
            mx1 = fmaxf(mx1, fmaxf(sa[jn][2], sa[jn][3]));
        }
        mx0 = fmaxf(mx0, __shfl_xor_sync(0xffffffffu, mx0, 1));
        mx0 = fmaxf(mx0, __shfl_xor_sync(0xffffffffu, mx0, 2));
        mx1 = fmaxf(mx1, __shfl_xor_sync(0xffffffffu, mx1, 1));
        mx1 = fmaxf(mx1, __shfl_xor_sync(0xffffffffu, mx1, 2));

        float mn0 = fmaxf(m0, mx0), mn1 = fmaxf(m1, mx1);
        float c0 = exp2f(m0 - mn0), c1 = exp2f(m1 - mn1);
        m0 = mn0; m1 = mn1;

        float rs0 = 0.f, rs1 = 0.f;
        #pragma unroll
        for (int jn = 0; jn < 8; jn++) {
            sa[jn][0] = exp2f(sa[jn][0] - mn0);
            sa[jn][1] = exp2f(sa[jn][1] - mn0);
            sa[jn][2] = exp2f(sa[jn][2] - mn1);
            sa[jn][3] = exp2f(sa[jn][3] - mn1);
            rs0 += sa[jn][0] + sa[jn][1];
            rs1 += sa[jn][2] + sa[jn][3];
        }
        rs0 += __shfl_xor_sync(0xffffffffu, rs0, 1);
        rs0 += __shfl_xor_sync(0xffffffffu, rs0, 2);
        rs1 += __shfl_xor_sync(0xffffffffu, rs1, 1);
        rs1 += __shfl_xor_sync(0xffffffffu, rs1, 2);
        l0 = l0 * c0 + rs0;
        l1 = l1 * c1 + rs1;
        #pragma unroll
        for (int jd = 0; jd < 16; jd++) {
            oa[jd][0] *= c0; oa[jd][1] *= c0;
            oa[jd][2] *= c1; oa[jd][3] *= c1;
        }

        // ---- PV (1-pass fp16 P), contraction over 64 s ----
        #pragma unroll
        for (int t = 0; t < 4; t++) {
            uint32_t pa[4];
            pa[0] = pack2(sa[2 * t][0],     sa[2 * t][1]);
            pa[1] = pack2(sa[2 * t][2],     sa[2 * t][3]);
            pa[2] = pack2(sa[2 * t + 1][0], sa[2 * t + 1][1]);
            pa[3] = pack2(sa[2 * t + 1][2], sa[2 * t + 1][3]);
            int k = t * 16 + ((q & 1) << 3) + l7;
            #pragma unroll
            for (int g = 0; g < 8; g++) {
                uint32_t b4[4];
                int bch = g * 2 + (q >> 1);
                ldm_x4_t(b4, stb + 16384 + k * 256 + ((bch ^ (k & 15)) << 4));
                mma16816(oa[2 * g],     pa, &b4[0]);
                mma16816(oa[2 * g + 1], pa, &b4[2]);
            }
        }

        __syncthreads();
        if (j + 2 < 32) load_kv(j & 1, j + 2);
        CP_COMMIT();
    }

    // ---- finalize + emit att single fp16 pairs ----
    const float i0 = 1.0f / l0, i1 = 1.0f / l1;
    const size_t row0 = (size_t)(b * 2048 + qt * 64 + wid * 16 + (lane >> 2));
    const int qc = lane & 3;
    #pragma unroll
    for (int jd = 0; jd < 16; jd++) {
        atH[row0 * 64 + 4 * jd + qc]       = pack2(oa[jd][0] * i0, oa[jd][1] * i0);
        atH[(row0 + 8) * 64 + 4 * jd + qc] = pack2(oa[jd][2] * i1, oa[jd][3] * i1);
    }
}

// ================= 1-pass GEMM, 128 thr, warp 64x64, BM=BN=128, 2 CTAs/SM ====
template<int EMIT, int EPI>
__global__ __launch_bounds__(128, 2)
void hg1pW(const uint32_t* __restrict__ Ah, const uint32_t* __restrict__ Bh,
           const float* __restrict__ bias, const float* __restrict__ res,
           float* __restrict__ outF, uint32_t* __restrict__ outH,
           int Ka, int Nb, int nc, float alpha)
{
    extern __shared__ char smc[];
    const uint32_t sb = smem_u32(smc);
    const int tid = threadIdx.x, wid = tid >> 5, lane = tid & 31;
    const int wm = wid >> 1, wn = wid & 1;
    const int bx = blockIdx.x, by = blockIdx.y;

    const uint32_t Ka2 = (uint32_t)Ka >> 1, Nb2 = (uint32_t)Nb >> 1;

    // stage 32KB: A@0 16K (128 rows x 128B) | B@16K 16K (64 k-rows x 256B). 3 stages.
    auto load_stage = [&](int st, int c) {
        const uint32_t stb = sb + st * 32768;
        #pragma unroll
        for (int t = 0; t < 8; t++) {
            int id = tid + t * 128;
            int m = id >> 3, ch = id & 7;
            size_t go = (size_t)(by * 128 + m) * Ka2 + (size_t)c * 32 + ch * 4;
            cpasync16(stb + m * 128 + ((ch ^ (m & 7)) << 4), Ah + go);
        }
        #pragma unroll
        for (int t = 0; t < 8; t++) {
            int id = tid + t * 128;
            int k = id >> 4, ch = id & 15;
            size_t go = (size_t)(c * 64 + k) * Nb2 + (size_t)bx * 64 + ch * 4;
            cpasync16(stb + 16384 + k * 256 + ((ch ^ (k & 15)) << 4), Bh + go);
        }
    };

    float acc[4][8][4];
    #pragma unroll
    for (int i = 0; i < 4; i++)
        #pragma unroll
        for (int j = 0; j < 8; j++)
            #pragma unroll
            for (int r = 0; r < 4; r++) acc[i][j][r] = 0.f;

    load_stage(0, 0); CP_COMMIT();
    if (nc > 1) load_stage(1, 1);
    CP_COMMIT();

    const int q = lane >> 3, l7 = lane & 7;

    for (int c = 0; c < nc; ++c) {
        CP_WAIT1();
        __syncthreads();
        if (c + 2 < nc) load_stage((c + 2) % 3, c + 2);
        CP_COMMIT();

        const uint32_t stb = sb + (c % 3) * 32768;
        #pragma unroll
        for (int ks = 0; ks < 4; ks++) {
            uint32_t aH[4][4];
            #pragma unroll
            for (int i = 0; i < 4; i++) {
                int m = wm * 64 + i * 16 + ((q & 1) << 3) + l7;
                int ch = 2 * ks + (q >> 1);
                ldm_x4(aH[i], stb + m * 128 + ((ch ^ (m & 7)) << 4));
            }
            #pragma unroll
            for (int g = 0; g < 4; g++) {
                uint32_t bH4[4];
                int k = ks * 16 + ((q & 1) << 3) + l7;
                int ch = wn * 8 + g * 2 + (q >> 1);
                ldm_x4_t(bH4, stb + 16384 + k * 256 + ((ch ^ (k & 15)) << 4));
                #pragma unroll
                for (int i = 0; i < 4; i++) {
                    mma16816(acc[i][g * 2 + 0], aH[i], &bH4[0]);
                    mma16816(acc[i][g * 2 + 1], aH[i], &bH4[2]);
                }
            }
        }
    }

    __syncthreads();
    float* Cs = (float*)smc;
    #pragma unroll
    for (int i = 0; i < 4; i++)
        #pragma unroll
        for (int j = 0; j < 8; j++) {
            int r0 = wm * 64 + i * 16 + (lane >> 2);
            int c0 = wn * 64 + j * 8 + 2 * (lane & 3);
            *(float2*)(Cs + r0 * 132 + c0)       = make_float2(acc[i][j][0], acc[i][j][1]);
            *(float2*)(Cs + (r0 + 8) * 132 + c0) = make_float2(acc[i][j][2], acc[i][j][3]);
        }
    __syncthreads();

    if (EMIT == EM_F32) {
        #pragma unroll
        for (int i = 0; i < 32; i++) {
            int u = tid + 128 * i;
            int row = u >> 5, c4 = (u & 31) * 4;
            float4 v = *(float4*)(Cs + row * 132 + c4);
            v.x *= alpha; v.y *= alpha; v.z *= alpha; v.w *= alpha;
            int gc = bx * 128 + c4;
            size_t gm = (size_t)by * 128 + row;
            if (EPI & 1) {
                float4 bb = *(const float4*)(bias + gc);
                v.x += bb.x; v.y += bb.y; v.z += bb.z; v.w += bb.w;
            }
            if (EPI & 2) { v.x = gelu1(v.x); v.y = gelu1(v.y); v.z = gelu1(v.z); v.w = gelu1(v.w); }
            if (EPI & 4) {
                float4 rr = *(const float4*)(res + gm * Nb + gc);
                v.x += rr.x; v.y += rr.y; v.z += rr.z; v.w += rr.w;
            }
            *(float4*)(outF + gm * Nb + gc) = v;
        }
    } else { // EM_HF
        #pragma unroll
        for (int i = 0; i < 64; i++) {
            int u = tid + 128 * i;
            int row = u >> 6, np = u & 63;
            float v0 = Cs[row * 132 + 2 * np]     * alpha;
            float v1 = Cs[row * 132 + 2 * np + 1] * alpha;
            int gc = bx * 128 + 2 * np;
            if (EPI & 1) { v0 += __ldg(bias + gc); v1 += __ldg(bias + gc + 1); }
            if (EPI & 2) { v0 = gelu1(v0); v1 = gelu1(v1); }
            size_t gm = (size_t)by * 128 + row;
            outH[gm * (Nb >> 1) + (size_t)bx * 64 + np] = pack2(v0, v1);
        }
    }
}

// ================= 1-pass QKV GEMM, 256 thr, 2 CTAs/SM =======================
__global__ __launch_bounds__(256, 2)
void hgqkv(const uint32_t* __restrict__ Ah, const uint32_t* __restrict__ Bh,
           const float* __restrict__ bias,
           uint32_t* __restrict__ outQ, uint32_t* __restrict__ outKT,
           uint32_t* __restrict__ outV,
           int Ka, int Nb, int nc)
{
    extern __shared__ char smc[];
    const uint32_t sb = smem_u32(smc);
    const int tid = threadIdx.x, wid = tid >> 5, lane = tid & 31;
    const int wm = wid >> 2, wn = wid & 3;
    const int bx = blockIdx.x, by = blockIdx.y;

    const uint32_t Ka2 = (uint32_t)Ka >> 1, Nb2 = (uint32_t)Nb >> 1;

    auto load_stage = [&](int st, int c) {
        const uint32_t stb = sb + st * 32768;
        #pragma unroll
        for (int t = 0; t < 4; t++) {
            int id = tid + t * 256;
            int m = id >> 3, ch = id & 7;
            size_t go = (size_t)(by * 128 + m) * Ka2 + (size_t)c * 32 + ch * 4;
            cpasync16(stb + m * 128 + ((ch ^ (m & 7)) << 4), Ah + go);
        }
        #pragma unroll
        for (int t = 0; t < 4; t++) {
            int id = tid + t * 256;
            int k = id >> 4, ch = id & 15;
            size_t go = (size_t)(c * 64 + k) * Nb2 + (size_t)bx * 64 + ch * 4;
            cpasync16(stb + 16384 + k * 256 + ((ch ^ (k & 15)) << 4), Bh + go);
        }
    };

    float acc[4][4][4];
    #pragma unroll
    for (int i = 0; i < 4; i++)
        #pragma unroll
        for (int j = 0; j < 4; j++)
            #pragma unroll
            for (int r = 0; r < 4; r++) acc[i][j][r] = 0.f;

    load_stage(0, 0); CP_COMMIT();
    load_stage(1, 1); CP_COMMIT();

    const int q = lane >> 3, l7 = lane & 7;

    for (int c = 0; c < nc; ++c) {
        CP_WAIT1();
        __syncthreads();
        if (c + 2 < nc) load_stage((c + 2) % 3, c + 2);
        CP_COMMIT();

        const uint32_t stb = sb + (c % 3) * 32768;
        #pragma unroll
        for (int ks = 0; ks < 4; ks++) {
            uint32_t aH[4][4], bH4[2][4];
            #pragma unroll
            for (int i = 0; i < 4; i++) {
                int m = wm * 64 + i * 16 + ((q & 1) << 3) + l7;
                int ch = 2 * ks + (q >> 1);
                ldm_x4(aH[i], stb + m * 128 + ((ch ^ (m & 7)) << 4));
            }
            #pragma unroll
            for (int g = 0; g < 2; g++) {
                int k = ks * 16 + ((q & 1) << 3) + l7;
                int ch = wn * 4 + g * 2 + (q >> 1);
                ldm_x4_t(bH4[g], stb + 16384 + k * 256 + ((ch ^ (k & 15)) << 4));
            }
            #pragma unroll
            for (int i = 0; i < 4; i++)
                #pragma unroll
                for (int j = 0; j < 4; j++)
                    mma16816(acc[i][j], aH[i], &bH4[j >> 1][(j & 1) * 2]);
        }
    }

    __syncthreads();
    float* Cs = (float*)smc;
    #pragma unroll
    for (int i = 0; i < 4; i++)
        #pragma unroll
        for (int j = 0; j < 4; j++) {
            int r0 = wm * 64 + i * 16 + (lane >> 2);
            int c0 = wn * 32 + j * 8 + 2 * (lane & 3);
            *(float2*)(Cs + r0 * 132 + c0)       = make_float2(acc[i][j][0], acc[i][j][1]);
            *(float2*)(Cs + (r0 + 8) * 132 + c0) = make_float2(acc[i][j][2], acc[i][j][3]);
        }
    __syncthreads();

    if (bx == 1) {            // kT transposed emit
        const int b = by >> 4;
        const int s0p = (by & 15) * 64;
        #pragma unroll
        for (int i = 0; i < 32; i++) {
            int u = tid + 256 * i;
            int d = u >> 6, sp = u & 63;
            float bb = __ldg(bias + 128 + d);
            float v0 = Cs[(2 * sp) * 132 + d]     + bb;
            float v1 = Cs[(2 * sp + 1) * 132 + d] + bb;
            outKT[(size_t)b * (DKV * SEQ / 2) + (size_t)d * (SEQ / 2) + s0p + sp] = pack2(v0, v1);
        }
    } else {
        uint32_t* oh = (bx == 0) ? outQ : outV;
        const int boff = (bx == 0) ? 0 : 256;
        #pragma unroll
        for (int i = 0; i < 32; i++) {
            int u = tid + 256 * i;
            int row = u >> 6, np = u & 63;
            float v0 = Cs[row * 132 + 2 * np]     + __ldg(bias + boff + 2 * np);
            float v1 = Cs[row * 132 + 2 * np + 1] + __ldg(bias + boff + 2 * np + 1);
            oh[((size_t)by * 128 + row) * 64 + np] = pack2(v0, v1);
        }
    }
}

// ---------------- launch sequence -------------------------------------------
extern "C" void kernel_launch(void* const* d_in, const int* in_sizes, int n_in,
                              void* d_out, int out_size)
{
    const float* x     = (const float*)d_in[0];
    const float* ln1_g = (const float*)d_in[1];
    const float* ln1_b = (const float*)d_in[2];
    const float* Wq    = (const float*)d_in[3];
    const float* bq    = (const float*)d_in[4];
    const float* Wk    = (const float*)d_in[5];
    const float* bk    = (const float*)d_in[6];
    const float* Wv    = (const float*)d_in[7];
    const float* bv    = (const float*)d_in[8];
    const float* Wo    = (const float*)d_in[9];
    const float* bo    = (const float*)d_in[10];
    const float* ln2_g = (const float*)d_in[11];
    const float* ln2_b = (const float*)d_in[12];
    const float* W1    = (const float*)d_in[13];
    const float* b1    = (const float*)d_in[14];
    const float* W2    = (const float*)d_in[15];
    const float* b2    = (const float*)d_in[16];
    float* out = (float*)d_out;

    float *xnF, *yF, *bqkv;
    uint32_t *xnH,*hH,*qH,*ktH,*vH,*atH,*acH;
    uint32_t *wqkvH,*woH,*w1H,*w2H;
    cudaGetSymbolAddress((void**)&xnF, g_xnF);
    cudaGetSymbolAddress((void**)&yF,  g_yF);  cudaGetSymbolAddress((void**)&bqkv, g_bqkv);
    cudaGetSymbolAddress((void**)&xnH, g_xnH);
    cudaGetSymbolAddress((void**)&hH,  g_hH);
    cudaGetSymbolAddress((void**)&qH,  g_qH);
    cudaGetSymbolAddress((void**)&ktH, g_ktH);
    cudaGetSymbolAddress((void**)&vH,  g_vH);
    cudaGetSymbolAddress((void**)&atH, g_atH);
    cudaGetSymbolAddress((void**)&acH, g_acH);
    cudaGetSymbolAddress((void**)&wqkvH, g_wqkvH);
    cudaGetSymbolAddress((void**)&woH, g_woH);
    cudaGetSymbolAddress((void**)&w1H, g_w1H);
    cudaGetSymbolAddress((void**)&w2H, g_w2H);

    const int SM_1P = 3 * 32768;            // 96 KB
    const int SM_FL = 16384 + 2 * 32768;    // 80 KB
    cudaFuncSetAttribute(flash_attn,       cudaFuncAttributeMaxDynamicSharedMemorySize, SM_FL);
    cudaFuncSetAttribute(hgqkv,            cudaFuncAttributeMaxDynamicSharedMemorySize, SM_1P);
    cudaFuncSetAttribute(hg1pW<EM_F32,5>,  cudaFuncAttributeMaxDynamicSharedMemorySize, SM_1P);
    cudaFuncSetAttribute(hg1pW<EM_HF, 3>,  cudaFuncAttributeMaxDynamicSharedMemorySize, SM_1P);

    const float scl2 = 0.08838834764831845f * 1.4426950408889634f; // scale*log2(e)

    // ---- weight conversions ----
    {
        WJobs jb;
        jb.src[0] = Wq; jb.H[0] = wqkvH; jb.np[0] = DMODEL*DKV/2; jb.srcP[0] = 64;  jb.dstP[0] = 192; jb.coff[0] = 0;
        jb.src[1] = Wk; jb.H[1] = wqkvH; jb.np[1] = DMODEL*DKV/2; jb.srcP[1] = 64;  jb.dstP[1] = 192; jb.coff[1] = 64;
        jb.src[2] = Wv; jb.H[2] = wqkvH; jb.np[2] = DMODEL*DKV/2; jb.srcP[2] = 64;  jb.dstP[2] = 192; jb.coff[2] = 128;
        jb.src[3] = Wo; jb.H[3] = woH;   jb.np[3] = DKV*DMODEL/2; jb.srcP[3] = 512; jb.dstP[3] = 512; jb.coff[3] = 0;
        jb.src[4] = W1; jb.H[4] = w1H;   jb.np[4] = DMODEL*DFF/2; jb.srcP[4] = 2048;jb.dstP[4] = 2048;jb.coff[4] = 0;
        jb.src[5] = W2; jb.H[5] = w2H;   jb.np[5] = DFF*DMODEL/2; jb.srcP[5] = 512; jb.dstP[5] = 512; jb.coff[5] = 0;
        int acc_ = 0;
        for (int s = 0; s < 6; s++) { jb.blkStart[s] = acc_; acc_ += (jb.np[s] + 255) / 256; }
        jb.blkStart[6] = acc_;
        jb.bq = bq; jb.bk = bk; jb.bv = bv; jb.bqkv = bqkv;
        wconv_all<<<acc_ + 1, 256>>>(jb);
    }

    // 2) ln1 -> xn (f32 + single fp16 pairs)
    ln_frag<true><<<MS, 256>>>(x, ln1_g, ln1_b, xnF, xnH);

    // 3) fused QKV (16384 x 384 x 1024): bx=0 q, 1 kT, 2 v
    hgqkv<<<dim3(3,128,1), 256, SM_1P>>>(xnH, wqkvH, bqkv, qH, ktH, vH, DMODEL, 384, 16);

    // 4) flash attention (64-row tiles, 2 CTA/SM, 256 CTAs) -> att single fp16
    flash_attn<<<dim3(SEQ/64, BATCH), 128, SM_FL>>>(qH, ktH, vH, atH, scl2);

    // 5) y = xn + att@Wo + bo (16384x1024x128) [1-pass]
    hg1pW<EM_F32, 5><<<dim3(8,128,1), 128, SM_1P>>>(atH, woH, bo, xnF,
        yF, nullptr, DKV, DMODEL, 2, 1.f);

    // 6) ln2 -> h single pairs
    ln_frag<false><<<MS, 256>>>(yF, ln2_g, ln2_b, nullptr, hH);

    // 7) act = gelu(h@W1 + b1) (16384x4096x1024) [1-pass]
    hg1pW<EM_HF, 3><<<dim3(32,128,1), 128, SM_1P>>>(hH, w1H, b1, nullptr,
        nullptr, acH, DMODEL, DFF, 16, 1.f);

    // 8) out = y + act@W2 + b2 (16384x1024x4096) [1-pass]
    hg1pW<EM_F32, 5><<<dim3(8,128,1), 128, SM_1P>>>(acH, w2H, b2, yF,
        out, nullptr, DFF, DMODEL, 64, 1.f);
}